// round 10
// baseline (speedup 1.0000x reference)
#include <cuda_runtime.h>

#define T_  128
#define B_  2048
#define F_  128
#define H_  64
#define A_  15
#define TB_ (T_*B_)
#define G_  256   // 4*H gates

// Scratch (allocation-free rule: __device__ globals)
__device__ float g_gin[(size_t)TB_ * G_];   // precomputed input-gate preactivations
__device__ float g_z[(size_t)TB_ * H_];     // LSTM hidden outputs per step

// ---------------------------------------------------------------------------
// math helpers
// ---------------------------------------------------------------------------
__device__ __forceinline__ float ftanh_fast(float x) {
    float y;
    asm("tanh.approx.f32 %0, %1;" : "=f"(y) : "f"(x));
    return y;
}
// sigmoid(x) = 0.5*tanh(x/2) + 0.5 : 1 MUFU + FMAs
__device__ __forceinline__ float fsig_fast(float x) {
    return fmaf(0.5f, ftanh_fast(0.5f * x), 0.5f);
}
__device__ __forceinline__ unsigned tf32_rna(float x) {
    unsigned u; asm("cvt.rna.tf32.f32 %0, %1;" : "=r"(u) : "f"(x)); return u;
}
__device__ __forceinline__ float tf32f(float x) {
    return __uint_as_float(tf32_rna(x));
}
// d += a (m16k8, tf32) * b (k8n8, tf32)
__device__ __forceinline__ void mma8(float* d, const unsigned* a, unsigned b0, unsigned b1) {
    asm("mma.sync.aligned.m16n8k8.row.col.f32.tf32.tf32.f32 "
        "{%0,%1,%2,%3}, {%4,%5,%6,%7}, {%8,%9}, {%0,%1,%2,%3};"
        : "+f"(d[0]), "+f"(d[1]), "+f"(d[2]), "+f"(d[3])
        : "r"(a[0]), "r"(a[1]), "r"(a[2]), "r"(a[3]), "r"(b0), "r"(b1));
}
__device__ __forceinline__ void cp16(float* dst_smem, const float* src) {
    unsigned s = (unsigned)__cvta_generic_to_shared(dst_smem);
    asm volatile("cp.async.cg.shared.global [%0], [%1], 16;" :: "r"(s), "l"(src));
}
__device__ __forceinline__ void cp8(float2* dst_smem, const float* src) {
    unsigned s = (unsigned)__cvta_generic_to_shared(dst_smem);
    asm volatile("cp.async.ca.shared.global [%0], [%1], 8;" :: "r"(s), "l"(src));
}
__device__ __forceinline__ void split2(float v, unsigned& hi, unsigned& lo) {
    hi = tf32_rna(v);
    lo = tf32_rna(v - __uint_as_float(hi));
}

// ---------------------------------------------------------------------------
// Kernel 1: fused MLP encoder + input-gate GEMM, tf32 mma.
// B operands stored as padded PAIR-float2: P[kt][qc][n] = {W[k0+qc][n],
// W[k0+qc+4][n]}; stride 68/260 f2 (==8 mod 32 words) -> each half-warp's
// LDS.64 covers all 32 banks once: conflict-free, half the B-LDS instrs.
// S1/S2: 2-term A split. S3: 1-term (ys pre-rounded; Wih pair-rounded).
// 256 threads (8 warps), 128 rows/block, 2048 blocks, 2 blocks/SM.
// ---------------------------------------------------------------------------
#define ENC_XS   0
#define ENC_WA   9216
#define ENC_H1   18432
#define ENC_BIAS 27136
#define ENC_SMEM_F 27520

__global__ __launch_bounds__(256, 2)
void k_encode(const float* __restrict__ x,
              const float* __restrict__ W1, const float* __restrict__ b1,
              const float* __restrict__ W2, const float* __restrict__ b2,
              const float* __restrict__ Wih, const float* __restrict__ bih,
              const float* __restrict__ bhh) {
    extern __shared__ float sm[];
    float2* wP  = (float2*)(sm + ENC_WA);   // pair layouts (W1/W2/Wih)
    float* h1   = sm + ENC_H1;
    float* ys   = sm + ENC_XS;     // reuses xs region after S1
    float* bias = sm + ENC_BIAS;

    const int tid  = threadIdx.x;
    const int lane = tid & 31;
    const int w    = tid >> 5;
    const int row0 = blockIdx.x * 128;
    const int qr   = lane >> 2;    // 0..7
    const int qc   = lane & 3;     // 0..3
    const int m0   = w * 16;       // warp's private row tile

    // per-warp xs double buffer: [2][16][36]
    float* xw = sm + ENC_XS + w * 1152;
    const float* xg = x + (size_t)(row0 + m0) * F_;

    // issue quarter loads q0,q1 (per-warp cp.async groups)
    #pragma unroll
    for (int q = 0; q < 2; q++) {
        float* dst = xw + q * 576;
        #pragma unroll
        for (int j = 0; j < 4; j++) {
            int idx = lane + j*32;           // float4 index 0..127
            int r = idx >> 3, c4 = (idx & 7) * 4;
            cp16(dst + r*36 + c4, xg + r*F_ + q*32 + c4);
        }
        asm volatile("cp.async.commit_group;");
    }

    // W1 -> pair layout (tf32-rounded) + biases
    for (int i = tid; i < F_*H_; i += 256) {
        int k = i >> 6, n = i & 63;
        int kt = k >> 3, r = k & 7;
        ((float*)wP)[2*((kt*4 + (r&3))*68 + n) + (r>>2)] = tf32f(W1[i]);
    }
    for (int i = tid; i < G_; i += 256) bias[i] = bih[i] + bhh[i];
    for (int i = tid; i < H_;  i += 256) { bias[256+i] = b1[i]; bias[320+i] = b2[i]; }
    __syncthreads();

    // ================= S1: h1 = tanh(x @ W1 + b1), K=128, 2-term =========
    {
        float acc[8][4];
        #pragma unroll
        for (int nt = 0; nt < 8; nt++)
            #pragma unroll
            for (int j = 0; j < 4; j++) acc[nt][j] = 0.f;

        #pragma unroll
        for (int q = 0; q < 4; q++) {
            if (q < 3) asm volatile("cp.async.wait_group 1;");
            else       asm volatile("cp.async.wait_group 0;");
            __syncwarp();
            float* xb = xw + (q & 1) * 576;
            #pragma unroll
            for (int kt2 = 0; kt2 < 4; kt2++) {
                int k0 = kt2 * 8;            // local col in quarter
                int ktg = q*4 + kt2;         // global k-tile
                float a0 = xb[qr*36 + k0 + qc];
                float a1 = xb[(qr+8)*36 + k0 + qc];
                float a2 = xb[qr*36 + k0 + qc + 4];
                float a3 = xb[(qr+8)*36 + k0 + qc + 4];
                unsigned ahi[4], alo[4];
                split2(a0, ahi[0], alo[0]); split2(a1, ahi[1], alo[1]);
                split2(a2, ahi[2], alo[2]); split2(a3, ahi[3], alo[3]);
                const float2* bp = wP + (ktg*4 + qc)*68;
                #pragma unroll
                for (int nt = 0; nt < 8; nt++) {
                    float2 bb = bp[nt*8 + qr];
                    unsigned bh0 = __float_as_uint(bb.x);
                    unsigned bh1 = __float_as_uint(bb.y);
                    mma8(acc[nt], ahi, bh0, bh1);
                    mma8(acc[nt], alo, bh0, bh1);
                }
            }
            __syncwarp();
            if (q < 2) {   // refill this buffer with quarter q+2
                float* dst = xw + (q & 1) * 576;
                #pragma unroll
                for (int j = 0; j < 4; j++) {
                    int idx = lane + j*32;
                    int r = idx >> 3, c4 = (idx & 7) * 4;
                    cp16(dst + r*36 + c4, xg + r*F_ + (q+2)*32 + c4);
                }
                asm volatile("cp.async.commit_group;");
            }
        }
        #pragma unroll
        for (int nt = 0; nt < 8; nt++) {
            int c = nt*8 + 2*qc;
            float bb0 = bias[256+c], bb1 = bias[256+c+1];
            *(float2*)&h1[(m0+qr)*68 + c] =
                make_float2(ftanh_fast(acc[nt][0]+bb0), ftanh_fast(acc[nt][1]+bb1));
            *(float2*)&h1[(m0+qr+8)*68 + c] =
                make_float2(ftanh_fast(acc[nt][2]+bb0), ftanh_fast(acc[nt][3]+bb1));
        }
    }
    __syncthreads();                    // all warps done with W1 pairs
    // W2 -> pair layout
    for (int i = tid; i < H_*H_; i += 256) {
        int k = i >> 6, n = i & 63;
        int kt = k >> 3, r = k & 7;
        ((float*)wP)[2*((kt*4 + (r&3))*68 + n) + (r>>2)] = tf32f(W2[i]);
    }
    __syncthreads();

    // ========= S2: ys = tf32(tanh(h1 @ W2 + b2)), K=64, 2-term ===========
    {
        float acc[8][4];
        #pragma unroll
        for (int nt = 0; nt < 8; nt++)
            #pragma unroll
            for (int j = 0; j < 4; j++) acc[nt][j] = 0.f;

        #pragma unroll 2
        for (int kt = 0; kt < 8; kt++) {
            int k0 = kt * 8;
            float a0 = h1[(m0+qr)*68 + k0 + qc];
            float a1 = h1[(m0+qr+8)*68 + k0 + qc];
            float a2 = h1[(m0+qr)*68 + k0 + qc + 4];
            float a3 = h1[(m0+qr+8)*68 + k0 + qc + 4];
            unsigned ahi[4], alo[4];
            split2(a0, ahi[0], alo[0]); split2(a1, ahi[1], alo[1]);
            split2(a2, ahi[2], alo[2]); split2(a3, ahi[3], alo[3]);
            const float2* bp = wP + (kt*4 + qc)*68;
            #pragma unroll
            for (int nt = 0; nt < 8; nt++) {
                float2 bb = bp[nt*8 + qr];
                unsigned bh0 = __float_as_uint(bb.x);
                unsigned bh1 = __float_as_uint(bb.y);
                mma8(acc[nt], ahi, bh0, bh1);
                mma8(acc[nt], alo, bh0, bh1);
            }
        }
        // store ys PRE-ROUNDED to tf32 (S3 is 1-term; loads need no cvt)
        #pragma unroll
        for (int nt = 0; nt < 8; nt++) {
            int c = nt*8 + 2*qc;
            float bb0 = bias[320+c], bb1 = bias[320+c+1];
            *(float2*)&ys[(m0+qr)*68 + c] =
                make_float2(tf32f(ftanh_fast(acc[nt][0]+bb0)),
                            tf32f(ftanh_fast(acc[nt][1]+bb1)));
            *(float2*)&ys[(m0+qr+8)*68 + c] =
                make_float2(tf32f(ftanh_fast(acc[nt][2]+bb0)),
                            tf32f(ftanh_fast(acc[nt][3]+bb1)));
        }
    }
    __syncthreads();                    // W2 pairs + h1 now dead everywhere

    // Wih -> pair layout directly from gmem (L2-resident), tf32-rounded.
    // Task (n, kt): read 8 floats Wih[n][kt*8..+7] -> 4 STS.64 pair stores.
    #pragma unroll
    for (int j = 0; j < 8; j++) {
        int tsk = tid + j*256;          // 0..2047
        int n = tsk & 255, kt = tsk >> 8;
        const float4* src = (const float4*)(Wih + n*H_ + kt*8);
        float4 a = src[0], b = src[1];
        float2* dst = wP + (kt*4)*260 + n;
        dst[0]     = make_float2(tf32f(a.x), tf32f(b.x));
        dst[260]   = make_float2(tf32f(a.y), tf32f(b.y));
        dst[520]   = make_float2(tf32f(a.z), tf32f(b.z));
        dst[780]   = make_float2(tf32f(a.w), tf32f(b.w));
    }
    __syncthreads();

    // ===== S3: gin = ys @ Wih^T + bias, K=64, N=256, 1-term, zero cvt ====
    #pragma unroll 1
    for (int ch = 0; ch < 4; ch++) {
        float acc[8][4];
        #pragma unroll
        for (int nt = 0; nt < 8; nt++)
            #pragma unroll
            for (int j = 0; j < 4; j++) acc[nt][j] = 0.f;

        #pragma unroll 2
        for (int kt = 0; kt < 8; kt++) {
            int k0 = kt * 8;
            unsigned a[4];
            a[0] = __float_as_uint(ys[(m0+qr)*68 + k0 + qc]);
            a[1] = __float_as_uint(ys[(m0+qr+8)*68 + k0 + qc]);
            a[2] = __float_as_uint(ys[(m0+qr)*68 + k0 + qc + 4]);
            a[3] = __float_as_uint(ys[(m0+qr+8)*68 + k0 + qc + 4]);
            const float2* bp = wP + (kt*4 + qc)*260 + ch*64;
            #pragma unroll
            for (int nt = 0; nt < 8; nt++) {
                float2 bb = bp[nt*8 + qr];
                mma8(acc[nt], a, __float_as_uint(bb.x), __float_as_uint(bb.y));
            }
        }
        #pragma unroll
        for (int nt = 0; nt < 8; nt++) {
            int r = row0 + m0 + qr;
            int c = ch*64 + nt*8 + 2*qc;
            float bb0 = bias[c], bb1 = bias[c+1];
            *(float2*)&g_gin[(size_t)r*G_ + c] =
                make_float2(acc[nt][0] + bb0, acc[nt][1] + bb1);
            *(float2*)&g_gin[(size_t)(r+8)*G_ + c] =
                make_float2(acc[nt][2] + bb0, acc[nt][3] + bb1);
        }
    }
}

// ---------------------------------------------------------------------------
// Kernel 2: LSTM recurrence, tf32 mma (1-term h). 256 threads (8 warps),
// 16 batch rows/block, 128 blocks.
// Warp w computes n-tiles {i,f,g,o} x (units 8w..8w+8): thread fragments
// hold all four gates for (2 rows x 2 units) -> cell fully in registers.
// gin staged PER-THREAD: each thread cp.async's exactly the 8 float2 slots
// it consumes (producer==consumer, so per-thread cp.async.wait_group is a
// sufficient fence -- fixes the R9 cross-thread race). hsh double-buffered
// -> ONE __syncthreads per step.
// smem (floats): hsh [2][16][68]=2176 | gq [2][8][256]f2=8192 | done 2048
// ---------------------------------------------------------------------------
#define LS_HSH   0
#define LS_GQ    2176
#define LS_DONE  (2176 + 8192)             // 10368
#define LS_SMEM_F (10368 + T_*16)          // 12416

__global__ __launch_bounds__(256, 1)
void k_lstm(const float* __restrict__ done,
            const float* __restrict__ h0, const float* __restrict__ c0,
            const float* __restrict__ Whh, float* __restrict__ out) {
    extern __shared__ float sm[];
    float*  hsh    = sm + LS_HSH;       // [2][16][68]
    float2* gq     = (float2*)(sm + LS_GQ);  // [2][8][256]
    float*  done_s = sm + LS_DONE;      // [128][16]

    const int tid  = threadIdx.x;
    const int lane = tid & 31;
    const int w    = tid >> 5;
    const int b0   = blockIdx.x * 16;
    const int qr   = lane >> 2, qc = lane & 3;

    // B frags: warp w, gate g -> cols [g*64 + 8w, g*64 + 8w + 8)
    unsigned bf0[8][4], bf1[8][4];
    #pragma unroll
    for (int kt = 0; kt < 8; kt++)
        #pragma unroll
        for (int g = 0; g < 4; g++) {
            int n = g*64 + w*8 + qr, k = kt*8 + qc;
            bf0[kt][g] = tf32_rna(Whh[n*H_ + k]);
            bf1[kt][g] = tf32_rna(Whh[n*H_ + k + 4]);
        }

    for (int i = tid; i < T_*16; i += 256)
        done_s[i] = done[(i>>4)*B_ + b0 + (i&15)];

    // ownership: rows rA=qr, rB=qr+8; units u, u+1 with u = 8w + 2qc
    const int rA = qr, rB = qr + 8;
    const int u  = w*8 + qc*2;
    const float mA0 = 1.0f - done[b0 + rA];
    const float mB0 = 1.0f - done[b0 + rB];
    // c order: [0]=(rA,u) [1]=(rA,u+1) [2]=(rB,u) [3]=(rB,u+1)
    float c_reg[4], hl[4];
    c_reg[0] = c0[(b0+rA)*H_ + u]   * mA0;
    c_reg[1] = c0[(b0+rA)*H_ + u+1] * mA0;
    c_reg[2] = c0[(b0+rB)*H_ + u]   * mB0;
    c_reg[3] = c0[(b0+rB)*H_ + u+1] * mB0;
    *(float2*)&hsh[rA*68 + u] =
        make_float2(tf32f(h0[(b0+rA)*H_ + u])*mA0, tf32f(h0[(b0+rA)*H_ + u+1])*mA0);
    *(float2*)&hsh[rB*68 + u] =
        make_float2(tf32f(h0[(b0+rB)*H_ + u])*mB0, tf32f(h0[(b0+rB)*H_ + u+1])*mB0);
    hl[0] = hl[1] = hl[2] = hl[3] = 0.f;

    // prologue: per-thread prefetch of own gin slots for t=0, buf 0
    {
        const float* base = g_gin + (size_t)b0 * G_;
        #pragma unroll
        for (int g = 0; g < 4; g++) {
            cp8(&gq[(g*2    )*256 + tid], base + rA*G_ + g*64 + u);
            cp8(&gq[(g*2 + 1)*256 + tid], base + rB*G_ + g*64 + u);
        }
        asm volatile("cp.async.commit_group;");
    }
    __syncthreads();

    for (int t = 0; t < T_; t++) {
        // per-thread prefetch of own gin slots for t+1 (other buffer)
        if (t + 1 < T_) {
            float2* gd = gq + ((t+1)&1) * 2048;
            const float* base = g_gin + (size_t)((t+1)*B_ + b0) * G_;
            #pragma unroll
            for (int g = 0; g < 4; g++) {
                cp8(&gd[(g*2    )*256 + tid], base + rA*G_ + g*64 + u);
                cp8(&gd[(g*2 + 1)*256 + tid], base + rB*G_ + g*64 + u);
            }
            asm volatile("cp.async.commit_group;");
        }

        // gates = h @ Whh^T  (per warp: 4 gate-tiles x 8 units)
        const float* hb = hsh + (t&1) * 1088;
        float acc[4][4];
        #pragma unroll
        for (int g = 0; g < 4; g++)
            #pragma unroll
            for (int j = 0; j < 4; j++) acc[g][j] = 0.f;

        #pragma unroll
        for (int kt = 0; kt < 8; kt++) {
            int k0 = kt*8;
            unsigned a[4];
            a[0] = __float_as_uint(hb[rA*68 + k0 + qc]);
            a[1] = __float_as_uint(hb[rB*68 + k0 + qc]);
            a[2] = __float_as_uint(hb[rA*68 + k0 + qc + 4]);
            a[3] = __float_as_uint(hb[rB*68 + k0 + qc + 4]);
            #pragma unroll
            for (int g = 0; g < 4; g++)
                mma8(acc[g], a, bf0[kt][g], bf1[kt][g]);
        }
        // fragment layout: acc[g] = {(rA,u), (rA,u+1), (rB,u), (rB,u+1)}

        // own-thread slots only -> per-thread wait is a sufficient fence
        if (t + 1 < T_) asm volatile("cp.async.wait_group 1;");
        else            asm volatile("cp.async.wait_group 0;");

        const float2* gv = gq + (t&1) * 2048;
        float2 giA = gv[0*256 + tid], giB = gv[1*256 + tid];
        float2 gfA = gv[2*256 + tid], gfB = gv[3*256 + tid];
        float2 ggA = gv[4*256 + tid], ggB = gv[5*256 + tid];
        float2 goA = gv[6*256 + tid], goB = gv[7*256 + tid];

        float gi[4] = {acc[0][0]+giA.x, acc[0][1]+giA.y, acc[0][2]+giB.x, acc[0][3]+giB.y};
        float gf[4] = {acc[1][0]+gfA.x, acc[1][1]+gfA.y, acc[1][2]+gfB.x, acc[1][3]+gfB.y};
        float gg[4] = {acc[2][0]+ggA.x, acc[2][1]+ggA.y, acc[2][2]+ggB.x, acc[2][3]+ggB.y};
        float go[4] = {acc[3][0]+goA.x, acc[3][1]+goA.y, acc[3][2]+goB.x, acc[3][3]+goB.y};

        float mnA = 1.0f, mnB = 1.0f;
        if (t + 1 < T_) {
            mnA = 1.0f - done_s[(t+1)*16 + rA];
            mnB = 1.0f - done_s[(t+1)*16 + rB];
        }

        float hr[4];
        #pragma unroll
        for (int i = 0; i < 4; i++) {
            float mn = (i < 2) ? mnA : mnB;
            float cn = fsig_fast(gf[i])*c_reg[i] + fsig_fast(gi[i])*ftanh_fast(gg[i]);
            float hn = fsig_fast(go[i])*ftanh_fast(cn);
            c_reg[i] = cn * mn;                 // pre-mask for next step
            hr[i] = tf32f(hn) * mn;             // pre-round + pre-mask
            hl[i] = hn;
        }
        // write next-step h (other buffer) + z to gmem
        float* hn_ = hsh + ((t+1)&1) * 1088;
        *(float2*)&hn_[rA*68 + u] = make_float2(hr[0], hr[1]);
        *(float2*)&hn_[rB*68 + u] = make_float2(hr[2], hr[3]);
        *(float2*)&g_z[(size_t)(t*B_ + b0 + rA)*H_ + u] = make_float2(hl[0], hl[1]);
        *(float2*)&g_z[(size_t)(t*B_ + b0 + rB)*H_ + u] = make_float2(hl[2], hl[3]);
        __syncthreads();   // publish hsh[(t+1)&1] to all warps
    }

    // epilogue: hT, cT (layout: logits | vf | hT | cT), full precision
    const size_t OH = (size_t)TB_ * 16;
    *(float2*)&out[OH + (size_t)(b0+rA)*H_ + u]              = make_float2(hl[0], hl[1]);
    *(float2*)&out[OH + (size_t)(b0+rB)*H_ + u]              = make_float2(hl[2], hl[3]);
    *(float2*)&out[OH + (size_t)B_*H_ + (size_t)(b0+rA)*H_ + u] = make_float2(c_reg[0], c_reg[1]);
    *(float2*)&out[OH + (size_t)B_*H_ + (size_t)(b0+rB)*H_ + u] = make_float2(c_reg[2], c_reg[3]);
}

// ---------------------------------------------------------------------------
// Kernel 3: actor/critic heads.
// ---------------------------------------------------------------------------
__global__ __launch_bounds__(128)
void k_heads(const float* __restrict__ Wa, const float* __restrict__ ba,
             const float* __restrict__ Wc, const float* __restrict__ bc,
             float* __restrict__ out) {
    __shared__ float ws[H_*16];
    __shared__ float zs[128*65];
    const int tid  = threadIdx.x;
    const int row0 = blockIdx.x * 128;

    for (int i = tid; i < 128*H_; i += 128) zs[(i>>6)*65 + (i&63)] = g_z[(size_t)row0*H_ + i];
    for (int i = tid; i < H_*16; i += 128) {
        int k = i >> 4, j = i & 15;
        ws[i] = (j < 15) ? Wa[k*A_ + j] : Wc[k];
    }
    __syncthreads();

    float acc[16];
    #pragma unroll
    for (int j = 0; j < 15; j++) acc[j] = ba[j];
    acc[15] = bc[0];
    #pragma unroll 4
    for (int k = 0; k < H_; k++) {
        float a = zs[tid*65 + k];
        #pragma unroll
        for (int j = 0; j < 16; j++) acc[j] = fmaf(a, ws[k*16 + j], acc[j]);
    }
    const size_t r = (size_t)row0 + tid;
    #pragma unroll
    for (int j = 0; j < 15; j++) out[r*A_ + j] = acc[j];
    out[(size_t)TB_*A_ + r] = acc[15];
}

// ---------------------------------------------------------------------------
extern "C" void kernel_launch(void* const* d_in, const int* in_sizes, int n_in,
                              void* d_out, int out_size) {
    const float* x    = (const float*)d_in[0];
    const float* done = (const float*)d_in[1];
    const float* h0   = (const float*)d_in[2];
    const float* c0   = (const float*)d_in[3];
    const float* W1   = (const float*)d_in[4];
    const float* b1   = (const float*)d_in[5];
    const float* W2   = (const float*)d_in[6];
    const float* b2   = (const float*)d_in[7];
    const float* Wih  = (const float*)d_in[8];
    const float* bih  = (const float*)d_in[9];
    const float* Whh  = (const float*)d_in[10];
    const float* bhh  = (const float*)d_in[11];
    const float* Wa   = (const float*)d_in[12];
    const float* ba   = (const float*)d_in[13];
    const float* Wc   = (const float*)d_in[14];
    const float* bc   = (const float*)d_in[15];
    float* out = (float*)d_out;

    cudaFuncSetAttribute(k_encode, cudaFuncAttributeMaxDynamicSharedMemorySize, ENC_SMEM_F*4);
    cudaFuncSetAttribute(k_lstm,   cudaFuncAttributeMaxDynamicSharedMemorySize, LS_SMEM_F*4);

    k_encode<<<TB_/128, 256, ENC_SMEM_F*4>>>(x, W1, b1, W2, b2, Wih, bih, bhh);
    k_lstm<<<B_/16, 256, LS_SMEM_F*4>>>(done, h0, c0, Whh, out);
    k_heads<<<TB_/128, 128>>>(Wa, ba, Wc, bc, out);
}

// round 11
// speedup vs baseline: 1.1589x; 1.1589x over previous
#include <cuda_runtime.h>

#define T_  128
#define B_  2048
#define F_  128
#define H_  64
#define A_  15
#define TB_ (T_*B_)
#define G_  256   // 4*H gates

// Scratch (allocation-free rule: __device__ globals)
__device__ float g_gin[(size_t)TB_ * G_];   // precomputed input-gate preactivations

// ---------------------------------------------------------------------------
// math helpers
// ---------------------------------------------------------------------------
__device__ __forceinline__ float ftanh_fast(float x) {
    float y;
    asm("tanh.approx.f32 %0, %1;" : "=f"(y) : "f"(x));
    return y;
}
// sigmoid(x) = 0.5*tanh(x/2) + 0.5 : 1 MUFU + FMAs
__device__ __forceinline__ float fsig_fast(float x) {
    return fmaf(0.5f, ftanh_fast(0.5f * x), 0.5f);
}
__device__ __forceinline__ unsigned tf32_rna(float x) {
    unsigned u; asm("cvt.rna.tf32.f32 %0, %1;" : "=r"(u) : "f"(x)); return u;
}
__device__ __forceinline__ float tf32f(float x) {
    return __uint_as_float(tf32_rna(x));
}
// d += a (m16k8, tf32) * b (k8n8, tf32)
__device__ __forceinline__ void mma8(float* d, const unsigned* a, unsigned b0, unsigned b1) {
    asm("mma.sync.aligned.m16n8k8.row.col.f32.tf32.tf32.f32 "
        "{%0,%1,%2,%3}, {%4,%5,%6,%7}, {%8,%9}, {%0,%1,%2,%3};"
        : "+f"(d[0]), "+f"(d[1]), "+f"(d[2]), "+f"(d[3])
        : "r"(a[0]), "r"(a[1]), "r"(a[2]), "r"(a[3]), "r"(b0), "r"(b1));
}
__device__ __forceinline__ void cp16(float* dst_smem, const float* src) {
    unsigned s = (unsigned)__cvta_generic_to_shared(dst_smem);
    asm volatile("cp.async.cg.shared.global [%0], [%1], 16;" :: "r"(s), "l"(src));
}
__device__ __forceinline__ void split2(float v, unsigned& hi, unsigned& lo) {
    hi = tf32_rna(v);
    lo = tf32_rna(v - __uint_as_float(hi));
}

// ---------------------------------------------------------------------------
// Kernel 1: fused MLP encoder + input-gate GEMM, tf32 mma.  (R8-exact —
// scalar distinct-word B-LDS is 1-phase-optimal; vectorized variants
// regressed twice.)
// ---------------------------------------------------------------------------
#define ENC_XS   0
#define ENC_WA   9216
#define ENC_H1   18432
#define ENC_BIAS 27136
#define ENC_SMEM_F 27520

__global__ __launch_bounds__(256, 2)
void k_encode(const float* __restrict__ x,
              const float* __restrict__ W1, const float* __restrict__ b1,
              const float* __restrict__ W2, const float* __restrict__ b2,
              const float* __restrict__ Wih, const float* __restrict__ bih,
              const float* __restrict__ bhh) {
    extern __shared__ float sm[];
    float* wA   = sm + ENC_WA;
    float* h1   = sm + ENC_H1;
    float* ys   = sm + ENC_XS;     // reuses xs region after S1
    float* wg   = sm + ENC_WA;     // raw->rounded Wih after S2 (spans WA+H1)
    float* bias = sm + ENC_BIAS;

    const int tid  = threadIdx.x;
    const int lane = tid & 31;
    const int w    = tid >> 5;
    const int row0 = blockIdx.x * 128;
    const int qr   = lane >> 2;    // 0..7
    const int qc   = lane & 3;     // 0..3
    const int m0   = w * 16;       // warp's private row tile

    // per-warp xs double buffer: [2][16][36]
    float* xw = sm + ENC_XS + w * 1152;
    const float* xg = x + (size_t)(row0 + m0) * F_;

    // issue quarter loads q0,q1 (per-warp cp.async groups)
    #pragma unroll
    for (int q = 0; q < 2; q++) {
        float* dst = xw + q * 576;
        #pragma unroll
        for (int j = 0; j < 4; j++) {
            int idx = lane + j*32;           // float4 index 0..127
            int r = idx >> 3, c4 = (idx & 7) * 4;
            cp16(dst + r*36 + c4, xg + r*F_ + q*32 + c4);
        }
        asm volatile("cp.async.commit_group;");
    }

    // W1 (tf32-rounded) + biases
    for (int i = tid; i < F_*H_; i += 256) {
        int k = i >> 6, n = i & 63;
        wA[k*72 + n] = tf32f(W1[i]);
    }
    for (int i = tid; i < G_; i += 256) bias[i] = bih[i] + bhh[i];
    for (int i = tid; i < H_;  i += 256) { bias[256+i] = b1[i]; bias[320+i] = b2[i]; }
    __syncthreads();

    // ================= S1: h1 = tanh(x @ W1 + b1), K=128, 2-term =========
    {
        float acc[8][4];
        #pragma unroll
        for (int nt = 0; nt < 8; nt++)
            #pragma unroll
            for (int j = 0; j < 4; j++) acc[nt][j] = 0.f;

        #pragma unroll
        for (int q = 0; q < 4; q++) {
            if (q < 3) asm volatile("cp.async.wait_group 1;");
            else       asm volatile("cp.async.wait_group 0;");
            __syncwarp();
            float* xb = xw + (q & 1) * 576;
            #pragma unroll
            for (int kt2 = 0; kt2 < 4; kt2++) {
                int k0 = kt2 * 8;            // local col in quarter
                int bk = q*32 + k0 + qc;     // global k for B
                float a0 = xb[qr*36 + k0 + qc];
                float a1 = xb[(qr+8)*36 + k0 + qc];
                float a2 = xb[qr*36 + k0 + qc + 4];
                float a3 = xb[(qr+8)*36 + k0 + qc + 4];
                unsigned ahi[4], alo[4];
                split2(a0, ahi[0], alo[0]); split2(a1, ahi[1], alo[1]);
                split2(a2, ahi[2], alo[2]); split2(a3, ahi[3], alo[3]);
                #pragma unroll
                for (int nt = 0; nt < 8; nt++) {
                    int bn = nt*8 + qr;
                    unsigned bh0 = __float_as_uint(wA[bk*72 + bn]);
                    unsigned bh1 = __float_as_uint(wA[(bk+4)*72 + bn]);
                    mma8(acc[nt], ahi, bh0, bh1);
                    mma8(acc[nt], alo, bh0, bh1);
                }
            }
            __syncwarp();
            if (q < 2) {   // refill this buffer with quarter q+2
                float* dst = xw + (q & 1) * 576;
                #pragma unroll
                for (int j = 0; j < 4; j++) {
                    int idx = lane + j*32;
                    int r = idx >> 3, c4 = (idx & 7) * 4;
                    cp16(dst + r*36 + c4, xg + r*F_ + (q+2)*32 + c4);
                }
                asm volatile("cp.async.commit_group;");
            }
        }
        #pragma unroll
        for (int nt = 0; nt < 8; nt++) {
            int c = nt*8 + 2*qc;
            float bb0 = bias[256+c], bb1 = bias[256+c+1];
            *(float2*)&h1[(m0+qr)*68 + c] =
                make_float2(ftanh_fast(acc[nt][0]+bb0), ftanh_fast(acc[nt][1]+bb1));
            *(float2*)&h1[(m0+qr+8)*68 + c] =
                make_float2(ftanh_fast(acc[nt][2]+bb0), ftanh_fast(acc[nt][3]+bb1));
        }
    }
    __syncthreads();                    // all warps done with W1 region
    for (int i = tid; i < H_*H_; i += 256) {
        int k = i >> 6, n = i & 63;
        wA[k*72 + n] = tf32f(W2[i]);
    }
    __syncthreads();

    // ========= S2: ys = tf32(tanh(h1 @ W2 + b2)), K=64, 2-term ===========
    {
        float acc[8][4];
        #pragma unroll
        for (int nt = 0; nt < 8; nt++)
            #pragma unroll
            for (int j = 0; j < 4; j++) acc[nt][j] = 0.f;

        #pragma unroll 2
        for (int kt = 0; kt < 8; kt++) {
            int k0 = kt * 8;
            float a0 = h1[(m0+qr)*68 + k0 + qc];
            float a1 = h1[(m0+qr+8)*68 + k0 + qc];
            float a2 = h1[(m0+qr)*68 + k0 + qc + 4];
            float a3 = h1[(m0+qr+8)*68 + k0 + qc + 4];
            unsigned ahi[4], alo[4];
            split2(a0, ahi[0], alo[0]); split2(a1, ahi[1], alo[1]);
            split2(a2, ahi[2], alo[2]); split2(a3, ahi[3], alo[3]);
            #pragma unroll
            for (int nt = 0; nt < 8; nt++) {
                int bk = k0 + qc, bn = nt*8 + qr;
                unsigned bh0 = __float_as_uint(wA[bk*72 + bn]);
                unsigned bh1 = __float_as_uint(wA[(bk+4)*72 + bn]);
                mma8(acc[nt], ahi, bh0, bh1);
                mma8(acc[nt], alo, bh0, bh1);
            }
        }
        // store ys PRE-ROUNDED to tf32 (S3 is 1-term; loads need no cvt)
        #pragma unroll
        for (int nt = 0; nt < 8; nt++) {
            int c = nt*8 + 2*qc;
            float bb0 = bias[320+c], bb1 = bias[320+c+1];
            *(float2*)&ys[(m0+qr)*68 + c] =
                make_float2(tf32f(ftanh_fast(acc[nt][0]+bb0)),
                            tf32f(ftanh_fast(acc[nt][1]+bb1)));
            *(float2*)&ys[(m0+qr+8)*68 + c] =
                make_float2(tf32f(ftanh_fast(acc[nt][2]+bb0)),
                            tf32f(ftanh_fast(acc[nt][3]+bb1)));
        }
    }
    __syncthreads();                    // W2 + h1 regions now dead everywhere

    // async-load FULL raw Wih [256][68] into dead WA+H1 regions,
    // then round own elements in place (no cvt needed in S3).
    #pragma unroll
    for (int j = 0; j < 16; j++) {
        int f = tid + j*256;            // 0..4095 (float4 units)
        int n = f >> 4, c4 = (f & 15) * 4;
        cp16(wg + n*68 + c4, Wih + n*H_ + c4);
    }
    asm volatile("cp.async.commit_group;");
    asm volatile("cp.async.wait_group 0;");
    #pragma unroll
    for (int j = 0; j < 16; j++) {
        int f = tid + j*256;
        int n = f >> 4, c4 = (f & 15) * 4;
        float* p = wg + n*68 + c4;
        p[0] = tf32f(p[0]); p[1] = tf32f(p[1]);
        p[2] = tf32f(p[2]); p[3] = tf32f(p[3]);
    }
    __syncthreads();

    // ===== S3: gin = ys @ Wih^T + bias, K=64, N=256, 1-term, zero cvt ====
    #pragma unroll 1
    for (int ch = 0; ch < 4; ch++) {
        float acc[8][4];
        #pragma unroll
        for (int nt = 0; nt < 8; nt++)
            #pragma unroll
            for (int j = 0; j < 4; j++) acc[nt][j] = 0.f;

        #pragma unroll 2
        for (int kt = 0; kt < 8; kt++) {
            int k0 = kt * 8;
            unsigned a[4];
            a[0] = __float_as_uint(ys[(m0+qr)*68 + k0 + qc]);
            a[1] = __float_as_uint(ys[(m0+qr+8)*68 + k0 + qc]);
            a[2] = __float_as_uint(ys[(m0+qr)*68 + k0 + qc + 4]);
            a[3] = __float_as_uint(ys[(m0+qr+8)*68 + k0 + qc + 4]);
            #pragma unroll
            for (int nt = 0; nt < 8; nt++) {
                int bn = ch*64 + nt*8 + qr, bk = k0 + qc;
                mma8(acc[nt], a,
                     __float_as_uint(wg[bn*68 + bk]),
                     __float_as_uint(wg[bn*68 + bk + 4]));
            }
        }
        #pragma unroll
        for (int nt = 0; nt < 8; nt++) {
            int r = row0 + m0 + qr;
            int c = ch*64 + nt*8 + 2*qc;
            float bb0 = bias[c], bb1 = bias[c+1];
            *(float2*)&g_gin[(size_t)r*G_ + c] =
                make_float2(acc[nt][0] + bb0, acc[nt][1] + bb1);
            *(float2*)&g_gin[(size_t)(r+8)*G_ + c] =
                make_float2(acc[nt][2] + bb0, acc[nt][3] + bb1);
        }
    }
}

// ---------------------------------------------------------------------------
// Kernel 2: LSTM recurrence (R8 core) + FUSED actor/critic heads.
// 256 threads, 16 rows/block, 128 blocks. Heads for step t-1 computed
// during step t: warp w does n-half (w&1), k-slice (w>>1) -> 2 MMAs/warp;
// partials reduced 4-way in the cell phase. z lives only in smem (zs,
// double-buffered); g_z gmem round-trip and k_heads kernel eliminated.
// smem (floats): hsh 1088 | gs 16*264=4224 | ginb 2*4096=8192 |
//                done 2048 | zs 2*1088=2176 | pbuf 4*16*18=1152  => 18880
// ---------------------------------------------------------------------------
#define LS_HSH   0
#define LS_GS    1088
#define LS_GINB  (LS_GS + 16*264)          // 5312
#define LS_DONE  (LS_GINB + 2*16*G_)       // 13504
#define LS_ZS    (LS_DONE + T_*16)         // 15552
#define LS_PBUF  (LS_ZS + 2*1088)          // 17728
#define LS_SMEM_F (LS_PBUF + 4*16*18)      // 18880

__global__ __launch_bounds__(256, 1)
void k_lstm(const float* __restrict__ done,
            const float* __restrict__ h0, const float* __restrict__ c0,
            const float* __restrict__ Whh,
            const float* __restrict__ Wa, const float* __restrict__ ba,
            const float* __restrict__ Wc, const float* __restrict__ bc,
            float* __restrict__ out) {
    extern __shared__ float sm[];
    float* hsh    = sm + LS_HSH;
    float* gs     = sm + LS_GS;
    float* ginb   = sm + LS_GINB;
    float* done_s = sm + LS_DONE;
    float* zs     = sm + LS_ZS;        // [2][16][68] exact z
    float* pbuf   = sm + LS_PBUF;      // [4][16][18] heads partials

    const int tid  = threadIdx.x;
    const int lane = tid & 31;
    const int w    = tid >> 5;
    const int b0   = blockIdx.x * 16;
    const int qr   = lane >> 2, qc = lane & 3;

    // Whh fragments: warp w owns gate cols [w*32, w*32+32)
    unsigned bf0[8][4], bf1[8][4];
    #pragma unroll
    for (int kt = 0; kt < 8; kt++)
        #pragma unroll
        for (int nt = 0; nt < 4; nt++) {
            int n = w*32 + nt*8 + qr, k = kt*8 + qc;
            bf0[kt][nt] = tf32_rna(Whh[n*H_ + k]);
            bf1[kt][nt] = tf32_rna(Whh[n*H_ + k + 4]);
        }

    // heads fragments: warp w -> n-half n0=(w&1)*8, k-slice ks=w>>1 (2 kt)
    const int n0 = (w & 1) * 8, ks = w >> 1;
    unsigned hb0[2], hb1[2];
    #pragma unroll
    for (int i = 0; i < 2; i++) {
        int k = (ks*2 + i)*8 + qc, j = n0 + qr;
        float v0 = (j < 15) ? Wa[k*A_ + j]     : Wc[k];
        float v1 = (j < 15) ? Wa[(k+4)*A_ + j] : Wc[k+4];
        hb0[i] = tf32_rna(v0);
        hb1[i] = tf32_rna(v1);
    }
    // reduce role: thread -> output (row rC, col rcol)
    const int rcol = tid & 15;
    const float rbias = (rcol < 15) ? ba[rcol] : bc[0];

    for (int i = tid; i < T_*16; i += 256)
        done_s[i] = done[(i>>4)*B_ + b0 + (i&15)];

    // cell ownership: thread -> (row rC, units u0..u0+3)
    const int rC = tid >> 4, u0 = (tid & 15) * 4;
    const float mk0 = 1.0f - done[b0 + rC];     // step-0 mask, direct gmem
    float c_reg[4], hlast[4];
    #pragma unroll
    for (int i = 0; i < 4; i++) {
        c_reg[i] = c0[(b0 + rC)*H_ + u0 + i] * mk0;
        hsh[rC*68 + u0 + i] = tf32f(h0[(b0 + rC)*H_ + u0 + i]) * mk0;
        hlast[i] = 0.f;
    }

    // prologue: prefetch gin[t=0]
    {
        const float* src = g_gin + (size_t)b0 * G_;
        #pragma unroll
        for (int j = 0; j < 4; j++) {
            int q = tid + j*256;
            cp16(ginb + q*4, src + q*4);
        }
        asm volatile("cp.async.commit_group;");
    }
    __syncthreads();

    for (int t = 0; t < T_; t++) {
        // prefetch gin[t+1]
        if (t + 1 < T_) {
            float* dst = ginb + ((t+1)&1) * (16*G_);
            const float* src = g_gin + (size_t)((t+1)*B_ + b0) * G_;
            #pragma unroll
            for (int j = 0; j < 4; j++) {
                int q = tid + j*256;
                cp16(dst + q*4, src + q*4);
            }
            asm volatile("cp.async.commit_group;");
        }

        // ---- heads partial for step t-1 (reads zs[(t-1)&1]) ----
        if (t) {
            const float* zb = zs + ((t-1)&1) * 1088;
            float pacc[4] = {0.f, 0.f, 0.f, 0.f};
            #pragma unroll
            for (int i = 0; i < 2; i++) {
                int k0 = (ks*2 + i)*8;
                unsigned a[4];
                a[0] = tf32_rna(zb[qr*68 + k0 + qc]);
                a[1] = tf32_rna(zb[(qr+8)*68 + k0 + qc]);
                a[2] = tf32_rna(zb[qr*68 + k0 + qc + 4]);
                a[3] = tf32_rna(zb[(qr+8)*68 + k0 + qc + 4]);
                mma8(pacc, a, hb0[i], hb1[i]);
            }
            *(float2*)&pbuf[ks*288 + qr*18 + n0 + 2*qc]     = make_float2(pacc[0], pacc[1]);
            *(float2*)&pbuf[ks*288 + (qr+8)*18 + n0 + 2*qc] = make_float2(pacc[2], pacc[3]);
        }

        // gates_rec = h @ Whh^T  (m16 x n32 per warp; hsh pre-rounded+masked)
        float acc[4][4];
        #pragma unroll
        for (int nt = 0; nt < 4; nt++)
            #pragma unroll
            for (int j = 0; j < 4; j++) acc[nt][j] = 0.f;

        #pragma unroll
        for (int kt = 0; kt < 8; kt++) {
            int k0 = kt*8;
            unsigned a[4];
            a[0] = __float_as_uint(hsh[qr*68 + k0 + qc]);
            a[1] = __float_as_uint(hsh[(qr+8)*68 + k0 + qc]);
            a[2] = __float_as_uint(hsh[qr*68 + k0 + qc + 4]);
            a[3] = __float_as_uint(hsh[(qr+8)*68 + k0 + qc + 4]);
            #pragma unroll
            for (int nt = 0; nt < 4; nt++)
                mma8(acc[nt], a, bf0[kt][nt], bf1[kt][nt]);
        }
        #pragma unroll
        for (int nt = 0; nt < 4; nt++) {
            int c = w*32 + nt*8 + 2*qc;
            *(float2*)&gs[qr*264 + c]     = make_float2(acc[nt][0], acc[nt][1]);
            *(float2*)&gs[(qr+8)*264 + c] = make_float2(acc[nt][2], acc[nt][3]);
        }

        if (t + 1 < T_) asm volatile("cp.async.wait_group 1;");
        else            asm volatile("cp.async.wait_group 0;");
        __syncthreads();   // publishes gs + pbuf

        // ---- heads reduce + output for step t-1 ----
        if (t) {
            float s = pbuf[0*288 + rC*18 + rcol] + pbuf[1*288 + rC*18 + rcol]
                    + pbuf[2*288 + rC*18 + rcol] + pbuf[3*288 + rC*18 + rcol]
                    + rbias;
            size_t r = (size_t)(t-1)*B_ + b0 + rC;
            if (rcol < 15) out[r*A_ + rcol] = s;
            else           out[(size_t)TB_*A_ + r] = s;
        }

        // cell update (gate order i,f,g,o); float4 gate loads
        const float* gv = ginb + (t&1)*(16*G_) + rC*G_;
        float mn = 1.0f;
        if (t + 1 < T_) mn = 1.0f - done_s[(t+1)*16 + rC];

        float4 gi4 = *(const float4*)&gs[rC*264 + u0];
        float4 gf4 = *(const float4*)&gs[rC*264 + 64 + u0];
        float4 gg4 = *(const float4*)&gs[rC*264 + 128 + u0];
        float4 go4 = *(const float4*)&gs[rC*264 + 192 + u0];
        float4 vi4 = *(const float4*)&gv[u0];
        float4 vf4 = *(const float4*)&gv[64 + u0];
        float4 vg4 = *(const float4*)&gv[128 + u0];
        float4 vo4 = *(const float4*)&gv[192 + u0];

        float gi[4] = {gi4.x+vi4.x, gi4.y+vi4.y, gi4.z+vi4.z, gi4.w+vi4.w};
        float gf[4] = {gf4.x+vf4.x, gf4.y+vf4.y, gf4.z+vf4.z, gf4.w+vf4.w};
        float gg[4] = {gg4.x+vg4.x, gg4.y+vg4.y, gg4.z+vg4.z, gg4.w+vg4.w};
        float go[4] = {go4.x+vo4.x, go4.y+vo4.y, go4.z+vo4.z, go4.w+vo4.w};

        float hn[4], hr[4];
        #pragma unroll
        for (int i = 0; i < 4; i++) {
            float cn = fsig_fast(gf[i])*c_reg[i] + fsig_fast(gi[i])*ftanh_fast(gg[i]);
            hn[i] = fsig_fast(go[i])*ftanh_fast(cn);
            c_reg[i] = cn * mn;                 // pre-mask for next step
            hr[i] = tf32f(hn[i]) * mn;          // pre-round + pre-mask
            hlast[i] = hn[i];
        }
        // exact z to smem (replaces g_z gmem store)
        *(float4*)&zs[(t&1)*1088 + rC*68 + u0] = make_float4(hn[0], hn[1], hn[2], hn[3]);
        *(float4*)&hsh[rC*68 + u0] = make_float4(hr[0], hr[1], hr[2], hr[3]);
        __syncthreads();   // publishes hsh + zs[t&1]
    }

    // ---- tail: heads for step T-1 ----
    {
        const float* zb = zs + ((T_-1)&1) * 1088;
        float pacc[4] = {0.f, 0.f, 0.f, 0.f};
        #pragma unroll
        for (int i = 0; i < 2; i++) {
            int k0 = (ks*2 + i)*8;
            unsigned a[4];
            a[0] = tf32_rna(zb[qr*68 + k0 + qc]);
            a[1] = tf32_rna(zb[(qr+8)*68 + k0 + qc]);
            a[2] = tf32_rna(zb[qr*68 + k0 + qc + 4]);
            a[3] = tf32_rna(zb[(qr+8)*68 + k0 + qc + 4]);
            mma8(pacc, a, hb0[i], hb1[i]);
        }
        *(float2*)&pbuf[ks*288 + qr*18 + n0 + 2*qc]     = make_float2(pacc[0], pacc[1]);
        *(float2*)&pbuf[ks*288 + (qr+8)*18 + n0 + 2*qc] = make_float2(pacc[2], pacc[3]);
        __syncthreads();
        float s = pbuf[0*288 + rC*18 + rcol] + pbuf[1*288 + rC*18 + rcol]
                + pbuf[2*288 + rC*18 + rcol] + pbuf[3*288 + rC*18 + rcol]
                + rbias;
        size_t r = (size_t)(T_-1)*B_ + b0 + rC;
        if (rcol < 15) out[r*A_ + rcol] = s;
        else           out[(size_t)TB_*A_ + r] = s;
    }

    // epilogue: hT, cT (layout: logits | vf | hT | cT), full precision
    const size_t OH = (size_t)TB_ * 16;
    #pragma unroll
    for (int i = 0; i < 4; i++) {
        out[OH + (size_t)(b0 + rC)*H_ + u0 + i]                 = hlast[i];
        out[OH + (size_t)B_*H_ + (size_t)(b0 + rC)*H_ + u0 + i] = c_reg[i];
    }
}

// ---------------------------------------------------------------------------
extern "C" void kernel_launch(void* const* d_in, const int* in_sizes, int n_in,
                              void* d_out, int out_size) {
    const float* x    = (const float*)d_in[0];
    const float* done = (const float*)d_in[1];
    const float* h0   = (const float*)d_in[2];
    const float* c0   = (const float*)d_in[3];
    const float* W1   = (const float*)d_in[4];
    const float* b1   = (const float*)d_in[5];
    const float* W2   = (const float*)d_in[6];
    const float* b2   = (const float*)d_in[7];
    const float* Wih  = (const float*)d_in[8];
    const float* bih  = (const float*)d_in[9];
    const float* Whh  = (const float*)d_in[10];
    const float* bhh  = (const float*)d_in[11];
    const float* Wa   = (const float*)d_in[12];
    const float* ba   = (const float*)d_in[13];
    const float* Wc   = (const float*)d_in[14];
    const float* bc   = (const float*)d_in[15];
    float* out = (float*)d_out;

    cudaFuncSetAttribute(k_encode, cudaFuncAttributeMaxDynamicSharedMemorySize, ENC_SMEM_F*4);
    cudaFuncSetAttribute(k_lstm,   cudaFuncAttributeMaxDynamicSharedMemorySize, LS_SMEM_F*4);

    k_encode<<<TB_/128, 256, ENC_SMEM_F*4>>>(x, W1, b1, W2, b2, Wih, bih, bhh);
    k_lstm<<<B_/16, 256, LS_SMEM_F*4>>>(done, h0, c0, Whh, Wa, ba, Wc, bc, out);
}

// round 12
// speedup vs baseline: 1.1717x; 1.0111x over previous
#include <cuda_runtime.h>

#define T_  128
#define B_  2048
#define F_  128
#define H_  64
#define A_  15
#define TB_ (T_*B_)
#define G_  256   // 4*H gates

// Scratch (allocation-free rule: __device__ globals)
__device__ float g_gin[(size_t)TB_ * G_];   // precomputed input-gate preactivations

// ---------------------------------------------------------------------------
// math helpers
// ---------------------------------------------------------------------------
__device__ __forceinline__ float ftanh_fast(float x) {
    float y;
    asm("tanh.approx.f32 %0, %1;" : "=f"(y) : "f"(x));
    return y;
}
// sigmoid(x) = 0.5*tanh(x/2) + 0.5 : 1 MUFU + FMAs
__device__ __forceinline__ float fsig_fast(float x) {
    return fmaf(0.5f, ftanh_fast(0.5f * x), 0.5f);
}
__device__ __forceinline__ unsigned tf32_rna(float x) {
    unsigned u; asm("cvt.rna.tf32.f32 %0, %1;" : "=r"(u) : "f"(x)); return u;
}
__device__ __forceinline__ float tf32f(float x) {
    return __uint_as_float(tf32_rna(x));
}
// d += a (m16k8, tf32) * b (k8n8, tf32)
__device__ __forceinline__ void mma8(float* d, const unsigned* a, unsigned b0, unsigned b1) {
    asm("mma.sync.aligned.m16n8k8.row.col.f32.tf32.tf32.f32 "
        "{%0,%1,%2,%3}, {%4,%5,%6,%7}, {%8,%9}, {%0,%1,%2,%3};"
        : "+f"(d[0]), "+f"(d[1]), "+f"(d[2]), "+f"(d[3])
        : "r"(a[0]), "r"(a[1]), "r"(a[2]), "r"(a[3]), "r"(b0), "r"(b1));
}
__device__ __forceinline__ void cp16(float* dst_smem, const float* src) {
    unsigned s = (unsigned)__cvta_generic_to_shared(dst_smem);
    asm volatile("cp.async.cg.shared.global [%0], [%1], 16;" :: "r"(s), "l"(src));
}
__device__ __forceinline__ void split2(float v, unsigned& hi, unsigned& lo) {
    hi = tf32_rna(v);
    lo = tf32_rna(v - __uint_as_float(hi));
}

// ---------------------------------------------------------------------------
// Kernel 1: fused MLP encoder + input-gate GEMM, tf32 mma.  (R8-exact —
// scalar distinct-word B-LDS is 1-phase-optimal; vectorized variants
// regressed twice. Do not touch.)
// ---------------------------------------------------------------------------
#define ENC_XS   0
#define ENC_WA   9216
#define ENC_H1   18432
#define ENC_BIAS 27136
#define ENC_SMEM_F 27520

__global__ __launch_bounds__(256, 2)
void k_encode(const float* __restrict__ x,
              const float* __restrict__ W1, const float* __restrict__ b1,
              const float* __restrict__ W2, const float* __restrict__ b2,
              const float* __restrict__ Wih, const float* __restrict__ bih,
              const float* __restrict__ bhh) {
    extern __shared__ float sm[];
    float* wA   = sm + ENC_WA;
    float* h1   = sm + ENC_H1;
    float* ys   = sm + ENC_XS;     // reuses xs region after S1
    float* wg   = sm + ENC_WA;     // raw->rounded Wih after S2 (spans WA+H1)
    float* bias = sm + ENC_BIAS;

    const int tid  = threadIdx.x;
    const int lane = tid & 31;
    const int w    = tid >> 5;
    const int row0 = blockIdx.x * 128;
    const int qr   = lane >> 2;    // 0..7
    const int qc   = lane & 3;     // 0..3
    const int m0   = w * 16;       // warp's private row tile

    // per-warp xs double buffer: [2][16][36]
    float* xw = sm + ENC_XS + w * 1152;
    const float* xg = x + (size_t)(row0 + m0) * F_;

    // issue quarter loads q0,q1 (per-warp cp.async groups)
    #pragma unroll
    for (int q = 0; q < 2; q++) {
        float* dst = xw + q * 576;
        #pragma unroll
        for (int j = 0; j < 4; j++) {
            int idx = lane + j*32;           // float4 index 0..127
            int r = idx >> 3, c4 = (idx & 7) * 4;
            cp16(dst + r*36 + c4, xg + r*F_ + q*32 + c4);
        }
        asm volatile("cp.async.commit_group;");
    }

    // W1 (tf32-rounded) + biases
    for (int i = tid; i < F_*H_; i += 256) {
        int k = i >> 6, n = i & 63;
        wA[k*72 + n] = tf32f(W1[i]);
    }
    for (int i = tid; i < G_; i += 256) bias[i] = bih[i] + bhh[i];
    for (int i = tid; i < H_;  i += 256) { bias[256+i] = b1[i]; bias[320+i] = b2[i]; }
    __syncthreads();

    // ================= S1: h1 = tanh(x @ W1 + b1), K=128, 2-term =========
    {
        float acc[8][4];
        #pragma unroll
        for (int nt = 0; nt < 8; nt++)
            #pragma unroll
            for (int j = 0; j < 4; j++) acc[nt][j] = 0.f;

        #pragma unroll
        for (int q = 0; q < 4; q++) {
            if (q < 3) asm volatile("cp.async.wait_group 1;");
            else       asm volatile("cp.async.wait_group 0;");
            __syncwarp();
            float* xb = xw + (q & 1) * 576;
            #pragma unroll
            for (int kt2 = 0; kt2 < 4; kt2++) {
                int k0 = kt2 * 8;            // local col in quarter
                int bk = q*32 + k0 + qc;     // global k for B
                float a0 = xb[qr*36 + k0 + qc];
                float a1 = xb[(qr+8)*36 + k0 + qc];
                float a2 = xb[qr*36 + k0 + qc + 4];
                float a3 = xb[(qr+8)*36 + k0 + qc + 4];
                unsigned ahi[4], alo[4];
                split2(a0, ahi[0], alo[0]); split2(a1, ahi[1], alo[1]);
                split2(a2, ahi[2], alo[2]); split2(a3, ahi[3], alo[3]);
                #pragma unroll
                for (int nt = 0; nt < 8; nt++) {
                    int bn = nt*8 + qr;
                    unsigned bh0 = __float_as_uint(wA[bk*72 + bn]);
                    unsigned bh1 = __float_as_uint(wA[(bk+4)*72 + bn]);
                    mma8(acc[nt], ahi, bh0, bh1);
                    mma8(acc[nt], alo, bh0, bh1);
                }
            }
            __syncwarp();
            if (q < 2) {   // refill this buffer with quarter q+2
                float* dst = xw + (q & 1) * 576;
                #pragma unroll
                for (int j = 0; j < 4; j++) {
                    int idx = lane + j*32;
                    int r = idx >> 3, c4 = (idx & 7) * 4;
                    cp16(dst + r*36 + c4, xg + r*F_ + (q+2)*32 + c4);
                }
                asm volatile("cp.async.commit_group;");
            }
        }
        #pragma unroll
        for (int nt = 0; nt < 8; nt++) {
            int c = nt*8 + 2*qc;
            float bb0 = bias[256+c], bb1 = bias[256+c+1];
            *(float2*)&h1[(m0+qr)*68 + c] =
                make_float2(ftanh_fast(acc[nt][0]+bb0), ftanh_fast(acc[nt][1]+bb1));
            *(float2*)&h1[(m0+qr+8)*68 + c] =
                make_float2(ftanh_fast(acc[nt][2]+bb0), ftanh_fast(acc[nt][3]+bb1));
        }
    }
    __syncthreads();                    // all warps done with W1 region
    for (int i = tid; i < H_*H_; i += 256) {
        int k = i >> 6, n = i & 63;
        wA[k*72 + n] = tf32f(W2[i]);
    }
    __syncthreads();

    // ========= S2: ys = tf32(tanh(h1 @ W2 + b2)), K=64, 2-term ===========
    {
        float acc[8][4];
        #pragma unroll
        for (int nt = 0; nt < 8; nt++)
            #pragma unroll
            for (int j = 0; j < 4; j++) acc[nt][j] = 0.f;

        #pragma unroll 2
        for (int kt = 0; kt < 8; kt++) {
            int k0 = kt * 8;
            float a0 = h1[(m0+qr)*68 + k0 + qc];
            float a1 = h1[(m0+qr+8)*68 + k0 + qc];
            float a2 = h1[(m0+qr)*68 + k0 + qc + 4];
            float a3 = h1[(m0+qr+8)*68 + k0 + qc + 4];
            unsigned ahi[4], alo[4];
            split2(a0, ahi[0], alo[0]); split2(a1, ahi[1], alo[1]);
            split2(a2, ahi[2], alo[2]); split2(a3, ahi[3], alo[3]);
            #pragma unroll
            for (int nt = 0; nt < 8; nt++) {
                int bk = k0 + qc, bn = nt*8 + qr;
                unsigned bh0 = __float_as_uint(wA[bk*72 + bn]);
                unsigned bh1 = __float_as_uint(wA[(bk+4)*72 + bn]);
                mma8(acc[nt], ahi, bh0, bh1);
                mma8(acc[nt], alo, bh0, bh1);
            }
        }
        // store ys PRE-ROUNDED to tf32 (S3 is 1-term; loads need no cvt)
        #pragma unroll
        for (int nt = 0; nt < 8; nt++) {
            int c = nt*8 + 2*qc;
            float bb0 = bias[320+c], bb1 = bias[320+c+1];
            *(float2*)&ys[(m0+qr)*68 + c] =
                make_float2(tf32f(ftanh_fast(acc[nt][0]+bb0)),
                            tf32f(ftanh_fast(acc[nt][1]+bb1)));
            *(float2*)&ys[(m0+qr+8)*68 + c] =
                make_float2(tf32f(ftanh_fast(acc[nt][2]+bb0)),
                            tf32f(ftanh_fast(acc[nt][3]+bb1)));
        }
    }
    __syncthreads();                    // W2 + h1 regions now dead everywhere

    // async-load FULL raw Wih [256][68] into dead WA+H1 regions,
    // then round own elements in place (no cvt needed in S3).
    #pragma unroll
    for (int j = 0; j < 16; j++) {
        int f = tid + j*256;            // 0..4095 (float4 units)
        int n = f >> 4, c4 = (f & 15) * 4;
        cp16(wg + n*68 + c4, Wih + n*H_ + c4);
    }
    asm volatile("cp.async.commit_group;");
    asm volatile("cp.async.wait_group 0;");
    #pragma unroll
    for (int j = 0; j < 16; j++) {
        int f = tid + j*256;
        int n = f >> 4, c4 = (f & 15) * 4;
        float* p = wg + n*68 + c4;
        p[0] = tf32f(p[0]); p[1] = tf32f(p[1]);
        p[2] = tf32f(p[2]); p[3] = tf32f(p[3]);
    }
    __syncthreads();

    // ===== S3: gin = ys @ Wih^T + bias, K=64, N=256, 1-term, zero cvt ====
    #pragma unroll 1
    for (int ch = 0; ch < 4; ch++) {
        float acc[8][4];
        #pragma unroll
        for (int nt = 0; nt < 8; nt++)
            #pragma unroll
            for (int j = 0; j < 4; j++) acc[nt][j] = 0.f;

        #pragma unroll 2
        for (int kt = 0; kt < 8; kt++) {
            int k0 = kt * 8;
            unsigned a[4];
            a[0] = __float_as_uint(ys[(m0+qr)*68 + k0 + qc]);
            a[1] = __float_as_uint(ys[(m0+qr+8)*68 + k0 + qc]);
            a[2] = __float_as_uint(ys[(m0+qr)*68 + k0 + qc + 4]);
            a[3] = __float_as_uint(ys[(m0+qr+8)*68 + k0 + qc + 4]);
            #pragma unroll
            for (int nt = 0; nt < 8; nt++) {
                int bn = ch*64 + nt*8 + qr, bk = k0 + qc;
                mma8(acc[nt], a,
                     __float_as_uint(wg[bn*68 + bk]),
                     __float_as_uint(wg[bn*68 + bk + 4]));
            }
        }
        #pragma unroll
        for (int nt = 0; nt < 8; nt++) {
            int r = row0 + m0 + qr;
            int c = ch*64 + nt*8 + 2*qc;
            float bb0 = bias[c], bb1 = bias[c+1];
            *(float2*)&g_gin[(size_t)r*G_ + c] =
                make_float2(acc[nt][0] + bb0, acc[nt][1] + bb1);
            *(float2*)&g_gin[(size_t)(r+8)*G_ + c] =
                make_float2(acc[nt][2] + bb0, acc[nt][3] + bb1);
        }
    }
}

// ---------------------------------------------------------------------------
// Kernel 2: LSTM + fused heads, gate-ownership fragments.
// Warp w computes {i,f,g,o} x units [8w,8w+8): thread fragments hold all 4
// gates for its (2 rows x 2 units) -> cell in registers, NO gs round-trip,
// ONE __syncthreads per step. gin: block-coalesced cp16 double-buffer
// (stride 264, conflict-free float2 gate reads); wait_group 0 placed before
// the end-of-step barrier -> cross-thread copies safely published (R9 fix).
// Heads: partial(t-1) during step t -> pbuf[(t-1)&1]; reduce(t-2) at step
// start (parities disjoint); tail drains T-2, T-1.
// smem (floats): hsh [2][16][68]=2176 | ginb [2][16][264]=8448 |
//                done 2048 | zs [2][16][68]=2176 | pbuf [2][4][16][18]=2304
// ---------------------------------------------------------------------------
#define LS_HSH   0
#define LS_GINB  2176
#define LS_DONE  (LS_GINB + 8448)          // 10624
#define LS_ZS    (LS_DONE + T_*16)         // 12672
#define LS_PBUF  (LS_ZS + 2176)            // 14848
#define LS_SMEM_F (LS_PBUF + 2304)         // 17152

__global__ __launch_bounds__(256, 1)
void k_lstm(const float* __restrict__ done,
            const float* __restrict__ h0, const float* __restrict__ c0,
            const float* __restrict__ Whh,
            const float* __restrict__ Wa, const float* __restrict__ ba,
            const float* __restrict__ Wc, const float* __restrict__ bc,
            float* __restrict__ out) {
    extern __shared__ float sm[];
    float* hsh    = sm + LS_HSH;       // [2][16][68]
    float* ginb   = sm + LS_GINB;      // [2][16][264]
    float* done_s = sm + LS_DONE;      // [128][16]
    float* zs     = sm + LS_ZS;        // [2][16][68] exact z
    float* pbuf   = sm + LS_PBUF;      // [2][4][16][18]

    const int tid  = threadIdx.x;
    const int lane = tid & 31;
    const int w    = tid >> 5;
    const int b0   = blockIdx.x * 16;
    const int qr   = lane >> 2, qc = lane & 3;

    // gate-ownership B frags: warp w, gate g -> cols [g*64+8w, g*64+8w+8)
    unsigned bf0[8][4], bf1[8][4];
    #pragma unroll
    for (int kt = 0; kt < 8; kt++)
        #pragma unroll
        for (int g = 0; g < 4; g++) {
            int n = g*64 + w*8 + qr, k = kt*8 + qc;
            bf0[kt][g] = tf32_rna(Whh[n*H_ + k]);
            bf1[kt][g] = tf32_rna(Whh[n*H_ + k + 4]);
        }

    // heads frags: warp w -> n-half n0=(w&1)*8, k-slice ks=w>>1 (2 kt)
    const int n0 = (w & 1) * 8, ks = w >> 1;
    unsigned hb0[2], hb1[2];
    #pragma unroll
    for (int i = 0; i < 2; i++) {
        int k = (ks*2 + i)*8 + qc, j = n0 + qr;
        float v0 = (j < 15) ? Wa[k*A_ + j]     : Wc[k];
        float v1 = (j < 15) ? Wa[(k+4)*A_ + j] : Wc[k+4];
        hb0[i] = tf32_rna(v0);
        hb1[i] = tf32_rna(v1);
    }
    // reduce role: thread -> output (row rrow, col rcol)
    const int rcol = tid & 15, rrow = tid >> 4;
    const float rbias = (rcol < 15) ? ba[rcol] : bc[0];

    for (int i = tid; i < T_*16; i += 256)
        done_s[i] = done[(i>>4)*B_ + b0 + (i&15)];

    // cell ownership: rows rA=qr, rB=qr+8; units u, u+1 with u = 8w + 2qc
    const int rA = qr, rB = qr + 8;
    const int u  = w*8 + qc*2;
    const float mA0 = 1.0f - done[b0 + rA];
    const float mB0 = 1.0f - done[b0 + rB];
    float c_reg[4], hl[4];
    c_reg[0] = c0[(b0+rA)*H_ + u]   * mA0;
    c_reg[1] = c0[(b0+rA)*H_ + u+1] * mA0;
    c_reg[2] = c0[(b0+rB)*H_ + u]   * mB0;
    c_reg[3] = c0[(b0+rB)*H_ + u+1] * mB0;
    *(float2*)&hsh[rA*68 + u] =
        make_float2(tf32f(h0[(b0+rA)*H_ + u])*mA0, tf32f(h0[(b0+rA)*H_ + u+1])*mA0);
    *(float2*)&hsh[rB*68 + u] =
        make_float2(tf32f(h0[(b0+rB)*H_ + u])*mB0, tf32f(h0[(b0+rB)*H_ + u+1])*mB0);
    hl[0] = hl[1] = hl[2] = hl[3] = 0.f;

    // prologue: block-coalesced prefetch of gin[t=0] into buf 0 (stride 264)
    {
        const float* src = g_gin + (size_t)b0 * G_;
        #pragma unroll
        for (int j = 0; j < 4; j++) {
            int q = tid + j*256;           // float4 tasks 0..1023
            int r = q >> 6, c4 = (q & 63) * 4;
            cp16(ginb + r*264 + c4, src + r*G_ + c4);
        }
        asm volatile("cp.async.commit_group;");
        asm volatile("cp.async.wait_group 0;");
    }
    __syncthreads();

    for (int t = 0; t < T_; t++) {
        // prefetch gin[t+1] into other buffer (consumed next step,
        // published by this step's trailing wait+barrier)
        if (t + 1 < T_) {
            float* dst = ginb + ((t+1)&1) * 4224;
            const float* src = g_gin + (size_t)((t+1)*B_ + b0) * G_;
            #pragma unroll
            for (int j = 0; j < 4; j++) {
                int q = tid + j*256;
                int r = q >> 6, c4 = (q & 63) * 4;
                cp16(dst + r*264 + c4, src + r*G_ + c4);
            }
            asm volatile("cp.async.commit_group;");
        }

        // ---- heads reduce + output for step t-2 ----
        if (t >= 2) {
            const float* pb = pbuf + ((t-2)&1) * 1152;
            float s = pb[0*288 + rrow*18 + rcol] + pb[1*288 + rrow*18 + rcol]
                    + pb[2*288 + rrow*18 + rcol] + pb[3*288 + rrow*18 + rcol]
                    + rbias;
            size_t r = (size_t)(t-2)*B_ + b0 + rrow;
            if (rcol < 15) out[r*A_ + rcol] = s;
            else           out[(size_t)TB_*A_ + r] = s;
        }

        // ---- gates = h @ Whh^T (4 gate-tiles x 8 units per warp) ----
        const float* hb = hsh + (t&1) * 1088;
        float acc[4][4];
        #pragma unroll
        for (int g = 0; g < 4; g++)
            #pragma unroll
            for (int j = 0; j < 4; j++) acc[g][j] = 0.f;

        #pragma unroll
        for (int kt = 0; kt < 8; kt++) {
            int k0 = kt*8;
            unsigned a[4];
            a[0] = __float_as_uint(hb[rA*68 + k0 + qc]);
            a[1] = __float_as_uint(hb[rB*68 + k0 + qc]);
            a[2] = __float_as_uint(hb[rA*68 + k0 + qc + 4]);
            a[3] = __float_as_uint(hb[rB*68 + k0 + qc + 4]);
            #pragma unroll
            for (int g = 0; g < 4; g++)
                mma8(acc[g], a, bf0[kt][g], bf1[kt][g]);
        }
        // acc[g] = {(rA,u), (rA,u+1), (rB,u), (rB,u+1)}

        // ---- heads partial for step t-1 (reads zs[(t-1)&1]) ----
        if (t) {
            const float* zb = zs + ((t-1)&1) * 1088;
            float* pw = pbuf + ((t-1)&1) * 1152;
            float pacc[4] = {0.f, 0.f, 0.f, 0.f};
            #pragma unroll
            for (int i = 0; i < 2; i++) {
                int k0 = (ks*2 + i)*8;
                unsigned a[4];
                a[0] = tf32_rna(zb[qr*68 + k0 + qc]);
                a[1] = tf32_rna(zb[(qr+8)*68 + k0 + qc]);
                a[2] = tf32_rna(zb[qr*68 + k0 + qc + 4]);
                a[3] = tf32_rna(zb[(qr+8)*68 + k0 + qc + 4]);
                mma8(pacc, a, hb0[i], hb1[i]);
            }
            *(float2*)&pw[ks*288 + qr*18 + n0 + 2*qc]     = make_float2(pacc[0], pacc[1]);
            *(float2*)&pw[ks*288 + (qr+8)*18 + n0 + 2*qc] = make_float2(pacc[2], pacc[3]);
        }

        // ---- cell update (gate order i,f,g,o), fully in registers ----
        const float* gv = ginb + (t&1) * 4224;
        float2 giA = *(const float2*)&gv[rA*264 +       u];
        float2 gfA = *(const float2*)&gv[rA*264 +  64 + u];
        float2 ggA = *(const float2*)&gv[rA*264 + 128 + u];
        float2 goA = *(const float2*)&gv[rA*264 + 192 + u];
        float2 giB = *(const float2*)&gv[rB*264 +       u];
        float2 gfB = *(const float2*)&gv[rB*264 +  64 + u];
        float2 ggB = *(const float2*)&gv[rB*264 + 128 + u];
        float2 goB = *(const float2*)&gv[rB*264 + 192 + u];

        float gi[4] = {acc[0][0]+giA.x, acc[0][1]+giA.y, acc[0][2]+giB.x, acc[0][3]+giB.y};
        float gf[4] = {acc[1][0]+gfA.x, acc[1][1]+gfA.y, acc[1][2]+gfB.x, acc[1][3]+gfB.y};
        float gg[4] = {acc[2][0]+ggA.x, acc[2][1]+ggA.y, acc[2][2]+ggB.x, acc[2][3]+ggB.y};
        float go[4] = {acc[3][0]+goA.x, acc[3][1]+goA.y, acc[3][2]+goB.x, acc[3][3]+goB.y};

        float mnA = 1.0f, mnB = 1.0f;
        if (t + 1 < T_) {
            mnA = 1.0f - done_s[(t+1)*16 + rA];
            mnB = 1.0f - done_s[(t+1)*16 + rB];
        }

        float hr[4];
        #pragma unroll
        for (int i = 0; i < 4; i++) {
            float mn = (i < 2) ? mnA : mnB;
            float cn = fsig_fast(gf[i])*c_reg[i] + fsig_fast(gi[i])*ftanh_fast(gg[i]);
            float hn = fsig_fast(go[i])*ftanh_fast(cn);
            c_reg[i] = cn * mn;                 // pre-mask for next step
            hr[i] = tf32f(hn) * mn;             // pre-round + pre-mask
            hl[i] = hn;
        }
        // write next-step h (other buffer) + exact z (this parity)
        float* hn_ = hsh + ((t+1)&1) * 1088;
        *(float2*)&hn_[rA*68 + u] = make_float2(hr[0], hr[1]);
        *(float2*)&hn_[rB*68 + u] = make_float2(hr[2], hr[3]);
        float* zw = zs + (t&1) * 1088;
        *(float2*)&zw[rA*68 + u] = make_float2(hl[0], hl[1]);
        *(float2*)&zw[rB*68 + u] = make_float2(hl[2], hl[3]);

        // publish: gin[t+1] copies (cross-thread) + hsh/zs/pbuf
        if (t + 1 < T_) asm volatile("cp.async.wait_group 0;");
        __syncthreads();
    }

    // ---- tail: reduce(T-2); partial(T-1); reduce(T-1) ----
    {
        const float* pb = pbuf + ((T_-2)&1) * 1152;
        float s = pb[0*288 + rrow*18 + rcol] + pb[1*288 + rrow*18 + rcol]
                + pb[2*288 + rrow*18 + rcol] + pb[3*288 + rrow*18 + rcol]
                + rbias;
        size_t r = (size_t)(T_-2)*B_ + b0 + rrow;
        if (rcol < 15) out[r*A_ + rcol] = s;
        else           out[(size_t)TB_*A_ + r] = s;
    }
    {
        const float* zb = zs + ((T_-1)&1) * 1088;
        float* pw = pbuf + ((T_-1)&1) * 1152;
        float pacc[4] = {0.f, 0.f, 0.f, 0.f};
        #pragma unroll
        for (int i = 0; i < 2; i++) {
            int k0 = (ks*2 + i)*8;
            unsigned a[4];
            a[0] = tf32_rna(zb[qr*68 + k0 + qc]);
            a[1] = tf32_rna(zb[(qr+8)*68 + k0 + qc]);
            a[2] = tf32_rna(zb[qr*68 + k0 + qc + 4]);
            a[3] = tf32_rna(zb[(qr+8)*68 + k0 + qc + 4]);
            mma8(pacc, a, hb0[i], hb1[i]);
        }
        *(float2*)&pw[ks*288 + qr*18 + n0 + 2*qc]     = make_float2(pacc[0], pacc[1]);
        *(float2*)&pw[ks*288 + (qr+8)*18 + n0 + 2*qc] = make_float2(pacc[2], pacc[3]);
        __syncthreads();
        const float* pb = pw;
        float s = pb[0*288 + rrow*18 + rcol] + pb[1*288 + rrow*18 + rcol]
                + pb[2*288 + rrow*18 + rcol] + pb[3*288 + rrow*18 + rcol]
                + rbias;
        size_t r = (size_t)(T_-1)*B_ + b0 + rrow;
        if (rcol < 15) out[r*A_ + rcol] = s;
        else           out[(size_t)TB_*A_ + r] = s;
    }

    // epilogue: hT, cT (layout: logits | vf | hT | cT), full precision
    const size_t OH = (size_t)TB_ * 16;
    *(float2*)&out[OH + (size_t)(b0+rA)*H_ + u]              = make_float2(hl[0], hl[1]);
    *(float2*)&out[OH + (size_t)(b0+rB)*H_ + u]              = make_float2(hl[2], hl[3]);
    *(float2*)&out[OH + (size_t)B_*H_ + (size_t)(b0+rA)*H_ + u] = make_float2(c_reg[0], c_reg[1]);
    *(float2*)&out[OH + (size_t)B_*H_ + (size_t)(b0+rB)*H_ + u] = make_float2(c_reg[2], c_reg[3]);
}

// ---------------------------------------------------------------------------
extern "C" void kernel_launch(void* const* d_in, const int* in_sizes, int n_in,
                              void* d_out, int out_size) {
    const float* x    = (const float*)d_in[0];
    const float* done = (const float*)d_in[1];
    const float* h0   = (const float*)d_in[2];
    const float* c0   = (const float*)d_in[3];
    const float* W1   = (const float*)d_in[4];
    const float* b1   = (const float*)d_in[5];
    const float* W2   = (const float*)d_in[6];
    const float* b2   = (const float*)d_in[7];
    const float* Wih  = (const float*)d_in[8];
    const float* bih  = (const float*)d_in[9];
    const float* Whh  = (const float*)d_in[10];
    const float* bhh  = (const float*)d_in[11];
    const float* Wa   = (const float*)d_in[12];
    const float* ba   = (const float*)d_in[13];
    const float* Wc   = (const float*)d_in[14];
    const float* bc   = (const float*)d_in[15];
    float* out = (float*)d_out;

    cudaFuncSetAttribute(k_encode, cudaFuncAttributeMaxDynamicSharedMemorySize, ENC_SMEM_F*4);
    cudaFuncSetAttribute(k_lstm,   cudaFuncAttributeMaxDynamicSharedMemorySize, LS_SMEM_F*4);

    k_encode<<<TB_/128, 256, ENC_SMEM_F*4>>>(x, W1, b1, W2, b2, Wih, bih, bhh);
    k_lstm<<<B_/16, 256, LS_SMEM_F*4>>>(done, h0, c0, Whh, Wa, ba, Wc, bc, out);
}

// round 13
// speedup vs baseline: 1.2050x; 1.0284x over previous
#include <cuda_runtime.h>

#define T_  128
#define B_  2048
#define F_  128
#define H_  64
#define A_  15
#define TB_ (T_*B_)
#define G_  256   // 4*H gates

// Scratch (allocation-free rule: __device__ globals)
__device__ float g_gin[(size_t)TB_ * G_];   // precomputed input-gate preactivations

// ---------------------------------------------------------------------------
// math helpers
// ---------------------------------------------------------------------------
__device__ __forceinline__ float ftanh_fast(float x) {
    float y;
    asm("tanh.approx.f32 %0, %1;" : "=f"(y) : "f"(x));
    return y;
}
// sigmoid(x) = 0.5*tanh(x/2) + 0.5 : 1 MUFU + FMAs
__device__ __forceinline__ float fsig_fast(float x) {
    return fmaf(0.5f, ftanh_fast(0.5f * x), 0.5f);
}
__device__ __forceinline__ unsigned tf32_rna(float x) {
    unsigned u; asm("cvt.rna.tf32.f32 %0, %1;" : "=r"(u) : "f"(x)); return u;
}
__device__ __forceinline__ float tf32f(float x) {
    return __uint_as_float(tf32_rna(x));
}
// d += a (m16k8, tf32) * b (k8n8, tf32)
__device__ __forceinline__ void mma8(float* d, const unsigned* a, unsigned b0, unsigned b1) {
    asm("mma.sync.aligned.m16n8k8.row.col.f32.tf32.tf32.f32 "
        "{%0,%1,%2,%3}, {%4,%5,%6,%7}, {%8,%9}, {%0,%1,%2,%3};"
        : "+f"(d[0]), "+f"(d[1]), "+f"(d[2]), "+f"(d[3])
        : "r"(a[0]), "r"(a[1]), "r"(a[2]), "r"(a[3]), "r"(b0), "r"(b1));
}
__device__ __forceinline__ void cp16(float* dst_smem, const float* src) {
    unsigned s = (unsigned)__cvta_generic_to_shared(dst_smem);
    asm volatile("cp.async.cg.shared.global [%0], [%1], 16;" :: "r"(s), "l"(src));
}

// ---------------------------------------------------------------------------
// Kernel 1: fused MLP encoder + input-gate GEMM, tf32 mma — ALL STAGES
// 1-term tf32 (A rounded once; B pre-rounded in smem). Activation smem
// (h1, ys) stored PRE-ROUNDED to tf32 so S2/S3 A-loads are raw bit loads.
// Scalar distinct-word B-LDS (1-phase-optimal; vectorized regressed twice).
// 256 threads (8 warps), 128 rows/block, 2048 blocks, 2 blocks/SM.
// ---------------------------------------------------------------------------
#define ENC_XS   0
#define ENC_WA   9216
#define ENC_H1   18432
#define ENC_BIAS 27136
#define ENC_SMEM_F 27520

__global__ __launch_bounds__(256, 2)
void k_encode(const float* __restrict__ x,
              const float* __restrict__ W1, const float* __restrict__ b1,
              const float* __restrict__ W2, const float* __restrict__ b2,
              const float* __restrict__ Wih, const float* __restrict__ bih,
              const float* __restrict__ bhh) {
    extern __shared__ float sm[];
    float* wA   = sm + ENC_WA;
    float* h1   = sm + ENC_H1;
    float* ys   = sm + ENC_XS;     // reuses xs region after S1
    float* wg   = sm + ENC_WA;     // raw->rounded Wih after S2 (spans WA+H1)
    float* bias = sm + ENC_BIAS;

    const int tid  = threadIdx.x;
    const int lane = tid & 31;
    const int w    = tid >> 5;
    const int row0 = blockIdx.x * 128;
    const int qr   = lane >> 2;    // 0..7
    const int qc   = lane & 3;     // 0..3
    const int m0   = w * 16;       // warp's private row tile

    // per-warp xs double buffer: [2][16][36]
    float* xw = sm + ENC_XS + w * 1152;
    const float* xg = x + (size_t)(row0 + m0) * F_;

    // issue quarter loads q0,q1 (per-warp cp.async groups)
    #pragma unroll
    for (int q = 0; q < 2; q++) {
        float* dst = xw + q * 576;
        #pragma unroll
        for (int j = 0; j < 4; j++) {
            int idx = lane + j*32;           // float4 index 0..127
            int r = idx >> 3, c4 = (idx & 7) * 4;
            cp16(dst + r*36 + c4, xg + r*F_ + q*32 + c4);
        }
        asm volatile("cp.async.commit_group;");
    }

    // W1 (tf32-rounded) + biases
    for (int i = tid; i < F_*H_; i += 256) {
        int k = i >> 6, n = i & 63;
        wA[k*72 + n] = tf32f(W1[i]);
    }
    for (int i = tid; i < G_; i += 256) bias[i] = bih[i] + bhh[i];
    for (int i = tid; i < H_;  i += 256) { bias[256+i] = b1[i]; bias[320+i] = b2[i]; }
    __syncthreads();

    // ========= S1: h1 = tf32(tanh(x @ W1 + b1)), K=128, 1-term ===========
    {
        float acc[8][4];
        #pragma unroll
        for (int nt = 0; nt < 8; nt++)
            #pragma unroll
            for (int j = 0; j < 4; j++) acc[nt][j] = 0.f;

        #pragma unroll
        for (int q = 0; q < 4; q++) {
            if (q < 3) asm volatile("cp.async.wait_group 1;");
            else       asm volatile("cp.async.wait_group 0;");
            __syncwarp();
            float* xb = xw + (q & 1) * 576;
            #pragma unroll
            for (int kt2 = 0; kt2 < 4; kt2++) {
                int k0 = kt2 * 8;            // local col in quarter
                int bk = q*32 + k0 + qc;     // global k for B
                unsigned a[4];
                a[0] = tf32_rna(xb[qr*36 + k0 + qc]);
                a[1] = tf32_rna(xb[(qr+8)*36 + k0 + qc]);
                a[2] = tf32_rna(xb[qr*36 + k0 + qc + 4]);
                a[3] = tf32_rna(xb[(qr+8)*36 + k0 + qc + 4]);
                #pragma unroll
                for (int nt = 0; nt < 8; nt++) {
                    int bn = nt*8 + qr;
                    unsigned bh0 = __float_as_uint(wA[bk*72 + bn]);
                    unsigned bh1 = __float_as_uint(wA[(bk+4)*72 + bn]);
                    mma8(acc[nt], a, bh0, bh1);
                }
            }
            __syncwarp();
            if (q < 2) {   // refill this buffer with quarter q+2
                float* dst = xw + (q & 1) * 576;
                #pragma unroll
                for (int j = 0; j < 4; j++) {
                    int idx = lane + j*32;
                    int r = idx >> 3, c4 = (idx & 7) * 4;
                    cp16(dst + r*36 + c4, xg + r*F_ + (q+2)*32 + c4);
                }
                asm volatile("cp.async.commit_group;");
            }
        }
        // store h1 PRE-ROUNDED to tf32 (S2 is 1-term; loads need no cvt)
        #pragma unroll
        for (int nt = 0; nt < 8; nt++) {
            int c = nt*8 + 2*qc;
            float bb0 = bias[256+c], bb1 = bias[256+c+1];
            *(float2*)&h1[(m0+qr)*68 + c] =
                make_float2(tf32f(ftanh_fast(acc[nt][0]+bb0)),
                            tf32f(ftanh_fast(acc[nt][1]+bb1)));
            *(float2*)&h1[(m0+qr+8)*68 + c] =
                make_float2(tf32f(ftanh_fast(acc[nt][2]+bb0)),
                            tf32f(ftanh_fast(acc[nt][3]+bb1)));
        }
    }
    __syncthreads();                    // all warps done with W1 region
    for (int i = tid; i < H_*H_; i += 256) {
        int k = i >> 6, n = i & 63;
        wA[k*72 + n] = tf32f(W2[i]);
    }
    __syncthreads();

    // ========= S2: ys = tf32(tanh(h1 @ W2 + b2)), K=64, 1-term ===========
    {
        float acc[8][4];
        #pragma unroll
        for (int nt = 0; nt < 8; nt++)
            #pragma unroll
            for (int j = 0; j < 4; j++) acc[nt][j] = 0.f;

        #pragma unroll 2
        for (int kt = 0; kt < 8; kt++) {
            int k0 = kt * 8;
            unsigned a[4];
            a[0] = __float_as_uint(h1[(m0+qr)*68 + k0 + qc]);
            a[1] = __float_as_uint(h1[(m0+qr+8)*68 + k0 + qc]);
            a[2] = __float_as_uint(h1[(m0+qr)*68 + k0 + qc + 4]);
            a[3] = __float_as_uint(h1[(m0+qr+8)*68 + k0 + qc + 4]);
            #pragma unroll
            for (int nt = 0; nt < 8; nt++) {
                int bk = k0 + qc, bn = nt*8 + qr;
                unsigned bh0 = __float_as_uint(wA[bk*72 + bn]);
                unsigned bh1 = __float_as_uint(wA[(bk+4)*72 + bn]);
                mma8(acc[nt], a, bh0, bh1);
            }
        }
        // store ys PRE-ROUNDED to tf32 (S3 is 1-term; loads need no cvt)
        #pragma unroll
        for (int nt = 0; nt < 8; nt++) {
            int c = nt*8 + 2*qc;
            float bb0 = bias[320+c], bb1 = bias[320+c+1];
            *(float2*)&ys[(m0+qr)*68 + c] =
                make_float2(tf32f(ftanh_fast(acc[nt][0]+bb0)),
                            tf32f(ftanh_fast(acc[nt][1]+bb1)));
            *(float2*)&ys[(m0+qr+8)*68 + c] =
                make_float2(tf32f(ftanh_fast(acc[nt][2]+bb0)),
                            tf32f(ftanh_fast(acc[nt][3]+bb1)));
        }
    }
    __syncthreads();                    // W2 + h1 regions now dead everywhere

    // async-load FULL raw Wih [256][68] into dead WA+H1 regions,
    // then round own elements in place (no cvt needed in S3).
    #pragma unroll
    for (int j = 0; j < 16; j++) {
        int f = tid + j*256;            // 0..4095 (float4 units)
        int n = f >> 4, c4 = (f & 15) * 4;
        cp16(wg + n*68 + c4, Wih + n*H_ + c4);
    }
    asm volatile("cp.async.commit_group;");
    asm volatile("cp.async.wait_group 0;");
    #pragma unroll
    for (int j = 0; j < 16; j++) {
        int f = tid + j*256;
        int n = f >> 4, c4 = (f & 15) * 4;
        float* p = wg + n*68 + c4;
        p[0] = tf32f(p[0]); p[1] = tf32f(p[1]);
        p[2] = tf32f(p[2]); p[3] = tf32f(p[3]);
    }
    __syncthreads();

    // ===== S3: gin = ys @ Wih^T + bias, K=64, N=256, 1-term, zero cvt ====
    #pragma unroll 1
    for (int ch = 0; ch < 4; ch++) {
        float acc[8][4];
        #pragma unroll
        for (int nt = 0; nt < 8; nt++)
            #pragma unroll
            for (int j = 0; j < 4; j++) acc[nt][j] = 0.f;

        #pragma unroll 2
        for (int kt = 0; kt < 8; kt++) {
            int k0 = kt * 8;
            unsigned a[4];
            a[0] = __float_as_uint(ys[(m0+qr)*68 + k0 + qc]);
            a[1] = __float_as_uint(ys[(m0+qr+8)*68 + k0 + qc]);
            a[2] = __float_as_uint(ys[(m0+qr)*68 + k0 + qc + 4]);
            a[3] = __float_as_uint(ys[(m0+qr+8)*68 + k0 + qc + 4]);
            #pragma unroll
            for (int nt = 0; nt < 8; nt++) {
                int bn = ch*64 + nt*8 + qr, bk = k0 + qc;
                mma8(acc[nt], a,
                     __float_as_uint(wg[bn*68 + bk]),
                     __float_as_uint(wg[bn*68 + bk + 4]));
            }
        }
        #pragma unroll
        for (int nt = 0; nt < 8; nt++) {
            int r = row0 + m0 + qr;
            int c = ch*64 + nt*8 + 2*qc;
            float bb0 = bias[c], bb1 = bias[c+1];
            *(float2*)&g_gin[(size_t)r*G_ + c] =
                make_float2(acc[nt][0] + bb0, acc[nt][1] + bb1);
            *(float2*)&g_gin[(size_t)(r+8)*G_ + c] =
                make_float2(acc[nt][2] + bb0, acc[nt][3] + bb1);
        }
    }
}

// ---------------------------------------------------------------------------
// Kernel 2: LSTM + fused heads, gate-ownership fragments.  (R12-exact.)
// ---------------------------------------------------------------------------
#define LS_HSH   0
#define LS_GINB  2176
#define LS_DONE  (LS_GINB + 8448)          // 10624
#define LS_ZS    (LS_DONE + T_*16)         // 12672
#define LS_PBUF  (LS_ZS + 2176)            // 14848
#define LS_SMEM_F (LS_PBUF + 2304)         // 17152

__global__ __launch_bounds__(256, 1)
void k_lstm(const float* __restrict__ done,
            const float* __restrict__ h0, const float* __restrict__ c0,
            const float* __restrict__ Whh,
            const float* __restrict__ Wa, const float* __restrict__ ba,
            const float* __restrict__ Wc, const float* __restrict__ bc,
            float* __restrict__ out) {
    extern __shared__ float sm[];
    float* hsh    = sm + LS_HSH;       // [2][16][68]
    float* ginb   = sm + LS_GINB;      // [2][16][264]
    float* done_s = sm + LS_DONE;      // [128][16]
    float* zs     = sm + LS_ZS;        // [2][16][68] exact z
    float* pbuf   = sm + LS_PBUF;      // [2][4][16][18]

    const int tid  = threadIdx.x;
    const int lane = tid & 31;
    const int w    = tid >> 5;
    const int b0   = blockIdx.x * 16;
    const int qr   = lane >> 2, qc = lane & 3;

    // gate-ownership B frags: warp w, gate g -> cols [g*64+8w, g*64+8w+8)
    unsigned bf0[8][4], bf1[8][4];
    #pragma unroll
    for (int kt = 0; kt < 8; kt++)
        #pragma unroll
        for (int g = 0; g < 4; g++) {
            int n = g*64 + w*8 + qr, k = kt*8 + qc;
            bf0[kt][g] = tf32_rna(Whh[n*H_ + k]);
            bf1[kt][g] = tf32_rna(Whh[n*H_ + k + 4]);
        }

    // heads frags: warp w -> n-half n0=(w&1)*8, k-slice ks=w>>1 (2 kt)
    const int n0 = (w & 1) * 8, ks = w >> 1;
    unsigned hb0[2], hb1[2];
    #pragma unroll
    for (int i = 0; i < 2; i++) {
        int k = (ks*2 + i)*8 + qc, j = n0 + qr;
        float v0 = (j < 15) ? Wa[k*A_ + j]     : Wc[k];
        float v1 = (j < 15) ? Wa[(k+4)*A_ + j] : Wc[k+4];
        hb0[i] = tf32_rna(v0);
        hb1[i] = tf32_rna(v1);
    }
    // reduce role: thread -> output (row rrow, col rcol)
    const int rcol = tid & 15, rrow = tid >> 4;
    const float rbias = (rcol < 15) ? ba[rcol] : bc[0];

    for (int i = tid; i < T_*16; i += 256)
        done_s[i] = done[(i>>4)*B_ + b0 + (i&15)];

    // cell ownership: rows rA=qr, rB=qr+8; units u, u+1 with u = 8w + 2qc
    const int rA = qr, rB = qr + 8;
    const int u  = w*8 + qc*2;
    const float mA0 = 1.0f - done[b0 + rA];
    const float mB0 = 1.0f - done[b0 + rB];
    float c_reg[4], hl[4];
    c_reg[0] = c0[(b0+rA)*H_ + u]   * mA0;
    c_reg[1] = c0[(b0+rA)*H_ + u+1] * mA0;
    c_reg[2] = c0[(b0+rB)*H_ + u]   * mB0;
    c_reg[3] = c0[(b0+rB)*H_ + u+1] * mB0;
    *(float2*)&hsh[rA*68 + u] =
        make_float2(tf32f(h0[(b0+rA)*H_ + u])*mA0, tf32f(h0[(b0+rA)*H_ + u+1])*mA0);
    *(float2*)&hsh[rB*68 + u] =
        make_float2(tf32f(h0[(b0+rB)*H_ + u])*mB0, tf32f(h0[(b0+rB)*H_ + u+1])*mB0);
    hl[0] = hl[1] = hl[2] = hl[3] = 0.f;

    // prologue: block-coalesced prefetch of gin[t=0] into buf 0 (stride 264)
    {
        const float* src = g_gin + (size_t)b0 * G_;
        #pragma unroll
        for (int j = 0; j < 4; j++) {
            int q = tid + j*256;           // float4 tasks 0..1023
            int r = q >> 6, c4 = (q & 63) * 4;
            cp16(ginb + r*264 + c4, src + r*G_ + c4);
        }
        asm volatile("cp.async.commit_group;");
        asm volatile("cp.async.wait_group 0;");
    }
    __syncthreads();

    for (int t = 0; t < T_; t++) {
        // prefetch gin[t+1] into other buffer (consumed next step,
        // published by this step's trailing wait+barrier)
        if (t + 1 < T_) {
            float* dst = ginb + ((t+1)&1) * 4224;
            const float* src = g_gin + (size_t)((t+1)*B_ + b0) * G_;
            #pragma unroll
            for (int j = 0; j < 4; j++) {
                int q = tid + j*256;
                int r = q >> 6, c4 = (q & 63) * 4;
                cp16(dst + r*264 + c4, src + r*G_ + c4);
            }
            asm volatile("cp.async.commit_group;");
        }

        // ---- heads reduce + output for step t-2 ----
        if (t >= 2) {
            const float* pb = pbuf + ((t-2)&1) * 1152;
            float s = pb[0*288 + rrow*18 + rcol] + pb[1*288 + rrow*18 + rcol]
                    + pb[2*288 + rrow*18 + rcol] + pb[3*288 + rrow*18 + rcol]
                    + rbias;
            size_t r = (size_t)(t-2)*B_ + b0 + rrow;
            if (rcol < 15) out[r*A_ + rcol] = s;
            else           out[(size_t)TB_*A_ + r] = s;
        }

        // ---- gates = h @ Whh^T (4 gate-tiles x 8 units per warp) ----
        const float* hb = hsh + (t&1) * 1088;
        float acc[4][4];
        #pragma unroll
        for (int g = 0; g < 4; g++)
            #pragma unroll
            for (int j = 0; j < 4; j++) acc[g][j] = 0.f;

        #pragma unroll
        for (int kt = 0; kt < 8; kt++) {
            int k0 = kt*8;
            unsigned a[4];
            a[0] = __float_as_uint(hb[rA*68 + k0 + qc]);
            a[1] = __float_as_uint(hb[rB*68 + k0 + qc]);
            a[2] = __float_as_uint(hb[rA*68 + k0 + qc + 4]);
            a[3] = __float_as_uint(hb[rB*68 + k0 + qc + 4]);
            #pragma unroll
            for (int g = 0; g < 4; g++)
                mma8(acc[g], a, bf0[kt][g], bf1[kt][g]);
        }
        // acc[g] = {(rA,u), (rA,u+1), (rB,u), (rB,u+1)}

        // ---- heads partial for step t-1 (reads zs[(t-1)&1]) ----
        if (t) {
            const float* zb = zs + ((t-1)&1) * 1088;
            float* pw = pbuf + ((t-1)&1) * 1152;
            float pacc[4] = {0.f, 0.f, 0.f, 0.f};
            #pragma unroll
            for (int i = 0; i < 2; i++) {
                int k0 = (ks*2 + i)*8;
                unsigned a[4];
                a[0] = tf32_rna(zb[qr*68 + k0 + qc]);
                a[1] = tf32_rna(zb[(qr+8)*68 + k0 + qc]);
                a[2] = tf32_rna(zb[qr*68 + k0 + qc + 4]);
                a[3] = tf32_rna(zb[(qr+8)*68 + k0 + qc + 4]);
                mma8(pacc, a, hb0[i], hb1[i]);
            }
            *(float2*)&pw[ks*288 + qr*18 + n0 + 2*qc]     = make_float2(pacc[0], pacc[1]);
            *(float2*)&pw[ks*288 + (qr+8)*18 + n0 + 2*qc] = make_float2(pacc[2], pacc[3]);
        }

        // ---- cell update (gate order i,f,g,o), fully in registers ----
        const float* gv = ginb + (t&1) * 4224;
        float2 giA = *(const float2*)&gv[rA*264 +       u];
        float2 gfA = *(const float2*)&gv[rA*264 +  64 + u];
        float2 ggA = *(const float2*)&gv[rA*264 + 128 + u];
        float2 goA = *(const float2*)&gv[rA*264 + 192 + u];
        float2 giB = *(const float2*)&gv[rB*264 +       u];
        float2 gfB = *(const float2*)&gv[rB*264 +  64 + u];
        float2 ggB = *(const float2*)&gv[rB*264 + 128 + u];
        float2 goB = *(const float2*)&gv[rB*264 + 192 + u];

        float gi[4] = {acc[0][0]+giA.x, acc[0][1]+giA.y, acc[0][2]+giB.x, acc[0][3]+giB.y};
        float gf[4] = {acc[1][0]+gfA.x, acc[1][1]+gfA.y, acc[1][2]+gfB.x, acc[1][3]+gfB.y};
        float gg[4] = {acc[2][0]+ggA.x, acc[2][1]+ggA.y, acc[2][2]+ggB.x, acc[2][3]+ggB.y};
        float go[4] = {acc[3][0]+goA.x, acc[3][1]+goA.y, acc[3][2]+goB.x, acc[3][3]+goB.y};

        float mnA = 1.0f, mnB = 1.0f;
        if (t + 1 < T_) {
            mnA = 1.0f - done_s[(t+1)*16 + rA];
            mnB = 1.0f - done_s[(t+1)*16 + rB];
        }

        float hr[4];
        #pragma unroll
        for (int i = 0; i < 4; i++) {
            float mn = (i < 2) ? mnA : mnB;
            float cn = fsig_fast(gf[i])*c_reg[i] + fsig_fast(gi[i])*ftanh_fast(gg[i]);
            float hn = fsig_fast(go[i])*ftanh_fast(cn);
            c_reg[i] = cn * mn;                 // pre-mask for next step
            hr[i] = tf32f(hn) * mn;             // pre-round + pre-mask
            hl[i] = hn;
        }
        // write next-step h (other buffer) + exact z (this parity)
        float* hn_ = hsh + ((t+1)&1) * 1088;
        *(float2*)&hn_[rA*68 + u] = make_float2(hr[0], hr[1]);
        *(float2*)&hn_[rB*68 + u] = make_float2(hr[2], hr[3]);
        float* zw = zs + (t&1) * 1088;
        *(float2*)&zw[rA*68 + u] = make_float2(hl[0], hl[1]);
        *(float2*)&zw[rB*68 + u] = make_float2(hl[2], hl[3]);

        // publish: gin[t+1] copies (cross-thread) + hsh/zs/pbuf
        if (t + 1 < T_) asm volatile("cp.async.wait_group 0;");
        __syncthreads();
    }

    // ---- tail: reduce(T-2); partial(T-1); reduce(T-1) ----
    {
        const float* pb = pbuf + ((T_-2)&1) * 1152;
        float s = pb[0*288 + rrow*18 + rcol] + pb[1*288 + rrow*18 + rcol]
                + pb[2*288 + rrow*18 + rcol] + pb[3*288 + rrow*18 + rcol]
                + rbias;
        size_t r = (size_t)(T_-2)*B_ + b0 + rrow;
        if (rcol < 15) out[r*A_ + rcol] = s;
        else           out[(size_t)TB_*A_ + r] = s;
    }
    {
        const float* zb = zs + ((T_-1)&1) * 1088;
        float* pw = pbuf + ((T_-1)&1) * 1152;
        float pacc[4] = {0.f, 0.f, 0.f, 0.f};
        #pragma unroll
        for (int i = 0; i < 2; i++) {
            int k0 = (ks*2 + i)*8;
            unsigned a[4];
            a[0] = tf32_rna(zb[qr*68 + k0 + qc]);
            a[1] = tf32_rna(zb[(qr+8)*68 + k0 + qc]);
            a[2] = tf32_rna(zb[qr*68 + k0 + qc + 4]);
            a[3] = tf32_rna(zb[(qr+8)*68 + k0 + qc + 4]);
            mma8(pacc, a, hb0[i], hb1[i]);
        }
        *(float2*)&pw[ks*288 + qr*18 + n0 + 2*qc]     = make_float2(pacc[0], pacc[1]);
        *(float2*)&pw[ks*288 + (qr+8)*18 + n0 + 2*qc] = make_float2(pacc[2], pacc[3]);
        __syncthreads();
        const float* pb = pw;
        float s = pb[0*288 + rrow*18 + rcol] + pb[1*288 + rrow*18 + rcol]
                + pb[2*288 + rrow*18 + rcol] + pb[3*288 + rrow*18 + rcol]
                + rbias;
        size_t r = (size_t)(T_-1)*B_ + b0 + rrow;
        if (rcol < 15) out[r*A_ + rcol] = s;
        else           out[(size_t)TB_*A_ + r] = s;
    }

    // epilogue: hT, cT (layout: logits | vf | hT | cT), full precision
    const size_t OH = (size_t)TB_ * 16;
    *(float2*)&out[OH + (size_t)(b0+rA)*H_ + u]              = make_float2(hl[0], hl[1]);
    *(float2*)&out[OH + (size_t)(b0+rB)*H_ + u]              = make_float2(hl[2], hl[3]);
    *(float2*)&out[OH + (size_t)B_*H_ + (size_t)(b0+rA)*H_ + u] = make_float2(c_reg[0], c_reg[1]);
    *(float2*)&out[OH + (size_t)B_*H_ + (size_t)(b0+rB)*H_ + u] = make_float2(c_reg[2], c_reg[3]);
}

// ---------------------------------------------------------------------------
extern "C" void kernel_launch(void* const* d_in, const int* in_sizes, int n_in,
                              void* d_out, int out_size) {
    const float* x    = (const float*)d_in[0];
    const float* done = (const float*)d_in[1];
    const float* h0   = (const float*)d_in[2];
    const float* c0   = (const float*)d_in[3];
    const float* W1   = (const float*)d_in[4];
    const float* b1   = (const float*)d_in[5];
    const float* W2   = (const float*)d_in[6];
    const float* b2   = (const float*)d_in[7];
    const float* Wih  = (const float*)d_in[8];
    const float* bih  = (const float*)d_in[9];
    const float* Whh  = (const float*)d_in[10];
    const float* bhh  = (const float*)d_in[11];
    const float* Wa   = (const float*)d_in[12];
    const float* ba   = (const float*)d_in[13];
    const float* Wc   = (const float*)d_in[14];
    const float* bc   = (const float*)d_in[15];
    float* out = (float*)d_out;

    cudaFuncSetAttribute(k_encode, cudaFuncAttributeMaxDynamicSharedMemorySize, ENC_SMEM_F*4);
    cudaFuncSetAttribute(k_lstm,   cudaFuncAttributeMaxDynamicSharedMemorySize, LS_SMEM_F*4);

    k_encode<<<TB_/128, 256, ENC_SMEM_F*4>>>(x, W1, b1, W2, b2, Wih, bih, bhh);
    k_lstm<<<B_/16, 256, LS_SMEM_F*4>>>(done, h0, c0, Whh, Wa, ba, Wc, bc, out);
}

// round 14
// speedup vs baseline: 1.2307x; 1.0213x over previous
#include <cuda_runtime.h>

#define T_  128
#define B_  2048
#define F_  128
#define H_  64
#define A_  15
#define TB_ (T_*B_)
#define G_  256   // 4*H gates

// ---------------------------------------------------------------------------
// math helpers
// ---------------------------------------------------------------------------
__device__ __forceinline__ float ftanh_fast(float x) {
    float y;
    asm("tanh.approx.f32 %0, %1;" : "=f"(y) : "f"(x));
    return y;
}
__device__ __forceinline__ float fsig_fast(float x) {
    return fmaf(0.5f, ftanh_fast(0.5f * x), 0.5f);
}
__device__ __forceinline__ unsigned tf32_rna(float x) {
    unsigned u; asm("cvt.rna.tf32.f32 %0, %1;" : "=r"(u) : "f"(x)); return u;
}
__device__ __forceinline__ float tf32f(float x) {
    return __uint_as_float(tf32_rna(x));
}
// d += a (m16k8, tf32) * b (k8n8, tf32)
__device__ __forceinline__ void mma8(float* d, const unsigned* a, unsigned b0, unsigned b1) {
    asm("mma.sync.aligned.m16n8k8.row.col.f32.tf32.tf32.f32 "
        "{%0,%1,%2,%3}, {%4,%5,%6,%7}, {%8,%9}, {%0,%1,%2,%3};"
        : "+f"(d[0]), "+f"(d[1]), "+f"(d[2]), "+f"(d[3])
        : "r"(a[0]), "r"(a[1]), "r"(a[2]), "r"(a[3]), "r"(b0), "r"(b1));
}
__device__ __forceinline__ void cp16(float* dst_smem, const float* src) {
    unsigned s = (unsigned)__cvta_generic_to_shared(dst_smem);
    asm volatile("cp.async.cg.shared.global [%0], [%1], 16;" :: "r"(s), "l"(src));
}

// ---------------------------------------------------------------------------
// FULLY-FUSED kernel: per-step MLP encoder + LSTM + heads. 128 blocks of
// 256 threads, 16 batch rows/block, 1 block/SM.
// Per step t:
//   S1: h1 = tf32(tanh(x(t) @ W1 + b1))      warp w -> n-cols [8w,8w+8)
//   S2: ys = tf32(tanh(h1 @ W2 + b2))        same n-slicing
//   S3 + gates: acc[g] = (bih+bhh) + ys@Wih^T + h@Whh^T, with gate-ownership
//       n-tiling (warp w -> cols g*64+8w..+8) -> gin NEVER touches memory.
//   heads partial(t-1), cell update in registers, 3 syncs/step.
// x double-buffered via cp.async (published by end-of-step wait+barrier).
// All weights tf32-pre-rounded in smem; activations pre-rounded at write.
// smem (floats): W1s[128][72] | W2s[64][72] | WGs[256][68] | xs[2][16][132] |
//   h1[16][68] | ys[16][68] | hsh[2][16][68] | zs[2][16][68] |
//   pbuf[2][4][16][18] | done[128][16] | bias 128  = 46464 fl = 185856 B
// ---------------------------------------------------------------------------
#define LSF_W1   0
#define LSF_W2   9216
#define LSF_WG   (LSF_W2 + 4608)           // 13824
#define LSF_XS   (LSF_WG + 17408)          // 31232
#define LSF_H1   (LSF_XS + 4224)           // 35456
#define LSF_YS   (LSF_H1 + 1088)           // 36544
#define LSF_HSH  (LSF_YS + 1088)           // 37632
#define LSF_ZS   (LSF_HSH + 2176)          // 39808
#define LSF_PBUF (LSF_ZS + 2176)           // 41984
#define LSF_DONE (LSF_PBUF + 2304)         // 44288
#define LSF_BIAS (LSF_DONE + 2048)         // 46336
#define LSF_SMEM (LSF_BIAS + 128)          // 46464

__global__ __launch_bounds__(256, 1)
void k_fused(const float* __restrict__ x,    const float* __restrict__ done,
             const float* __restrict__ h0,   const float* __restrict__ c0,
             const float* __restrict__ W1,   const float* __restrict__ b1,
             const float* __restrict__ W2,   const float* __restrict__ b2,
             const float* __restrict__ Wih,  const float* __restrict__ bih,
             const float* __restrict__ Whh,  const float* __restrict__ bhh,
             const float* __restrict__ Wa,   const float* __restrict__ ba,
             const float* __restrict__ Wc,   const float* __restrict__ bc,
             float* __restrict__ out) {
    extern __shared__ float sm[];
    float* W1s    = sm + LSF_W1;       // [128][72] k-major, tf32
    float* W2s    = sm + LSF_W2;       // [64][72]  k-major, tf32
    float* WGs    = sm + LSF_WG;       // [256][68] n-major (Wih[n][k]), tf32
    float* xs     = sm + LSF_XS;       // [2][16][132]
    float* h1     = sm + LSF_H1;       // [16][68] tf32
    float* ys     = sm + LSF_YS;       // [16][68] tf32
    float* hsh    = sm + LSF_HSH;      // [2][16][68] tf32, pre-masked
    float* zs     = sm + LSF_ZS;       // [2][16][68] exact z
    float* pbuf   = sm + LSF_PBUF;     // [2][4][16][18]
    float* done_s = sm + LSF_DONE;     // [128][16]
    float* bsm    = sm + LSF_BIAS;     // b1 [64] | b2 [64]

    const int tid  = threadIdx.x;
    const int lane = tid & 31;
    const int w    = tid >> 5;
    const int b0   = blockIdx.x * 16;
    const int qr   = lane >> 2, qc = lane & 3;
    const int u    = w*8 + qc*2;       // unit pair base (gate-ownership)
    const int nc1  = w*8 + 2*qc;       // S1/S2 output col pair base

    // gates B frags: warp w, gate g -> cols [g*64+8w, g*64+8w+8)
    unsigned bf0[8][4], bf1[8][4];
    #pragma unroll
    for (int kt = 0; kt < 8; kt++)
        #pragma unroll
        for (int g = 0; g < 4; g++) {
            int n = g*64 + w*8 + qr, k = kt*8 + qc;
            bf0[kt][g] = tf32_rna(Whh[n*H_ + k]);
            bf1[kt][g] = tf32_rna(Whh[n*H_ + k + 4]);
        }
    // gate bias pairs (bih+bhh) for this thread's fragment cols
    float gb[4][2];
    #pragma unroll
    for (int g = 0; g < 4; g++) {
        gb[g][0] = bih[g*64 + u]     + bhh[g*64 + u];
        gb[g][1] = bih[g*64 + u + 1] + bhh[g*64 + u + 1];
    }
    // heads frags: warp w -> n-half n0=(w&1)*8, k-slice ks=w>>1 (2 kt)
    const int n0 = (w & 1) * 8, ks = w >> 1;
    unsigned hb0[2], hb1[2];
    #pragma unroll
    for (int i = 0; i < 2; i++) {
        int k = (ks*2 + i)*8 + qc, j = n0 + qr;
        float v0 = (j < 15) ? Wa[k*A_ + j]     : Wc[k];
        float v1 = (j < 15) ? Wa[(k+4)*A_ + j] : Wc[k+4];
        hb0[i] = tf32_rna(v0);
        hb1[i] = tf32_rna(v1);
    }
    const int rcol = tid & 15, rrow = tid >> 4;
    const float rbias = (rcol < 15) ? ba[rcol] : bc[0];

    // prologue: prefetch x(0) tile
    {
        const float* src = x + (size_t)b0 * F_;
        #pragma unroll
        for (int j = 0; j < 2; j++) {
            int q = tid + j*256;           // 0..511 float4 tasks
            int r = q >> 5, c4 = (q & 31) * 4;
            cp16(xs + r*132 + c4, src + r*F_ + c4);
        }
        asm volatile("cp.async.commit_group;");
    }

    // weights -> smem (tf32-rounded), biases, done
    for (int i = tid; i < F_*H_; i += 256) {
        int k = i >> 6, n = i & 63;
        W1s[k*72 + n] = tf32f(W1[i]);
    }
    for (int i = tid; i < H_*H_; i += 256) {
        int k = i >> 6, n = i & 63;
        W2s[k*72 + n] = tf32f(W2[i]);
    }
    for (int i = tid; i < G_*H_; i += 256) {
        int n = i >> 6, k = i & 63;
        WGs[n*68 + k] = tf32f(Wih[i]);
    }
    for (int i = tid; i < H_; i += 256) { bsm[i] = b1[i]; bsm[64+i] = b2[i]; }
    for (int i = tid; i < T_*16; i += 256)
        done_s[i] = done[(i>>4)*B_ + b0 + (i&15)];

    // state init (cell ownership: rows rA=qr, rB=qr+8; units u, u+1)
    const int rA = qr, rB = qr + 8;
    const float mA0 = 1.0f - done[b0 + rA];
    const float mB0 = 1.0f - done[b0 + rB];
    float c_reg[4], hl[4];
    c_reg[0] = c0[(b0+rA)*H_ + u]   * mA0;
    c_reg[1] = c0[(b0+rA)*H_ + u+1] * mA0;
    c_reg[2] = c0[(b0+rB)*H_ + u]   * mB0;
    c_reg[3] = c0[(b0+rB)*H_ + u+1] * mB0;
    *(float2*)&hsh[rA*68 + u] =
        make_float2(tf32f(h0[(b0+rA)*H_ + u])*mA0, tf32f(h0[(b0+rA)*H_ + u+1])*mA0);
    *(float2*)&hsh[rB*68 + u] =
        make_float2(tf32f(h0[(b0+rB)*H_ + u])*mB0, tf32f(h0[(b0+rB)*H_ + u+1])*mB0);
    hl[0] = hl[1] = hl[2] = hl[3] = 0.f;

    asm volatile("cp.async.wait_group 0;");
    __syncthreads();

    for (int t = 0; t < T_; t++) {
        // prefetch x(t+1) into other buffer
        if (t + 1 < T_) {
            float* dst = xs + ((t+1)&1) * 2112;
            const float* src = x + (size_t)((t+1)*B_ + b0) * F_;
            #pragma unroll
            for (int j = 0; j < 2; j++) {
                int q = tid + j*256;
                int r = q >> 5, c4 = (q & 31) * 4;
                cp16(dst + r*132 + c4, src + r*F_ + c4);
            }
            asm volatile("cp.async.commit_group;");
        }

        // ---- heads reduce + output for step t-2 ----
        if (t >= 2) {
            const float* pb = pbuf + ((t-2)&1) * 1152;
            float s = pb[0*288 + rrow*18 + rcol] + pb[1*288 + rrow*18 + rcol]
                    + pb[2*288 + rrow*18 + rcol] + pb[3*288 + rrow*18 + rcol]
                    + rbias;
            size_t r = (size_t)(t-2)*B_ + b0 + rrow;
            if (rcol < 15) out[r*A_ + rcol] = s;
            else           out[(size_t)TB_*A_ + r] = s;
        }

        // ======== S1: h1 = tf32(tanh(x @ W1 + b1)), K=128 ========
        {
            const float* xb = xs + (t&1) * 2112;
            float a1[4] = {0.f, 0.f, 0.f, 0.f};
            #pragma unroll 4
            for (int kt = 0; kt < 16; kt++) {
                int k0 = kt*8;
                unsigned a[4];
                a[0] = tf32_rna(xb[rA*132 + k0 + qc]);
                a[1] = tf32_rna(xb[rB*132 + k0 + qc]);
                a[2] = tf32_rna(xb[rA*132 + k0 + qc + 4]);
                a[3] = tf32_rna(xb[rB*132 + k0 + qc + 4]);
                unsigned bh0 = __float_as_uint(W1s[(k0+qc)*72 + w*8 + qr]);
                unsigned bh1 = __float_as_uint(W1s[(k0+qc+4)*72 + w*8 + qr]);
                mma8(a1, a, bh0, bh1);
            }
            float bb0 = bsm[nc1], bb1 = bsm[nc1+1];
            *(float2*)&h1[rA*68 + nc1] =
                make_float2(tf32f(ftanh_fast(a1[0]+bb0)), tf32f(ftanh_fast(a1[1]+bb1)));
            *(float2*)&h1[rB*68 + nc1] =
                make_float2(tf32f(ftanh_fast(a1[2]+bb0)), tf32f(ftanh_fast(a1[3]+bb1)));
        }
        __syncthreads();

        // ======== S2: ys = tf32(tanh(h1 @ W2 + b2)), K=64 ========
        {
            float a2r[4] = {0.f, 0.f, 0.f, 0.f};
            #pragma unroll
            for (int kt = 0; kt < 8; kt++) {
                int k0 = kt*8;
                unsigned a[4];
                a[0] = __float_as_uint(h1[rA*68 + k0 + qc]);
                a[1] = __float_as_uint(h1[rB*68 + k0 + qc]);
                a[2] = __float_as_uint(h1[rA*68 + k0 + qc + 4]);
                a[3] = __float_as_uint(h1[rB*68 + k0 + qc + 4]);
                unsigned bh0 = __float_as_uint(W2s[(k0+qc)*72 + w*8 + qr]);
                unsigned bh1 = __float_as_uint(W2s[(k0+qc+4)*72 + w*8 + qr]);
                mma8(a2r, a, bh0, bh1);
            }
            float bb0 = bsm[64+nc1], bb1 = bsm[64+nc1+1];
            *(float2*)&ys[rA*68 + nc1] =
                make_float2(tf32f(ftanh_fast(a2r[0]+bb0)), tf32f(ftanh_fast(a2r[1]+bb1)));
            *(float2*)&ys[rB*68 + nc1] =
                make_float2(tf32f(ftanh_fast(a2r[2]+bb0)), tf32f(ftanh_fast(a2r[3]+bb1)));
        }
        __syncthreads();

        // ======== S3 + gates: acc[g] = bias + ys@Wih^T + h@Whh^T ========
        float acc[4][4];
        #pragma unroll
        for (int g = 0; g < 4; g++) {
            acc[g][0] = gb[g][0]; acc[g][1] = gb[g][1];
            acc[g][2] = gb[g][0]; acc[g][3] = gb[g][1];
        }
        #pragma unroll
        for (int kt = 0; kt < 8; kt++) {       // gin part (ys, raw loads)
            int k0 = kt*8;
            unsigned a[4];
            a[0] = __float_as_uint(ys[rA*68 + k0 + qc]);
            a[1] = __float_as_uint(ys[rB*68 + k0 + qc]);
            a[2] = __float_as_uint(ys[rA*68 + k0 + qc + 4]);
            a[3] = __float_as_uint(ys[rB*68 + k0 + qc + 4]);
            #pragma unroll
            for (int g = 0; g < 4; g++) {
                int bn = g*64 + w*8 + qr;
                mma8(acc[g], a,
                     __float_as_uint(WGs[bn*68 + k0 + qc]),
                     __float_as_uint(WGs[bn*68 + k0 + qc + 4]));
            }
        }
        {
            const float* hb = hsh + (t&1) * 1088;
            #pragma unroll
            for (int kt = 0; kt < 8; kt++) {   // recurrent part
                int k0 = kt*8;
                unsigned a[4];
                a[0] = __float_as_uint(hb[rA*68 + k0 + qc]);
                a[1] = __float_as_uint(hb[rB*68 + k0 + qc]);
                a[2] = __float_as_uint(hb[rA*68 + k0 + qc + 4]);
                a[3] = __float_as_uint(hb[rB*68 + k0 + qc + 4]);
                #pragma unroll
                for (int g = 0; g < 4; g++)
                    mma8(acc[g], a, bf0[kt][g], bf1[kt][g]);
            }
        }

        // ---- heads partial for step t-1 (reads zs[(t-1)&1]) ----
        if (t) {
            const float* zb = zs + ((t-1)&1) * 1088;
            float* pw = pbuf + ((t-1)&1) * 1152;
            float pacc[4] = {0.f, 0.f, 0.f, 0.f};
            #pragma unroll
            for (int i = 0; i < 2; i++) {
                int k0 = (ks*2 + i)*8;
                unsigned a[4];
                a[0] = tf32_rna(zb[qr*68 + k0 + qc]);
                a[1] = tf32_rna(zb[(qr+8)*68 + k0 + qc]);
                a[2] = tf32_rna(zb[qr*68 + k0 + qc + 4]);
                a[3] = tf32_rna(zb[(qr+8)*68 + k0 + qc + 4]);
                mma8(pacc, a, hb0[i], hb1[i]);
            }
            *(float2*)&pw[ks*288 + qr*18 + n0 + 2*qc]     = make_float2(pacc[0], pacc[1]);
            *(float2*)&pw[ks*288 + (qr+8)*18 + n0 + 2*qc] = make_float2(pacc[2], pacc[3]);
        }

        // ---- cell update (gate order i,f,g,o), fully in registers ----
        float mnA = 1.0f, mnB = 1.0f;
        if (t + 1 < T_) {
            mnA = 1.0f - done_s[(t+1)*16 + rA];
            mnB = 1.0f - done_s[(t+1)*16 + rB];
        }
        float hr[4];
        #pragma unroll
        for (int i = 0; i < 4; i++) {
            float mn = (i < 2) ? mnA : mnB;
            float cn = fsig_fast(acc[1][i])*c_reg[i]
                     + fsig_fast(acc[0][i])*ftanh_fast(acc[2][i]);
            float hn = fsig_fast(acc[3][i])*ftanh_fast(cn);
            c_reg[i] = cn * mn;                 // pre-mask for next step
            hr[i] = tf32f(hn) * mn;             // pre-round + pre-mask
            hl[i] = hn;
        }
        float* hn_ = hsh + ((t+1)&1) * 1088;
        *(float2*)&hn_[rA*68 + u] = make_float2(hr[0], hr[1]);
        *(float2*)&hn_[rB*68 + u] = make_float2(hr[2], hr[3]);
        float* zw = zs + (t&1) * 1088;
        *(float2*)&zw[rA*68 + u] = make_float2(hl[0], hl[1]);
        *(float2*)&zw[rB*68 + u] = make_float2(hl[2], hl[3]);

        // publish: x(t+1) copies + hsh/zs/pbuf
        if (t + 1 < T_) asm volatile("cp.async.wait_group 0;");
        __syncthreads();
    }

    // ---- tail: reduce(T-2); partial(T-1); reduce(T-1) ----
    {
        const float* pb = pbuf + ((T_-2)&1) * 1152;
        float s = pb[0*288 + rrow*18 + rcol] + pb[1*288 + rrow*18 + rcol]
                + pb[2*288 + rrow*18 + rcol] + pb[3*288 + rrow*18 + rcol]
                + rbias;
        size_t r = (size_t)(T_-2)*B_ + b0 + rrow;
        if (rcol < 15) out[r*A_ + rcol] = s;
        else           out[(size_t)TB_*A_ + r] = s;
    }
    {
        const float* zb = zs + ((T_-1)&1) * 1088;
        float* pw = pbuf + ((T_-1)&1) * 1152;
        float pacc[4] = {0.f, 0.f, 0.f, 0.f};
        #pragma unroll
        for (int i = 0; i < 2; i++) {
            int k0 = (ks*2 + i)*8;
            unsigned a[4];
            a[0] = tf32_rna(zb[qr*68 + k0 + qc]);
            a[1] = tf32_rna(zb[(qr+8)*68 + k0 + qc]);
            a[2] = tf32_rna(zb[qr*68 + k0 + qc + 4]);
            a[3] = tf32_rna(zb[(qr+8)*68 + k0 + qc + 4]);
            mma8(pacc, a, hb0[i], hb1[i]);
        }
        *(float2*)&pw[ks*288 + qr*18 + n0 + 2*qc]     = make_float2(pacc[0], pacc[1]);
        *(float2*)&pw[ks*288 + (qr+8)*18 + n0 + 2*qc] = make_float2(pacc[2], pacc[3]);
        __syncthreads();
        float s = pw[0*288 + rrow*18 + rcol] + pw[1*288 + rrow*18 + rcol]
                + pw[2*288 + rrow*18 + rcol] + pw[3*288 + rrow*18 + rcol]
                + rbias;
        size_t r = (size_t)(T_-1)*B_ + b0 + rrow;
        if (rcol < 15) out[r*A_ + rcol] = s;
        else           out[(size_t)TB_*A_ + r] = s;
    }

    // epilogue: hT, cT (layout: logits | vf | hT | cT), full precision
    const size_t OH = (size_t)TB_ * 16;
    *(float2*)&out[OH + (size_t)(b0+rA)*H_ + u]                 = make_float2(hl[0], hl[1]);
    *(float2*)&out[OH + (size_t)(b0+rB)*H_ + u]                 = make_float2(hl[2], hl[3]);
    *(float2*)&out[OH + (size_t)B_*H_ + (size_t)(b0+rA)*H_ + u] = make_float2(c_reg[0], c_reg[1]);
    *(float2*)&out[OH + (size_t)B_*H_ + (size_t)(b0+rB)*H_ + u] = make_float2(c_reg[2], c_reg[3]);
}

// ---------------------------------------------------------------------------
extern "C" void kernel_launch(void* const* d_in, const int* in_sizes, int n_in,
                              void* d_out, int out_size) {
    const float* x    = (const float*)d_in[0];
    const float* done = (const float*)d_in[1];
    const float* h0   = (const float*)d_in[2];
    const float* c0   = (const float*)d_in[3];
    const float* W1   = (const float*)d_in[4];
    const float* b1   = (const float*)d_in[5];
    const float* W2   = (const float*)d_in[6];
    const float* b2   = (const float*)d_in[7];
    const float* Wih  = (const float*)d_in[8];
    const float* bih  = (const float*)d_in[9];
    const float* Whh  = (const float*)d_in[10];
    const float* bhh  = (const float*)d_in[11];
    const float* Wa   = (const float*)d_in[12];
    const float* ba   = (const float*)d_in[13];
    const float* Wc   = (const float*)d_in[14];
    const float* bc   = (const float*)d_in[15];
    float* out = (float*)d_out;

    cudaFuncSetAttribute(k_fused, cudaFuncAttributeMaxDynamicSharedMemorySize, LSF_SMEM*4);

    k_fused<<<B_/16, 256, LSF_SMEM*4>>>(x, done, h0, c0, W1, b1, W2, b2,
                                        Wih, bih, Whh, bhh, Wa, ba, Wc, bc, out);
}

// round 15
// speedup vs baseline: 1.2996x; 1.0561x over previous
#include <cuda_runtime.h>

#define T_  128
#define B_  2048
#define F_  128
#define H_  64
#define A_  15
#define TB_ (T_*B_)
#define G_  256   // 4*H gates

// ---------------------------------------------------------------------------
// math helpers
// ---------------------------------------------------------------------------
__device__ __forceinline__ float ftanh_fast(float x) {
    float y;
    asm("tanh.approx.f32 %0, %1;" : "=f"(y) : "f"(x));
    return y;
}
__device__ __forceinline__ float fsig_fast(float x) {
    return fmaf(0.5f, ftanh_fast(0.5f * x), 0.5f);
}
__device__ __forceinline__ unsigned tf32_rna(float x) {
    unsigned u; asm("cvt.rna.tf32.f32 %0, %1;" : "=r"(u) : "f"(x)); return u;
}
__device__ __forceinline__ float tf32f(float x) {
    return __uint_as_float(tf32_rna(x));
}
// d += a (m16k8, tf32) * b (k8n8, tf32)
__device__ __forceinline__ void mma8(float* d, const unsigned* a, unsigned b0, unsigned b1) {
    asm("mma.sync.aligned.m16n8k8.row.col.f32.tf32.tf32.f32 "
        "{%0,%1,%2,%3}, {%4,%5,%6,%7}, {%8,%9}, {%0,%1,%2,%3};"
        : "+f"(d[0]), "+f"(d[1]), "+f"(d[2]), "+f"(d[3])
        : "r"(a[0]), "r"(a[1]), "r"(a[2]), "r"(a[3]), "r"(b0), "r"(b1));
}
__device__ __forceinline__ void cp16(float* dst_smem, const float* src) {
    unsigned s = (unsigned)__cvta_generic_to_shared(dst_smem);
    asm volatile("cp.async.cg.shared.global [%0], [%1], 16;" :: "r"(s), "l"(src));
}

// ---------------------------------------------------------------------------
// FULLY-FUSED, SOFTWARE-PIPELINED kernel. 128 blocks x 256 threads,
// 16 batch rows/block, 1 block/SM. Iter t computes (all independent):
//   S1(t+2): h1[(t+2)&1] = tf32(tanh(x(t+2) @ W1 + b1))
//   S2(t+1): ys[(t+1)&1] = tf32(tanh(h1[(t+1)&1] @ W2 + b2))
//   gates(t): acc = (bih+bhh) + ys[t&1]@Wih^T + hsh[t&1]@Whh^T  (gate-own)
//   heads partial(t-1), reduce(t-2), cell(t)  -> ONE sync per step.
// All cross-warp buffers double-buffered with disjoint parities.
// ---------------------------------------------------------------------------
#define LSF_W1   0
#define LSF_W2   9216
#define LSF_WG   (LSF_W2 + 4608)           // 13824
#define LSF_XS   (LSF_WG + 17408)          // 31232
#define LSF_H1   (LSF_XS + 4224)           // 35456  [2][16][68]
#define LSF_YS   (LSF_H1 + 2176)           // 37632  [2][16][68]
#define LSF_HSH  (LSF_YS + 2176)           // 39808  [2][16][68]
#define LSF_ZS   (LSF_HSH + 2176)          // 41984  [2][16][68]
#define LSF_PBUF (LSF_ZS + 2176)           // 44160  [2][4][16][18]
#define LSF_DONE (LSF_PBUF + 2304)         // 46464  [128][16]
#define LSF_BIAS (LSF_DONE + 2048)         // 48512
#define LSF_SMEM (LSF_BIAS + 128)          // 48640 fl = 194560 B

__global__ __launch_bounds__(256, 1)
void k_fused(const float* __restrict__ x,    const float* __restrict__ done,
             const float* __restrict__ h0,   const float* __restrict__ c0,
             const float* __restrict__ W1,   const float* __restrict__ b1,
             const float* __restrict__ W2,   const float* __restrict__ b2,
             const float* __restrict__ Wih,  const float* __restrict__ bih,
             const float* __restrict__ Whh,  const float* __restrict__ bhh,
             const float* __restrict__ Wa,   const float* __restrict__ ba,
             const float* __restrict__ Wc,   const float* __restrict__ bc,
             float* __restrict__ out) {
    extern __shared__ float sm[];
    float* W1s    = sm + LSF_W1;       // [128][72] k-major, tf32
    float* W2s    = sm + LSF_W2;       // [64][72]  k-major, tf32
    float* WGs    = sm + LSF_WG;       // [256][68] n-major (Wih[n][k]), tf32
    float* xs     = sm + LSF_XS;       // [2][16][132]
    float* h1b    = sm + LSF_H1;       // [2][16][68] tf32
    float* ysb    = sm + LSF_YS;       // [2][16][68] tf32
    float* hsh    = sm + LSF_HSH;      // [2][16][68] tf32, pre-masked
    float* zs     = sm + LSF_ZS;       // [2][16][68] exact z
    float* pbuf   = sm + LSF_PBUF;     // [2][4][16][18]
    float* done_s = sm + LSF_DONE;     // [128][16]
    float* bsm    = sm + LSF_BIAS;     // b1 [64] | b2 [64]

    const int tid  = threadIdx.x;
    const int lane = tid & 31;
    const int w    = tid >> 5;
    const int b0   = blockIdx.x * 16;
    const int qr   = lane >> 2, qc = lane & 3;
    const int u    = w*8 + qc*2;       // unit pair base (gate-ownership)
    const int nc1  = w*8 + 2*qc;       // S1/S2 output col pair base
    const int rA = qr, rB = qr + 8;

    // gates B frags: warp w, gate g -> cols [g*64+8w, g*64+8w+8)
    unsigned bf0[8][4], bf1[8][4];
    #pragma unroll
    for (int kt = 0; kt < 8; kt++)
        #pragma unroll
        for (int g = 0; g < 4; g++) {
            int n = g*64 + w*8 + qr, k = kt*8 + qc;
            bf0[kt][g] = tf32_rna(Whh[n*H_ + k]);
            bf1[kt][g] = tf32_rna(Whh[n*H_ + k + 4]);
        }
    // gate bias pairs (bih+bhh) for this thread's fragment cols
    float gb[4][2];
    #pragma unroll
    for (int g = 0; g < 4; g++) {
        gb[g][0] = bih[g*64 + u]     + bhh[g*64 + u];
        gb[g][1] = bih[g*64 + u + 1] + bhh[g*64 + u + 1];
    }
    // heads frags: warp w -> n-half n0=(w&1)*8, k-slice ks=w>>1 (2 kt)
    const int n0 = (w & 1) * 8, ks = w >> 1;
    unsigned hb0[2], hb1[2];
    #pragma unroll
    for (int i = 0; i < 2; i++) {
        int k = (ks*2 + i)*8 + qc, j = n0 + qr;
        float v0 = (j < 15) ? Wa[k*A_ + j]     : Wc[k];
        float v1 = (j < 15) ? Wa[(k+4)*A_ + j] : Wc[k+4];
        hb0[i] = tf32_rna(v0);
        hb1[i] = tf32_rna(v1);
    }
    const int rcol = tid & 15, rrow = tid >> 4;
    const float rbias = (rcol < 15) ? ba[rcol] : bc[0];

    // prologue: prefetch x(0) -> xs[0], x(1) -> xs[1]
    #pragma unroll
    for (int s = 0; s < 2; s++) {
        const float* src = x + (size_t)(s*B_ + b0) * F_;
        float* dst = xs + s * 2112;
        #pragma unroll
        for (int j = 0; j < 2; j++) {
            int q = tid + j*256;
            int r = q >> 5, c4 = (q & 31) * 4;
            cp16(dst + r*132 + c4, src + r*F_ + c4);
        }
    }
    asm volatile("cp.async.commit_group;");

    // weights -> smem (tf32-rounded), biases, done
    for (int i = tid; i < F_*H_; i += 256) {
        int k = i >> 6, n = i & 63;
        W1s[k*72 + n] = tf32f(W1[i]);
    }
    for (int i = tid; i < H_*H_; i += 256) {
        int k = i >> 6, n = i & 63;
        W2s[k*72 + n] = tf32f(W2[i]);
    }
    for (int i = tid; i < G_*H_; i += 256) {
        int n = i >> 6, k = i & 63;
        WGs[n*68 + k] = tf32f(Wih[i]);
    }
    for (int i = tid; i < H_; i += 256) { bsm[i] = b1[i]; bsm[64+i] = b2[i]; }
    for (int i = tid; i < T_*16; i += 256)
        done_s[i] = done[(i>>4)*B_ + b0 + (i&15)];

    // state init (cell ownership: rows rA, rB; units u, u+1)
    const float mA0 = 1.0f - done[b0 + rA];
    const float mB0 = 1.0f - done[b0 + rB];
    float c_reg[4], hl[4];
    c_reg[0] = c0[(b0+rA)*H_ + u]   * mA0;
    c_reg[1] = c0[(b0+rA)*H_ + u+1] * mA0;
    c_reg[2] = c0[(b0+rB)*H_ + u]   * mB0;
    c_reg[3] = c0[(b0+rB)*H_ + u+1] * mB0;
    *(float2*)&hsh[rA*68 + u] =
        make_float2(tf32f(h0[(b0+rA)*H_ + u])*mA0, tf32f(h0[(b0+rA)*H_ + u+1])*mA0);
    *(float2*)&hsh[rB*68 + u] =
        make_float2(tf32f(h0[(b0+rB)*H_ + u])*mB0, tf32f(h0[(b0+rB)*H_ + u+1])*mB0);
    hl[0] = hl[1] = hl[2] = hl[3] = 0.f;

    asm volatile("cp.async.wait_group 0;");
    __syncthreads();

    // ---- prologue pipeline priming: S1(0) ----
    {
        const float* xb = xs;          // buf 0
        float a1[4] = {0.f, 0.f, 0.f, 0.f};
        #pragma unroll 4
        for (int kt = 0; kt < 16; kt++) {
            int k0 = kt*8;
            unsigned a[4];
            a[0] = tf32_rna(xb[rA*132 + k0 + qc]);
            a[1] = tf32_rna(xb[rB*132 + k0 + qc]);
            a[2] = tf32_rna(xb[rA*132 + k0 + qc + 4]);
            a[3] = tf32_rna(xb[rB*132 + k0 + qc + 4]);
            unsigned bh0 = __float_as_uint(W1s[(k0+qc)*72 + w*8 + qr]);
            unsigned bh1 = __float_as_uint(W1s[(k0+qc+4)*72 + w*8 + qr]);
            mma8(a1, a, bh0, bh1);
        }
        float bb0 = bsm[nc1], bb1 = bsm[nc1+1];
        *(float2*)&h1b[rA*68 + nc1] =
            make_float2(tf32f(ftanh_fast(a1[0]+bb0)), tf32f(ftanh_fast(a1[1]+bb1)));
        *(float2*)&h1b[rB*68 + nc1] =
            make_float2(tf32f(ftanh_fast(a1[2]+bb0)), tf32f(ftanh_fast(a1[3]+bb1)));
    }
    __syncthreads();                  // publish h1[0]; xs[0] now dead

    // prefetch x(2) -> xs[0]
    {
        const float* src = x + (size_t)(2*B_ + b0) * F_;
        #pragma unroll
        for (int j = 0; j < 2; j++) {
            int q = tid + j*256;
            int r = q >> 5, c4 = (q & 31) * 4;
            cp16(xs + r*132 + c4, src + r*F_ + c4);
        }
        asm volatile("cp.async.commit_group;");
    }
    // ---- S2(0) and S1(1) ----
    {
        float a2r[4] = {0.f, 0.f, 0.f, 0.f};
        #pragma unroll
        for (int kt = 0; kt < 8; kt++) {
            int k0 = kt*8;
            unsigned a[4];
            a[0] = __float_as_uint(h1b[rA*68 + k0 + qc]);
            a[1] = __float_as_uint(h1b[rB*68 + k0 + qc]);
            a[2] = __float_as_uint(h1b[rA*68 + k0 + qc + 4]);
            a[3] = __float_as_uint(h1b[rB*68 + k0 + qc + 4]);
            unsigned bh0 = __float_as_uint(W2s[(k0+qc)*72 + w*8 + qr]);
            unsigned bh1 = __float_as_uint(W2s[(k0+qc+4)*72 + w*8 + qr]);
            mma8(a2r, a, bh0, bh1);
        }
        float bb0 = bsm[64+nc1], bb1 = bsm[64+nc1+1];
        *(float2*)&ysb[rA*68 + nc1] =
            make_float2(tf32f(ftanh_fast(a2r[0]+bb0)), tf32f(ftanh_fast(a2r[1]+bb1)));
        *(float2*)&ysb[rB*68 + nc1] =
            make_float2(tf32f(ftanh_fast(a2r[2]+bb0)), tf32f(ftanh_fast(a2r[3]+bb1)));

        const float* xb = xs + 2112;   // buf 1 = x(1)
        float a1[4] = {0.f, 0.f, 0.f, 0.f};
        #pragma unroll 4
        for (int kt = 0; kt < 16; kt++) {
            int k0 = kt*8;
            unsigned a[4];
            a[0] = tf32_rna(xb[rA*132 + k0 + qc]);
            a[1] = tf32_rna(xb[rB*132 + k0 + qc]);
            a[2] = tf32_rna(xb[rA*132 + k0 + qc + 4]);
            a[3] = tf32_rna(xb[rB*132 + k0 + qc + 4]);
            unsigned bh0 = __float_as_uint(W1s[(k0+qc)*72 + w*8 + qr]);
            unsigned bh1 = __float_as_uint(W1s[(k0+qc+4)*72 + w*8 + qr]);
            mma8(a1, a, bh0, bh1);
        }
        float cb0 = bsm[nc1], cb1 = bsm[nc1+1];
        *(float2*)&h1b[1088 + rA*68 + nc1] =
            make_float2(tf32f(ftanh_fast(a1[0]+cb0)), tf32f(ftanh_fast(a1[1]+cb1)));
        *(float2*)&h1b[1088 + rB*68 + nc1] =
            make_float2(tf32f(ftanh_fast(a1[2]+cb0)), tf32f(ftanh_fast(a1[3]+cb1)));
    }
    asm volatile("cp.async.wait_group 0;");
    __syncthreads();                  // publish ys[0], h1[1], xs[0]=x(2)

    // =========================== main loop ===========================
    for (int t = 0; t < T_; t++) {
        // prefetch x(t+3) -> xs[(t+3)&1] (consumed by S1 at iter t+1)
        if (t + 3 < T_) {
            float* dst = xs + ((t+3)&1) * 2112;
            const float* src = x + (size_t)((t+3)*B_ + b0) * F_;
            #pragma unroll
            for (int j = 0; j < 2; j++) {
                int q = tid + j*256;
                int r = q >> 5, c4 = (q & 31) * 4;
                cp16(dst + r*132 + c4, src + r*F_ + c4);
            }
            asm volatile("cp.async.commit_group;");
        }

        // ---- heads reduce + output for step t-2 ----
        if (t >= 2) {
            const float* pb = pbuf + ((t-2)&1) * 1152;
            float s = pb[0*288 + rrow*18 + rcol] + pb[1*288 + rrow*18 + rcol]
                    + pb[2*288 + rrow*18 + rcol] + pb[3*288 + rrow*18 + rcol]
                    + rbias;
            size_t r = (size_t)(t-2)*B_ + b0 + rrow;
            if (rcol < 15) out[r*A_ + rcol] = s;
            else           out[(size_t)TB_*A_ + r] = s;
        }

        // ---- gates(t): acc = bias + ys[t&1]@Wih^T + hsh[t&1]@Whh^T ----
        float acc[4][4];
        #pragma unroll
        for (int g = 0; g < 4; g++) {
            acc[g][0] = gb[g][0]; acc[g][1] = gb[g][1];
            acc[g][2] = gb[g][0]; acc[g][3] = gb[g][1];
        }
        {
            const float* yb = ysb + (t&1) * 1088;
            #pragma unroll
            for (int kt = 0; kt < 8; kt++) {
                int k0 = kt*8;
                unsigned a[4];
                a[0] = __float_as_uint(yb[rA*68 + k0 + qc]);
                a[1] = __float_as_uint(yb[rB*68 + k0 + qc]);
                a[2] = __float_as_uint(yb[rA*68 + k0 + qc + 4]);
                a[3] = __float_as_uint(yb[rB*68 + k0 + qc + 4]);
                #pragma unroll
                for (int g = 0; g < 4; g++) {
                    int bn = g*64 + w*8 + qr;
                    mma8(acc[g], a,
                         __float_as_uint(WGs[bn*68 + k0 + qc]),
                         __float_as_uint(WGs[bn*68 + k0 + qc + 4]));
                }
            }
            const float* hb = hsh + (t&1) * 1088;
            #pragma unroll
            for (int kt = 0; kt < 8; kt++) {
                int k0 = kt*8;
                unsigned a[4];
                a[0] = __float_as_uint(hb[rA*68 + k0 + qc]);
                a[1] = __float_as_uint(hb[rB*68 + k0 + qc]);
                a[2] = __float_as_uint(hb[rA*68 + k0 + qc + 4]);
                a[3] = __float_as_uint(hb[rB*68 + k0 + qc + 4]);
                #pragma unroll
                for (int g = 0; g < 4; g++)
                    mma8(acc[g], a, bf0[kt][g], bf1[kt][g]);
            }
        }

        // ---- S1(t+2) -> h1[(t+2)&1] ----
        if (t + 2 < T_) {
            const float* xb = xs + ((t+2)&1) * 2112;
            float a1[4] = {0.f, 0.f, 0.f, 0.f};
            #pragma unroll 4
            for (int kt = 0; kt < 16; kt++) {
                int k0 = kt*8;
                unsigned a[4];
                a[0] = tf32_rna(xb[rA*132 + k0 + qc]);
                a[1] = tf32_rna(xb[rB*132 + k0 + qc]);
                a[2] = tf32_rna(xb[rA*132 + k0 + qc + 4]);
                a[3] = tf32_rna(xb[rB*132 + k0 + qc + 4]);
                unsigned bh0 = __float_as_uint(W1s[(k0+qc)*72 + w*8 + qr]);
                unsigned bh1 = __float_as_uint(W1s[(k0+qc+4)*72 + w*8 + qr]);
                mma8(a1, a, bh0, bh1);
            }
            float bb0 = bsm[nc1], bb1 = bsm[nc1+1];
            float* hd = h1b + ((t+2)&1) * 1088;
            *(float2*)&hd[rA*68 + nc1] =
                make_float2(tf32f(ftanh_fast(a1[0]+bb0)), tf32f(ftanh_fast(a1[1]+bb1)));
            *(float2*)&hd[rB*68 + nc1] =
                make_float2(tf32f(ftanh_fast(a1[2]+bb0)), tf32f(ftanh_fast(a1[3]+bb1)));
        }

        // ---- S2(t+1) -> ys[(t+1)&1] ----
        if (t + 1 < T_) {
            const float* hs = h1b + ((t+1)&1) * 1088;
            float a2r[4] = {0.f, 0.f, 0.f, 0.f};
            #pragma unroll
            for (int kt = 0; kt < 8; kt++) {
                int k0 = kt*8;
                unsigned a[4];
                a[0] = __float_as_uint(hs[rA*68 + k0 + qc]);
                a[1] = __float_as_uint(hs[rB*68 + k0 + qc]);
                a[2] = __float_as_uint(hs[rA*68 + k0 + qc + 4]);
                a[3] = __float_as_uint(hs[rB*68 + k0 + qc + 4]);
                unsigned bh0 = __float_as_uint(W2s[(k0+qc)*72 + w*8 + qr]);
                unsigned bh1 = __float_as_uint(W2s[(k0+qc+4)*72 + w*8 + qr]);
                mma8(a2r, a, bh0, bh1);
            }
            float bb0 = bsm[64+nc1], bb1 = bsm[64+nc1+1];
            float* yd = ysb + ((t+1)&1) * 1088;
            *(float2*)&yd[rA*68 + nc1] =
                make_float2(tf32f(ftanh_fast(a2r[0]+bb0)), tf32f(ftanh_fast(a2r[1]+bb1)));
            *(float2*)&yd[rB*68 + nc1] =
                make_float2(tf32f(ftanh_fast(a2r[2]+bb0)), tf32f(ftanh_fast(a2r[3]+bb1)));
        }

        // ---- heads partial for step t-1 (reads zs[(t-1)&1]) ----
        if (t) {
            const float* zb = zs + ((t-1)&1) * 1088;
            float* pw = pbuf + ((t-1)&1) * 1152;
            float pacc[4] = {0.f, 0.f, 0.f, 0.f};
            #pragma unroll
            for (int i = 0; i < 2; i++) {
                int k0 = (ks*2 + i)*8;
                unsigned a[4];
                a[0] = tf32_rna(zb[qr*68 + k0 + qc]);
                a[1] = tf32_rna(zb[(qr+8)*68 + k0 + qc]);
                a[2] = tf32_rna(zb[qr*68 + k0 + qc + 4]);
                a[3] = tf32_rna(zb[(qr+8)*68 + k0 + qc + 4]);
                mma8(pacc, a, hb0[i], hb1[i]);
            }
            *(float2*)&pw[ks*288 + qr*18 + n0 + 2*qc]     = make_float2(pacc[0], pacc[1]);
            *(float2*)&pw[ks*288 + (qr+8)*18 + n0 + 2*qc] = make_float2(pacc[2], pacc[3]);
        }

        // ---- cell update (gate order i,f,g,o), fully in registers ----
        float mnA = 1.0f, mnB = 1.0f;
        if (t + 1 < T_) {
            mnA = 1.0f - done_s[(t+1)*16 + rA];
            mnB = 1.0f - done_s[(t+1)*16 + rB];
        }
        float hr[4];
        #pragma unroll
        for (int i = 0; i < 4; i++) {
            float mn = (i < 2) ? mnA : mnB;
            float cn = fsig_fast(acc[1][i])*c_reg[i]
                     + fsig_fast(acc[0][i])*ftanh_fast(acc[2][i]);
            float hn = fsig_fast(acc[3][i])*ftanh_fast(cn);
            c_reg[i] = cn * mn;                 // pre-mask for next step
            hr[i] = tf32f(hn) * mn;             // pre-round + pre-mask
            hl[i] = hn;
        }
        float* hn_ = hsh + ((t+1)&1) * 1088;
        *(float2*)&hn_[rA*68 + u] = make_float2(hr[0], hr[1]);
        *(float2*)&hn_[rB*68 + u] = make_float2(hr[2], hr[3]);
        float* zw = zs + (t&1) * 1088;
        *(float2*)&zw[rA*68 + u] = make_float2(hl[0], hl[1]);
        *(float2*)&zw[rB*68 + u] = make_float2(hl[2], hl[3]);

        // publish everything (x prefetch + h1/ys/hsh/zs/pbuf)
        if (t + 3 < T_) asm volatile("cp.async.wait_group 0;");
        __syncthreads();
    }

    // ---- tail: reduce(T-2); partial(T-1); reduce(T-1) ----
    {
        const float* pb = pbuf + ((T_-2)&1) * 1152;
        float s = pb[0*288 + rrow*18 + rcol] + pb[1*288 + rrow*18 + rcol]
                + pb[2*288 + rrow*18 + rcol] + pb[3*288 + rrow*18 + rcol]
                + rbias;
        size_t r = (size_t)(T_-2)*B_ + b0 + rrow;
        if (rcol < 15) out[r*A_ + rcol] = s;
        else           out[(size_t)TB_*A_ + r] = s;
    }
    {
        const float* zb = zs + ((T_-1)&1) * 1088;
        float* pw = pbuf + ((T_-1)&1) * 1152;
        float pacc[4] = {0.f, 0.f, 0.f, 0.f};
        #pragma unroll
        for (int i = 0; i < 2; i++) {
            int k0 = (ks*2 + i)*8;
            unsigned a[4];
            a[0] = tf32_rna(zb[qr*68 + k0 + qc]);
            a[1] = tf32_rna(zb[(qr+8)*68 + k0 + qc]);
            a[2] = tf32_rna(zb[qr*68 + k0 + qc + 4]);
            a[3] = tf32_rna(zb[(qr+8)*68 + k0 + qc + 4]);
            mma8(pacc, a, hb0[i], hb1[i]);
        }
        *(float2*)&pw[ks*288 + qr*18 + n0 + 2*qc]     = make_float2(pacc[0], pacc[1]);
        *(float2*)&pw[ks*288 + (qr+8)*18 + n0 + 2*qc] = make_float2(pacc[2], pacc[3]);
        __syncthreads();
        float s = pw[0*288 + rrow*18 + rcol] + pw[1*288 + rrow*18 + rcol]
                + pw[2*288 + rrow*18 + rcol] + pw[3*288 + rrow*18 + rcol]
                + rbias;
        size_t r = (size_t)(T_-1)*B_ + b0 + rrow;
        if (rcol < 15) out[r*A_ + rcol] = s;
        else           out[(size_t)TB_*A_ + r] = s;
    }

    // epilogue: hT, cT (layout: logits | vf | hT | cT), full precision
    const size_t OH = (size_t)TB_ * 16;
    *(float2*)&out[OH + (size_t)(b0+rA)*H_ + u]                 = make_float2(hl[0], hl[1]);
    *(float2*)&out[OH + (size_t)(b0+rB)*H_ + u]                 = make_float2(hl[2], hl[3]);
    *(float2*)&out[OH + (size_t)B_*H_ + (size_t)(b0+rA)*H_ + u] = make_float2(c_reg[0], c_reg[1]);
    *(float2*)&out[OH + (size_t)B_*H_ + (size_t)(b0+rB)*H_ + u] = make_float2(c_reg[2], c_reg[3]);
}

// ---------------------------------------------------------------------------
extern "C" void kernel_launch(void* const* d_in, const int* in_sizes, int n_in,
                              void* d_out, int out_size) {
    const float* x    = (const float*)d_in[0];
    const float* done = (const float*)d_in[1];
    const float* h0   = (const float*)d_in[2];
    const float* c0   = (const float*)d_in[3];
    const float* W1   = (const float*)d_in[4];
    const float* b1   = (const float*)d_in[5];
    const float* W2   = (const float*)d_in[6];
    const float* b2   = (const float*)d_in[7];
    const float* Wih  = (const float*)d_in[8];
    const float* bih  = (const float*)d_in[9];
    const float* Whh  = (const float*)d_in[10];
    const float* bhh  = (const float*)d_in[11];
    const float* Wa   = (const float*)d_in[12];
    const float* ba   = (const float*)d_in[13];
    const float* Wc   = (const float*)d_in[14];
    const float* bc   = (const float*)d_in[15];
    float* out = (float*)d_out;

    cudaFuncSetAttribute(k_fused, cudaFuncAttributeMaxDynamicSharedMemorySize, LSF_SMEM*4);

    k_fused<<<B_/16, 256, LSF_SMEM*4>>>(x, done, h0, c0, W1, b1, W2, b2,
                                        Wih, bih, Whh, bhh, Wa, ba, Wc, bc, out);
}

// round 16
// speedup vs baseline: 1.5268x; 1.1748x over previous
#include <cuda_runtime.h>

#define T_  128
#define B_  2048
#define F_  128
#define H_  64
#define A_  15
#define TB_ (T_*B_)
#define G_  256   // 4*H gates

// ---------------------------------------------------------------------------
// math helpers
// ---------------------------------------------------------------------------
__device__ __forceinline__ float ftanh_fast(float x) {
    float y;
    asm("tanh.approx.f32 %0, %1;" : "=f"(y) : "f"(x));
    return y;
}
__device__ __forceinline__ float fsig_fast(float x) {
    return fmaf(0.5f, ftanh_fast(0.5f * x), 0.5f);
}
__device__ __forceinline__ unsigned tf32_rna(float x) {
    unsigned u; asm("cvt.rna.tf32.f32 %0, %1;" : "=r"(u) : "f"(x)); return u;
}
__device__ __forceinline__ float tf32f(float x) {
    return __uint_as_float(tf32_rna(x));
}
// d += a (m16k8, tf32) * b (k8n8, tf32)
__device__ __forceinline__ void mma8(float* d, const unsigned* a, unsigned b0, unsigned b1) {
    asm("mma.sync.aligned.m16n8k8.row.col.f32.tf32.tf32.f32 "
        "{%0,%1,%2,%3}, {%4,%5,%6,%7}, {%8,%9}, {%0,%1,%2,%3};"
        : "+f"(d[0]), "+f"(d[1]), "+f"(d[2]), "+f"(d[3])
        : "r"(a[0]), "r"(a[1]), "r"(a[2]), "r"(a[3]), "r"(b0), "r"(b1));
}
__device__ __forceinline__ void cp16(float* dst_smem, const float* src) {
    unsigned s = (unsigned)__cvta_generic_to_shared(dst_smem);
    asm volatile("cp.async.cg.shared.global [%0], [%1], 16;" :: "r"(s), "l"(src));
}

// ---------------------------------------------------------------------------
// FULLY-FUSED, WARP-SPECIALIZED, PIPELINED kernel. 128 blocks x 384 threads,
// 16 batch rows/block, 1 block/SM, 3 warps/SMSP.
//   Group A (warps 0-7):  gates(t) = bias + ys[t&1]@Wih^T + hsh[t&1]@Whh^T
//                         (gate-ownership frags), heads partial(t-1),
//                         reduce(t-2), cell(t).
//   Group B (warps 8-11): S1(t+2) (2 n-slices/warp), S2(t+1), x prefetch.
// ONE __syncthreads per step publishes all cross-warp buffers
// (parities all disjoint; verified per buffer).
// ---------------------------------------------------------------------------
#define LSF_W1   0
#define LSF_W2   9216
#define LSF_WG   (LSF_W2 + 4608)           // 13824
#define LSF_XS   (LSF_WG + 17408)          // 31232  [2][16][132]
#define LSF_H1   (LSF_XS + 4224)           // 35456  [2][16][68]
#define LSF_YS   (LSF_H1 + 2176)           // 37632  [2][16][68]
#define LSF_HSH  (LSF_YS + 2176)           // 39808  [2][16][68]
#define LSF_ZS   (LSF_HSH + 2176)          // 41984  [2][16][68] (tf32 z)
#define LSF_PBUF (LSF_ZS + 2176)           // 44160  [2][4][16][18]
#define LSF_DONE (LSF_PBUF + 2304)         // 46464  [128][16]
#define LSF_BIAS (LSF_DONE + 2048)         // 48512
#define LSF_SMEM (LSF_BIAS + 128)          // 48640 fl = 194560 B

__global__ __launch_bounds__(384, 1)
void k_fused(const float* __restrict__ x,    const float* __restrict__ done,
             const float* __restrict__ h0,   const float* __restrict__ c0,
             const float* __restrict__ W1,   const float* __restrict__ b1,
             const float* __restrict__ W2,   const float* __restrict__ b2,
             const float* __restrict__ Wih,  const float* __restrict__ bih,
             const float* __restrict__ Whh,  const float* __restrict__ bhh,
             const float* __restrict__ Wa,   const float* __restrict__ ba,
             const float* __restrict__ Wc,   const float* __restrict__ bc,
             float* __restrict__ out) {
    extern __shared__ float sm[];
    float* W1s    = sm + LSF_W1;
    float* W2s    = sm + LSF_W2;
    float* WGs    = sm + LSF_WG;
    float* xs     = sm + LSF_XS;
    float* h1b    = sm + LSF_H1;
    float* ysb    = sm + LSF_YS;
    float* hsh    = sm + LSF_HSH;
    float* zs     = sm + LSF_ZS;
    float* pbuf   = sm + LSF_PBUF;
    float* done_s = sm + LSF_DONE;
    float* bsm    = sm + LSF_BIAS;

    const int tid  = threadIdx.x;
    const int lane = tid & 31;
    const int b0   = blockIdx.x * 16;
    const int qr   = lane >> 2, qc = lane & 3;
    const int rA = qr, rB = qr + 8;
    const bool gA = (tid < 256);
    const int w   = tid >> 5;              // 0..11
    const int wb  = w - 8;                 // group B warp id 0..3
    const int tidB = tid - 256;            // 0..127 for group B

    // ---------------- group A per-thread state ----------------
    const int u = (w & 7)*8 + qc*2;        // gate-ownership unit pair
    unsigned bf0[8][4], bf1[8][4];
    float gb[4][2];
    unsigned hb0[2], hb1[2];
    const int n0 = (w & 1) * 8, ks = (w & 7) >> 1;
    const int rcol = tid & 15, rrow = (tid >> 4) & 15;
    float rbias = 0.f;
    float c_reg[4], hl[4];

    if (gA) {
        #pragma unroll
        for (int kt = 0; kt < 8; kt++)
            #pragma unroll
            for (int g = 0; g < 4; g++) {
                int n = g*64 + (w&7)*8 + qr, k = kt*8 + qc;
                bf0[kt][g] = tf32_rna(Whh[n*H_ + k]);
                bf1[kt][g] = tf32_rna(Whh[n*H_ + k + 4]);
            }
        #pragma unroll
        for (int g = 0; g < 4; g++) {
            gb[g][0] = bih[g*64 + u]     + bhh[g*64 + u];
            gb[g][1] = bih[g*64 + u + 1] + bhh[g*64 + u + 1];
        }
        #pragma unroll
        for (int i = 0; i < 2; i++) {
            int k = (ks*2 + i)*8 + qc, j = n0 + qr;
            float v0 = (j < 15) ? Wa[k*A_ + j]     : Wc[k];
            float v1 = (j < 15) ? Wa[(k+4)*A_ + j] : Wc[k+4];
            hb0[i] = tf32_rna(v0);
            hb1[i] = tf32_rna(v1);
        }
        rbias = (rcol < 15) ? ba[rcol] : bc[0];
        // cell state init
        const float mA0 = 1.0f - done[b0 + rA];
        const float mB0 = 1.0f - done[b0 + rB];
        c_reg[0] = c0[(b0+rA)*H_ + u]   * mA0;
        c_reg[1] = c0[(b0+rA)*H_ + u+1] * mA0;
        c_reg[2] = c0[(b0+rB)*H_ + u]   * mB0;
        c_reg[3] = c0[(b0+rB)*H_ + u+1] * mB0;
        *(float2*)&hsh[rA*68 + u] =
            make_float2(tf32f(h0[(b0+rA)*H_ + u])*mA0, tf32f(h0[(b0+rA)*H_ + u+1])*mA0);
        *(float2*)&hsh[rB*68 + u] =
            make_float2(tf32f(h0[(b0+rB)*H_ + u])*mB0, tf32f(h0[(b0+rB)*H_ + u+1])*mB0);
        hl[0] = hl[1] = hl[2] = hl[3] = 0.f;
    } else {
        // group B: prefetch x(0) -> xs[0], x(1) -> xs[1]
        #pragma unroll
        for (int s = 0; s < 2; s++) {
            const float* src = x + (size_t)(s*B_ + b0) * F_;
            float* dst = xs + s * 2112;
            #pragma unroll
            for (int j = 0; j < 4; j++) {
                int q = tidB + j*128;
                int r = q >> 5, c4 = (q & 31) * 4;
                cp16(dst + r*132 + c4, src + r*F_ + c4);
            }
        }
        asm volatile("cp.async.commit_group;");
    }

    // weights -> smem (tf32-rounded), biases, done (all threads)
    for (int i = tid; i < F_*H_; i += 384) {
        int k = i >> 6, n = i & 63;
        W1s[k*72 + n] = tf32f(W1[i]);
    }
    for (int i = tid; i < H_*H_; i += 384) {
        int k = i >> 6, n = i & 63;
        W2s[k*72 + n] = tf32f(W2[i]);
    }
    for (int i = tid; i < G_*H_; i += 384) {
        int n = i >> 6, k = i & 63;
        WGs[n*68 + k] = tf32f(Wih[i]);
    }
    for (int i = tid; i < H_; i += 384) { bsm[i] = b1[i]; bsm[64+i] = b2[i]; }
    for (int i = tid; i < T_*16; i += 384)
        done_s[i] = done[(i>>4)*B_ + b0 + (i&15)];

    if (!gA) asm volatile("cp.async.wait_group 0;");
    __syncthreads();                       // (1) weights + x0/x1 + hsh

    // ---- prologue: S1(0) by group B ----
    if (!gA) {
        const float* xb = xs;              // x(0)
        float a1[2][4];
        #pragma unroll
        for (int si = 0; si < 2; si++)
            #pragma unroll
            for (int j = 0; j < 4; j++) a1[si][j] = 0.f;
        #pragma unroll 4
        for (int kt = 0; kt < 16; kt++) {
            int k0 = kt*8;
            unsigned a[4];
            a[0] = tf32_rna(xb[rA*132 + k0 + qc]);
            a[1] = tf32_rna(xb[rB*132 + k0 + qc]);
            a[2] = tf32_rna(xb[rA*132 + k0 + qc + 4]);
            a[3] = tf32_rna(xb[rB*132 + k0 + qc + 4]);
            #pragma unroll
            for (int si = 0; si < 2; si++) {
                int bn = wb*16 + si*8 + qr;
                mma8(a1[si], a,
                     __float_as_uint(W1s[(k0+qc)*72 + bn]),
                     __float_as_uint(W1s[(k0+qc+4)*72 + bn]));
            }
        }
        #pragma unroll
        for (int si = 0; si < 2; si++) {
            int c = wb*16 + si*8 + 2*qc;
            float bb0 = bsm[c], bb1 = bsm[c+1];
            *(float2*)&h1b[rA*68 + c] =
                make_float2(tf32f(ftanh_fast(a1[si][0]+bb0)), tf32f(ftanh_fast(a1[si][1]+bb1)));
            *(float2*)&h1b[rB*68 + c] =
                make_float2(tf32f(ftanh_fast(a1[si][2]+bb0)), tf32f(ftanh_fast(a1[si][3]+bb1)));
        }
    }
    __syncthreads();                       // (2) h1[0]

    // ---- prologue: x(2)->xs[0], S2(0)->ys[0], S1(1)->h1[1] by group B ----
    if (!gA) {
        {
            const float* src = x + (size_t)(2*B_ + b0) * F_;
            #pragma unroll
            for (int j = 0; j < 4; j++) {
                int q = tidB + j*128;
                int r = q >> 5, c4 = (q & 31) * 4;
                cp16(xs + r*132 + c4, src + r*F_ + c4);
            }
            asm volatile("cp.async.commit_group;");
        }
        {   // S2(0)
            float a2r[2][4];
            #pragma unroll
            for (int si = 0; si < 2; si++)
                #pragma unroll
                for (int j = 0; j < 4; j++) a2r[si][j] = 0.f;
            #pragma unroll
            for (int kt = 0; kt < 8; kt++) {
                int k0 = kt*8;
                unsigned a[4];
                a[0] = __float_as_uint(h1b[rA*68 + k0 + qc]);
                a[1] = __float_as_uint(h1b[rB*68 + k0 + qc]);
                a[2] = __float_as_uint(h1b[rA*68 + k0 + qc + 4]);
                a[3] = __float_as_uint(h1b[rB*68 + k0 + qc + 4]);
                #pragma unroll
                for (int si = 0; si < 2; si++) {
                    int bn = wb*16 + si*8 + qr;
                    mma8(a2r[si], a,
                         __float_as_uint(W2s[(k0+qc)*72 + bn]),
                         __float_as_uint(W2s[(k0+qc+4)*72 + bn]));
                }
            }
            #pragma unroll
            for (int si = 0; si < 2; si++) {
                int c = wb*16 + si*8 + 2*qc;
                float bb0 = bsm[64+c], bb1 = bsm[64+c+1];
                *(float2*)&ysb[rA*68 + c] =
                    make_float2(tf32f(ftanh_fast(a2r[si][0]+bb0)), tf32f(ftanh_fast(a2r[si][1]+bb1)));
                *(float2*)&ysb[rB*68 + c] =
                    make_float2(tf32f(ftanh_fast(a2r[si][2]+bb0)), tf32f(ftanh_fast(a2r[si][3]+bb1)));
            }
        }
        {   // S1(1) from xs[1]
            const float* xb = xs + 2112;
            float a1[2][4];
            #pragma unroll
            for (int si = 0; si < 2; si++)
                #pragma unroll
                for (int j = 0; j < 4; j++) a1[si][j] = 0.f;
            #pragma unroll 4
            for (int kt = 0; kt < 16; kt++) {
                int k0 = kt*8;
                unsigned a[4];
                a[0] = tf32_rna(xb[rA*132 + k0 + qc]);
                a[1] = tf32_rna(xb[rB*132 + k0 + qc]);
                a[2] = tf32_rna(xb[rA*132 + k0 + qc + 4]);
                a[3] = tf32_rna(xb[rB*132 + k0 + qc + 4]);
                #pragma unroll
                for (int si = 0; si < 2; si++) {
                    int bn = wb*16 + si*8 + qr;
                    mma8(a1[si], a,
                         __float_as_uint(W1s[(k0+qc)*72 + bn]),
                         __float_as_uint(W1s[(k0+qc+4)*72 + bn]));
                }
            }
            #pragma unroll
            for (int si = 0; si < 2; si++) {
                int c = wb*16 + si*8 + 2*qc;
                float bb0 = bsm[c], bb1 = bsm[c+1];
                *(float2*)&h1b[1088 + rA*68 + c] =
                    make_float2(tf32f(ftanh_fast(a1[si][0]+bb0)), tf32f(ftanh_fast(a1[si][1]+bb1)));
                *(float2*)&h1b[1088 + rB*68 + c] =
                    make_float2(tf32f(ftanh_fast(a1[si][2]+bb0)), tf32f(ftanh_fast(a1[si][3]+bb1)));
            }
        }
        asm volatile("cp.async.wait_group 0;");
    }
    __syncthreads();                       // (3) ys[0], h1[1], xs[0]=x(2)

    // =========================== main loop ===========================
    for (int t = 0; t < T_; t++) {
        if (gA) {
            // ---- reduce(t-2) ----
            if (t >= 2) {
                const float* pb = pbuf + ((t-2)&1) * 1152;
                float s = pb[0*288 + rrow*18 + rcol] + pb[1*288 + rrow*18 + rcol]
                        + pb[2*288 + rrow*18 + rcol] + pb[3*288 + rrow*18 + rcol]
                        + rbias;
                size_t r = (size_t)(t-2)*B_ + b0 + rrow;
                if (rcol < 15) out[r*A_ + rcol] = s;
                else           out[(size_t)TB_*A_ + r] = s;
            }

            // ---- gates(t) ----
            float acc[4][4];
            #pragma unroll
            for (int g = 0; g < 4; g++) {
                acc[g][0] = gb[g][0]; acc[g][1] = gb[g][1];
                acc[g][2] = gb[g][0]; acc[g][3] = gb[g][1];
            }
            {
                const float* yb = ysb + (t&1) * 1088;
                #pragma unroll
                for (int kt = 0; kt < 8; kt++) {
                    int k0 = kt*8;
                    unsigned a[4];
                    a[0] = __float_as_uint(yb[rA*68 + k0 + qc]);
                    a[1] = __float_as_uint(yb[rB*68 + k0 + qc]);
                    a[2] = __float_as_uint(yb[rA*68 + k0 + qc + 4]);
                    a[3] = __float_as_uint(yb[rB*68 + k0 + qc + 4]);
                    #pragma unroll
                    for (int g = 0; g < 4; g++) {
                        int bn = g*64 + (w&7)*8 + qr;
                        mma8(acc[g], a,
                             __float_as_uint(WGs[bn*68 + k0 + qc]),
                             __float_as_uint(WGs[bn*68 + k0 + qc + 4]));
                    }
                }
                const float* hb = hsh + (t&1) * 1088;
                #pragma unroll
                for (int kt = 0; kt < 8; kt++) {
                    int k0 = kt*8;
                    unsigned a[4];
                    a[0] = __float_as_uint(hb[rA*68 + k0 + qc]);
                    a[1] = __float_as_uint(hb[rB*68 + k0 + qc]);
                    a[2] = __float_as_uint(hb[rA*68 + k0 + qc + 4]);
                    a[3] = __float_as_uint(hb[rB*68 + k0 + qc + 4]);
                    #pragma unroll
                    for (int g = 0; g < 4; g++)
                        mma8(acc[g], a, bf0[kt][g], bf1[kt][g]);
                }
            }

            // ---- heads partial(t-1), zs pre-rounded -> raw loads ----
            if (t) {
                const float* zb = zs + ((t-1)&1) * 1088;
                float* pw = pbuf + ((t-1)&1) * 1152;
                float pacc[4] = {0.f, 0.f, 0.f, 0.f};
                #pragma unroll
                for (int i = 0; i < 2; i++) {
                    int k0 = (ks*2 + i)*8;
                    unsigned a[4];
                    a[0] = __float_as_uint(zb[qr*68 + k0 + qc]);
                    a[1] = __float_as_uint(zb[(qr+8)*68 + k0 + qc]);
                    a[2] = __float_as_uint(zb[qr*68 + k0 + qc + 4]);
                    a[3] = __float_as_uint(zb[(qr+8)*68 + k0 + qc + 4]);
                    mma8(pacc, a, hb0[i], hb1[i]);
                }
                *(float2*)&pw[ks*288 + qr*18 + n0 + 2*qc]     = make_float2(pacc[0], pacc[1]);
                *(float2*)&pw[ks*288 + (qr+8)*18 + n0 + 2*qc] = make_float2(pacc[2], pacc[3]);
            }

            // ---- cell(t) ----
            float mnA = 1.0f, mnB = 1.0f;
            if (t + 1 < T_) {
                mnA = 1.0f - done_s[(t+1)*16 + rA];
                mnB = 1.0f - done_s[(t+1)*16 + rB];
            }
            float hr[4], zr[4];
            #pragma unroll
            for (int i = 0; i < 4; i++) {
                float mn = (i < 2) ? mnA : mnB;
                float cn = fsig_fast(acc[1][i])*c_reg[i]
                         + fsig_fast(acc[0][i])*ftanh_fast(acc[2][i]);
                float hn = fsig_fast(acc[3][i])*ftanh_fast(cn);
                c_reg[i] = cn * mn;
                zr[i] = tf32f(hn);          // pre-rounded z for heads
                hr[i] = zr[i] * mn;         // pre-round + pre-mask
                hl[i] = hn;
            }
            float* hn_ = hsh + ((t+1)&1) * 1088;
            *(float2*)&hn_[rA*68 + u] = make_float2(hr[0], hr[1]);
            *(float2*)&hn_[rB*68 + u] = make_float2(hr[2], hr[3]);
            float* zw = zs + (t&1) * 1088;
            *(float2*)&zw[rA*68 + u] = make_float2(zr[0], zr[1]);
            *(float2*)&zw[rB*68 + u] = make_float2(zr[2], zr[3]);
        } else {
            // ---- group B: prefetch x(t+3) ----
            bool issued = false;
            if (t + 3 < T_) {
                float* dst = xs + ((t+3)&1) * 2112;
                const float* src = x + (size_t)((t+3)*B_ + b0) * F_;
                #pragma unroll
                for (int j = 0; j < 4; j++) {
                    int q = tidB + j*128;
                    int r = q >> 5, c4 = (q & 31) * 4;
                    cp16(dst + r*132 + c4, src + r*F_ + c4);
                }
                asm volatile("cp.async.commit_group;");
                issued = true;
            }

            // ---- S1(t+2) ----
            if (t + 2 < T_) {
                const float* xb = xs + ((t+2)&1) * 2112;
                float a1[2][4];
                #pragma unroll
                for (int si = 0; si < 2; si++)
                    #pragma unroll
                    for (int j = 0; j < 4; j++) a1[si][j] = 0.f;
                #pragma unroll 4
                for (int kt = 0; kt < 16; kt++) {
                    int k0 = kt*8;
                    unsigned a[4];
                    a[0] = tf32_rna(xb[rA*132 + k0 + qc]);
                    a[1] = tf32_rna(xb[rB*132 + k0 + qc]);
                    a[2] = tf32_rna(xb[rA*132 + k0 + qc + 4]);
                    a[3] = tf32_rna(xb[rB*132 + k0 + qc + 4]);
                    #pragma unroll
                    for (int si = 0; si < 2; si++) {
                        int bn = wb*16 + si*8 + qr;
                        mma8(a1[si], a,
                             __float_as_uint(W1s[(k0+qc)*72 + bn]),
                             __float_as_uint(W1s[(k0+qc+4)*72 + bn]));
                    }
                }
                float* hd = h1b + ((t+2)&1) * 1088;
                #pragma unroll
                for (int si = 0; si < 2; si++) {
                    int c = wb*16 + si*8 + 2*qc;
                    float bb0 = bsm[c], bb1 = bsm[c+1];
                    *(float2*)&hd[rA*68 + c] =
                        make_float2(tf32f(ftanh_fast(a1[si][0]+bb0)), tf32f(ftanh_fast(a1[si][1]+bb1)));
                    *(float2*)&hd[rB*68 + c] =
                        make_float2(tf32f(ftanh_fast(a1[si][2]+bb0)), tf32f(ftanh_fast(a1[si][3]+bb1)));
                }
            }

            // ---- S2(t+1) ----
            if (t + 1 < T_) {
                const float* hs = h1b + ((t+1)&1) * 1088;
                float a2r[2][4];
                #pragma unroll
                for (int si = 0; si < 2; si++)
                    #pragma unroll
                    for (int j = 0; j < 4; j++) a2r[si][j] = 0.f;
                #pragma unroll
                for (int kt = 0; kt < 8; kt++) {
                    int k0 = kt*8;
                    unsigned a[4];
                    a[0] = __float_as_uint(hs[rA*68 + k0 + qc]);
                    a[1] = __float_as_uint(hs[rB*68 + k0 + qc]);
                    a[2] = __float_as_uint(hs[rA*68 + k0 + qc + 4]);
                    a[3] = __float_as_uint(hs[rB*68 + k0 + qc + 4]);
                    #pragma unroll
                    for (int si = 0; si < 2; si++) {
                        int bn = wb*16 + si*8 + qr;
                        mma8(a2r[si], a,
                             __float_as_uint(W2s[(k0+qc)*72 + bn]),
                             __float_as_uint(W2s[(k0+qc+4)*72 + bn]));
                    }
                }
                float* yd = ysb + ((t+1)&1) * 1088;
                #pragma unroll
                for (int si = 0; si < 2; si++) {
                    int c = wb*16 + si*8 + 2*qc;
                    float bb0 = bsm[64+c], bb1 = bsm[64+c+1];
                    *(float2*)&yd[rA*68 + c] =
                        make_float2(tf32f(ftanh_fast(a2r[si][0]+bb0)), tf32f(ftanh_fast(a2r[si][1]+bb1)));
                    *(float2*)&yd[rB*68 + c] =
                        make_float2(tf32f(ftanh_fast(a2r[si][2]+bb0)), tf32f(ftanh_fast(a2r[si][3]+bb1)));
                }
            }
            if (issued) asm volatile("cp.async.wait_group 0;");
        }
        __syncthreads();                   // publish all buffers
    }

    // ---- tail: reduce(T-2); partial(T-1); reduce(T-1); epilogue ----
    if (gA) {
        const float* pb = pbuf + ((T_-2)&1) * 1152;
        float s = pb[0*288 + rrow*18 + rcol] + pb[1*288 + rrow*18 + rcol]
                + pb[2*288 + rrow*18 + rcol] + pb[3*288 + rrow*18 + rcol]
                + rbias;
        size_t r = (size_t)(T_-2)*B_ + b0 + rrow;
        if (rcol < 15) out[r*A_ + rcol] = s;
        else           out[(size_t)TB_*A_ + r] = s;

        const float* zb = zs + ((T_-1)&1) * 1088;
        float* pw = pbuf + ((T_-1)&1) * 1152;
        float pacc[4] = {0.f, 0.f, 0.f, 0.f};
        #pragma unroll
        for (int i = 0; i < 2; i++) {
            int k0 = (ks*2 + i)*8;
            unsigned a[4];
            a[0] = __float_as_uint(zb[qr*68 + k0 + qc]);
            a[1] = __float_as_uint(zb[(qr+8)*68 + k0 + qc]);
            a[2] = __float_as_uint(zb[qr*68 + k0 + qc + 4]);
            a[3] = __float_as_uint(zb[(qr+8)*68 + k0 + qc + 4]);
            mma8(pacc, a, hb0[i], hb1[i]);
        }
        *(float2*)&pw[ks*288 + qr*18 + n0 + 2*qc]     = make_float2(pacc[0], pacc[1]);
        *(float2*)&pw[ks*288 + (qr+8)*18 + n0 + 2*qc] = make_float2(pacc[2], pacc[3]);
    }
    __syncthreads();
    if (gA) {
        const float* pw = pbuf + ((T_-1)&1) * 1152;
        float s = pw[0*288 + rrow*18 + rcol] + pw[1*288 + rrow*18 + rcol]
                + pw[2*288 + rrow*18 + rcol] + pw[3*288 + rrow*18 + rcol]
                + rbias;
        size_t r = (size_t)(T_-1)*B_ + b0 + rrow;
        if (rcol < 15) out[r*A_ + rcol] = s;
        else           out[(size_t)TB_*A_ + r] = s;

        const size_t OH = (size_t)TB_ * 16;
        *(float2*)&out[OH + (size_t)(b0+rA)*H_ + u]                 = make_float2(hl[0], hl[1]);
        *(float2*)&out[OH + (size_t)(b0+rB)*H_ + u]                 = make_float2(hl[2], hl[3]);
        *(float2*)&out[OH + (size_t)B_*H_ + (size_t)(b0+rA)*H_ + u] = make_float2(c_reg[0], c_reg[1]);
        *(float2*)&out[OH + (size_t)B_*H_ + (size_t)(b0+rB)*H_ + u] = make_float2(c_reg[2], c_reg[3]);
    }
}

// ---------------------------------------------------------------------------
extern "C" void kernel_launch(void* const* d_in, const int* in_sizes, int n_in,
                              void* d_out, int out_size) {
    const float* x    = (const float*)d_in[0];
    const float* done = (const float*)d_in[1];
    const float* h0   = (const float*)d_in[2];
    const float* c0   = (const float*)d_in[3];
    const float* W1   = (const float*)d_in[4];
    const float* b1   = (const float*)d_in[5];
    const float* W2   = (const float*)d_in[6];
    const float* b2   = (const float*)d_in[7];
    const float* Wih  = (const float*)d_in[8];
    const float* bih  = (const float*)d_in[9];
    const float* Whh  = (const float*)d_in[10];
    const float* bhh  = (const float*)d_in[11];
    const float* Wa   = (const float*)d_in[12];
    const float* ba   = (const float*)d_in[13];
    const float* Wc   = (const float*)d_in[14];
    const float* bc   = (const float*)d_in[15];
    float* out = (float*)d_out;

    cudaFuncSetAttribute(k_fused, cudaFuncAttributeMaxDynamicSharedMemorySize, LSF_SMEM*4);

    k_fused<<<B_/16, 384, LSF_SMEM*4>>>(x, done, h0, c0, W1, b1, W2, b2,
                                        Wih, bih, Whh, bhh, Wa, ba, Wc, bc, out);
}

// round 17
// speedup vs baseline: 1.5599x; 1.0217x over previous
#include <cuda_runtime.h>

#define T_  128
#define B_  2048
#define F_  128
#define H_  64
#define A_  15
#define TB_ (T_*B_)
#define G_  256   // 4*H gates

// ---------------------------------------------------------------------------
// math helpers
// ---------------------------------------------------------------------------
__device__ __forceinline__ float ftanh_fast(float x) {
    float y;
    asm("tanh.approx.f32 %0, %1;" : "=f"(y) : "f"(x));
    return y;
}
__device__ __forceinline__ float fsig_fast(float x) {
    return fmaf(0.5f, ftanh_fast(0.5f * x), 0.5f);
}
__device__ __forceinline__ unsigned tf32_rna(float x) {
    unsigned u; asm("cvt.rna.tf32.f32 %0, %1;" : "=r"(u) : "f"(x)); return u;
}
__device__ __forceinline__ float tf32f(float x) {
    return __uint_as_float(tf32_rna(x));
}
// d += a (m16k8, tf32) * b (k8n8, tf32)
__device__ __forceinline__ void mma8(float* d, const unsigned* a, unsigned b0, unsigned b1) {
    asm("mma.sync.aligned.m16n8k8.row.col.f32.tf32.tf32.f32 "
        "{%0,%1,%2,%3}, {%4,%5,%6,%7}, {%8,%9}, {%0,%1,%2,%3};"
        : "+f"(d[0]), "+f"(d[1]), "+f"(d[2]), "+f"(d[3])
        : "r"(a[0]), "r"(a[1]), "r"(a[2]), "r"(a[3]), "r"(b0), "r"(b1));
}
__device__ __forceinline__ void cp16(float* dst_smem, const float* src) {
    unsigned s = (unsigned)__cvta_generic_to_shared(dst_smem);
    asm volatile("cp.async.cg.shared.global [%0], [%1], 16;" :: "r"(s), "l"(src));
}

// ---------------------------------------------------------------------------
// FULLY-FUSED, WARP-SPECIALIZED, PIPELINED kernel. 128 blocks x 384 threads,
// 16 batch rows/block, 1 block/SM, 3 warps/SMSP.
//   Group A (warps 0-7):  gates(t) with SPLIT accumulators (accg: gin-part,
//                         accr: recurrent part -> 8 indep chains),
//                         heads partial(t-1), cell(t).
//   Group B (warps 8-11): S1(t+2) (K split in 2 halves -> 4 chains),
//                         S2(t+1), x prefetch, reduce(t-2).
// ONE __syncthreads per step; all buffer parities disjoint.
// Gate bias (bih+bhh) lives in smem (broadcast LDS at cell time).
// ---------------------------------------------------------------------------
#define LSF_W1   0
#define LSF_W2   9216
#define LSF_WG   (LSF_W2 + 4608)           // 13824
#define LSF_XS   (LSF_WG + 17408)          // 31232  [2][16][132]
#define LSF_H1   (LSF_XS + 4224)           // 35456  [2][16][68]
#define LSF_YS   (LSF_H1 + 2176)           // 37632  [2][16][68]
#define LSF_HSH  (LSF_YS + 2176)           // 39808  [2][16][68]
#define LSF_ZS   (LSF_HSH + 2176)          // 41984  [2][16][68] (tf32 z)
#define LSF_PBUF (LSF_ZS + 2176)           // 44160  [2][4][16][18]
#define LSF_DONE (LSF_PBUF + 2304)         // 46464  [128][16]
#define LSF_BIAS (LSF_DONE + 2048)         // 48512  b1|b2
#define LSF_GB   (LSF_BIAS + 128)          // 48640  gate bias [256]
#define LSF_SMEM (LSF_GB + 256)            // 48896 fl = 195584 B

__global__ __launch_bounds__(384, 1)
void k_fused(const float* __restrict__ x,    const float* __restrict__ done,
             const float* __restrict__ h0,   const float* __restrict__ c0,
             const float* __restrict__ W1,   const float* __restrict__ b1,
             const float* __restrict__ W2,   const float* __restrict__ b2,
             const float* __restrict__ Wih,  const float* __restrict__ bih,
             const float* __restrict__ Whh,  const float* __restrict__ bhh,
             const float* __restrict__ Wa,   const float* __restrict__ ba,
             const float* __restrict__ Wc,   const float* __restrict__ bc,
             float* __restrict__ out) {
    extern __shared__ float sm[];
    float* W1s    = sm + LSF_W1;
    float* W2s    = sm + LSF_W2;
    float* WGs    = sm + LSF_WG;
    float* xs     = sm + LSF_XS;
    float* h1b    = sm + LSF_H1;
    float* ysb    = sm + LSF_YS;
    float* hsh    = sm + LSF_HSH;
    float* zs     = sm + LSF_ZS;
    float* pbuf   = sm + LSF_PBUF;
    float* done_s = sm + LSF_DONE;
    float* bsm    = sm + LSF_BIAS;
    float* gbias  = sm + LSF_GB;

    const int tid  = threadIdx.x;
    const int lane = tid & 31;
    const int b0   = blockIdx.x * 16;
    const int qr   = lane >> 2, qc = lane & 3;
    const int rA = qr, rB = qr + 8;
    const bool gA = (tid < 256);
    const int w   = tid >> 5;              // 0..11
    const int wb  = w - 8;                 // group B warp id 0..3
    const int tidB = tid - 256;            // 0..127 for group B

    // ---------------- group A per-thread state ----------------
    const int u = (w & 7)*8 + qc*2;        // gate-ownership unit pair
    unsigned bf0[8][4], bf1[8][4];
    unsigned hb0[2], hb1[2];
    const int n0 = (w & 1) * 8, ks = (w & 7) >> 1;
    const int rcol = tid & 15, rrow = (tid >> 4) & 15;
    float rbias = 0.f;
    float c_reg[4], hl[4];
    // group B reduce role: 2 outputs (rows rrowB, rrowB+8; col rcolB)
    const int rcolB = tidB & 15, rrowB = (tidB >> 4) & 7;
    float rbB = 0.f;

    if (gA) {
        #pragma unroll
        for (int kt = 0; kt < 8; kt++)
            #pragma unroll
            for (int g = 0; g < 4; g++) {
                int n = g*64 + (w&7)*8 + qr, k = kt*8 + qc;
                bf0[kt][g] = tf32_rna(Whh[n*H_ + k]);
                bf1[kt][g] = tf32_rna(Whh[n*H_ + k + 4]);
            }
        #pragma unroll
        for (int i = 0; i < 2; i++) {
            int k = (ks*2 + i)*8 + qc, j = n0 + qr;
            float v0 = (j < 15) ? Wa[k*A_ + j]     : Wc[k];
            float v1 = (j < 15) ? Wa[(k+4)*A_ + j] : Wc[k+4];
            hb0[i] = tf32_rna(v0);
            hb1[i] = tf32_rna(v1);
        }
        rbias = (rcol < 15) ? ba[rcol] : bc[0];
        // cell state init
        const float mA0 = 1.0f - done[b0 + rA];
        const float mB0 = 1.0f - done[b0 + rB];
        c_reg[0] = c0[(b0+rA)*H_ + u]   * mA0;
        c_reg[1] = c0[(b0+rA)*H_ + u+1] * mA0;
        c_reg[2] = c0[(b0+rB)*H_ + u]   * mB0;
        c_reg[3] = c0[(b0+rB)*H_ + u+1] * mB0;
        *(float2*)&hsh[rA*68 + u] =
            make_float2(tf32f(h0[(b0+rA)*H_ + u])*mA0, tf32f(h0[(b0+rA)*H_ + u+1])*mA0);
        *(float2*)&hsh[rB*68 + u] =
            make_float2(tf32f(h0[(b0+rB)*H_ + u])*mB0, tf32f(h0[(b0+rB)*H_ + u+1])*mB0);
        hl[0] = hl[1] = hl[2] = hl[3] = 0.f;
    } else {
        rbB = (rcolB < 15) ? ba[rcolB] : bc[0];
        // group B: prefetch x(0) -> xs[0], x(1) -> xs[1]
        #pragma unroll
        for (int s = 0; s < 2; s++) {
            const float* src = x + (size_t)(s*B_ + b0) * F_;
            float* dst = xs + s * 2112;
            #pragma unroll
            for (int j = 0; j < 4; j++) {
                int q = tidB + j*128;
                int r = q >> 5, c4 = (q & 31) * 4;
                cp16(dst + r*132 + c4, src + r*F_ + c4);
            }
        }
        asm volatile("cp.async.commit_group;");
    }

    // weights -> smem (tf32-rounded), biases, done (all threads)
    for (int i = tid; i < F_*H_; i += 384) {
        int k = i >> 6, n = i & 63;
        W1s[k*72 + n] = tf32f(W1[i]);
    }
    for (int i = tid; i < H_*H_; i += 384) {
        int k = i >> 6, n = i & 63;
        W2s[k*72 + n] = tf32f(W2[i]);
    }
    for (int i = tid; i < G_*H_; i += 384) {
        int n = i >> 6, k = i & 63;
        WGs[n*68 + k] = tf32f(Wih[i]);
    }
    for (int i = tid; i < H_; i += 384) { bsm[i] = b1[i]; bsm[64+i] = b2[i]; }
    for (int i = tid; i < G_; i += 384) gbias[i] = bih[i] + bhh[i];
    for (int i = tid; i < T_*16; i += 384)
        done_s[i] = done[(i>>4)*B_ + b0 + (i&15)];

    if (!gA) asm volatile("cp.async.wait_group 0;");
    __syncthreads();                       // (1) weights + x0/x1 + hsh

    // ---- prologue: S1(0) by group B ----
    if (!gA) {
        const float* xb = xs;              // x(0)
        float a1[2][4];
        #pragma unroll
        for (int si = 0; si < 2; si++)
            #pragma unroll
            for (int j = 0; j < 4; j++) a1[si][j] = 0.f;
        #pragma unroll 4
        for (int kt = 0; kt < 16; kt++) {
            int k0 = kt*8;
            unsigned a[4];
            a[0] = tf32_rna(xb[rA*132 + k0 + qc]);
            a[1] = tf32_rna(xb[rB*132 + k0 + qc]);
            a[2] = tf32_rna(xb[rA*132 + k0 + qc + 4]);
            a[3] = tf32_rna(xb[rB*132 + k0 + qc + 4]);
            #pragma unroll
            for (int si = 0; si < 2; si++) {
                int bn = wb*16 + si*8 + qr;
                mma8(a1[si], a,
                     __float_as_uint(W1s[(k0+qc)*72 + bn]),
                     __float_as_uint(W1s[(k0+qc+4)*72 + bn]));
            }
        }
        #pragma unroll
        for (int si = 0; si < 2; si++) {
            int c = wb*16 + si*8 + 2*qc;
            float bb0 = bsm[c], bb1 = bsm[c+1];
            *(float2*)&h1b[rA*68 + c] =
                make_float2(tf32f(ftanh_fast(a1[si][0]+bb0)), tf32f(ftanh_fast(a1[si][1]+bb1)));
            *(float2*)&h1b[rB*68 + c] =
                make_float2(tf32f(ftanh_fast(a1[si][2]+bb0)), tf32f(ftanh_fast(a1[si][3]+bb1)));
        }
    }
    __syncthreads();                       // (2) h1[0]

    // ---- prologue: x(2)->xs[0], S2(0)->ys[0], S1(1)->h1[1] by group B ----
    if (!gA) {
        {
            const float* src = x + (size_t)(2*B_ + b0) * F_;
            #pragma unroll
            for (int j = 0; j < 4; j++) {
                int q = tidB + j*128;
                int r = q >> 5, c4 = (q & 31) * 4;
                cp16(xs + r*132 + c4, src + r*F_ + c4);
            }
            asm volatile("cp.async.commit_group;");
        }
        {   // S2(0)
            float a2r[2][4];
            #pragma unroll
            for (int si = 0; si < 2; si++)
                #pragma unroll
                for (int j = 0; j < 4; j++) a2r[si][j] = 0.f;
            #pragma unroll
            for (int kt = 0; kt < 8; kt++) {
                int k0 = kt*8;
                unsigned a[4];
                a[0] = __float_as_uint(h1b[rA*68 + k0 + qc]);
                a[1] = __float_as_uint(h1b[rB*68 + k0 + qc]);
                a[2] = __float_as_uint(h1b[rA*68 + k0 + qc + 4]);
                a[3] = __float_as_uint(h1b[rB*68 + k0 + qc + 4]);
                #pragma unroll
                for (int si = 0; si < 2; si++) {
                    int bn = wb*16 + si*8 + qr;
                    mma8(a2r[si], a,
                         __float_as_uint(W2s[(k0+qc)*72 + bn]),
                         __float_as_uint(W2s[(k0+qc+4)*72 + bn]));
                }
            }
            #pragma unroll
            for (int si = 0; si < 2; si++) {
                int c = wb*16 + si*8 + 2*qc;
                float bb0 = bsm[64+c], bb1 = bsm[64+c+1];
                *(float2*)&ysb[rA*68 + c] =
                    make_float2(tf32f(ftanh_fast(a2r[si][0]+bb0)), tf32f(ftanh_fast(a2r[si][1]+bb1)));
                *(float2*)&ysb[rB*68 + c] =
                    make_float2(tf32f(ftanh_fast(a2r[si][2]+bb0)), tf32f(ftanh_fast(a2r[si][3]+bb1)));
            }
        }
        {   // S1(1) from xs[1]
            const float* xb = xs + 2112;
            float a1[2][4];
            #pragma unroll
            for (int si = 0; si < 2; si++)
                #pragma unroll
                for (int j = 0; j < 4; j++) a1[si][j] = 0.f;
            #pragma unroll 4
            for (int kt = 0; kt < 16; kt++) {
                int k0 = kt*8;
                unsigned a[4];
                a[0] = tf32_rna(xb[rA*132 + k0 + qc]);
                a[1] = tf32_rna(xb[rB*132 + k0 + qc]);
                a[2] = tf32_rna(xb[rA*132 + k0 + qc + 4]);
                a[3] = tf32_rna(xb[rB*132 + k0 + qc + 4]);
                #pragma unroll
                for (int si = 0; si < 2; si++) {
                    int bn = wb*16 + si*8 + qr;
                    mma8(a1[si], a,
                         __float_as_uint(W1s[(k0+qc)*72 + bn]),
                         __float_as_uint(W1s[(k0+qc+4)*72 + bn]));
                }
            }
            #pragma unroll
            for (int si = 0; si < 2; si++) {
                int c = wb*16 + si*8 + 2*qc;
                float bb0 = bsm[c], bb1 = bsm[c+1];
                *(float2*)&h1b[1088 + rA*68 + c] =
                    make_float2(tf32f(ftanh_fast(a1[si][0]+bb0)), tf32f(ftanh_fast(a1[si][1]+bb1)));
                *(float2*)&h1b[1088 + rB*68 + c] =
                    make_float2(tf32f(ftanh_fast(a1[si][2]+bb0)), tf32f(ftanh_fast(a1[si][3]+bb1)));
            }
        }
        asm volatile("cp.async.wait_group 0;");
    }
    __syncthreads();                       // (3) ys[0], h1[1], xs[0]=x(2)

    // =========================== main loop ===========================
    for (int t = 0; t < T_; t++) {
        if (gA) {
            // ---- gates(t): accg = gin-part, accr = rec-part (8 chains) ----
            float accg[4][4], accr[4][4];
            #pragma unroll
            for (int g = 0; g < 4; g++)
                #pragma unroll
                for (int j = 0; j < 4; j++) { accg[g][j] = 0.f; accr[g][j] = 0.f; }
            {
                const float* yb = ysb + (t&1) * 1088;
                const float* hb = hsh + (t&1) * 1088;
                #pragma unroll
                for (int kt = 0; kt < 8; kt++) {
                    int k0 = kt*8;
                    unsigned a[4], ah[4];
                    a[0] = __float_as_uint(yb[rA*68 + k0 + qc]);
                    a[1] = __float_as_uint(yb[rB*68 + k0 + qc]);
                    a[2] = __float_as_uint(yb[rA*68 + k0 + qc + 4]);
                    a[3] = __float_as_uint(yb[rB*68 + k0 + qc + 4]);
                    ah[0] = __float_as_uint(hb[rA*68 + k0 + qc]);
                    ah[1] = __float_as_uint(hb[rB*68 + k0 + qc]);
                    ah[2] = __float_as_uint(hb[rA*68 + k0 + qc + 4]);
                    ah[3] = __float_as_uint(hb[rB*68 + k0 + qc + 4]);
                    #pragma unroll
                    for (int g = 0; g < 4; g++) {
                        int bn = g*64 + (w&7)*8 + qr;
                        mma8(accg[g], a,
                             __float_as_uint(WGs[bn*68 + k0 + qc]),
                             __float_as_uint(WGs[bn*68 + k0 + qc + 4]));
                        mma8(accr[g], ah, bf0[kt][g], bf1[kt][g]);
                    }
                }
            }

            // ---- heads partial(t-1), zs pre-rounded -> raw loads ----
            if (t) {
                const float* zb = zs + ((t-1)&1) * 1088;
                float* pw = pbuf + ((t-1)&1) * 1152;
                float pacc[4] = {0.f, 0.f, 0.f, 0.f};
                #pragma unroll
                for (int i = 0; i < 2; i++) {
                    int k0 = (ks*2 + i)*8;
                    unsigned a[4];
                    a[0] = __float_as_uint(zb[qr*68 + k0 + qc]);
                    a[1] = __float_as_uint(zb[(qr+8)*68 + k0 + qc]);
                    a[2] = __float_as_uint(zb[qr*68 + k0 + qc + 4]);
                    a[3] = __float_as_uint(zb[(qr+8)*68 + k0 + qc + 4]);
                    mma8(pacc, a, hb0[i], hb1[i]);
                }
                *(float2*)&pw[ks*288 + qr*18 + n0 + 2*qc]     = make_float2(pacc[0], pacc[1]);
                *(float2*)&pw[ks*288 + (qr+8)*18 + n0 + 2*qc] = make_float2(pacc[2], pacc[3]);
            }

            // ---- cell(t): combine accg+accr+bias (broadcast LDS) ----
            float gv[4][4];
            #pragma unroll
            for (int g = 0; g < 4; g++) {
                float2 bb = *(const float2*)&gbias[g*64 + u];
                gv[g][0] = accg[g][0] + accr[g][0] + bb.x;
                gv[g][1] = accg[g][1] + accr[g][1] + bb.y;
                gv[g][2] = accg[g][2] + accr[g][2] + bb.x;
                gv[g][3] = accg[g][3] + accr[g][3] + bb.y;
            }
            float mnA = 1.0f, mnB = 1.0f;
            if (t + 1 < T_) {
                mnA = 1.0f - done_s[(t+1)*16 + rA];
                mnB = 1.0f - done_s[(t+1)*16 + rB];
            }
            float hr[4], zr[4];
            #pragma unroll
            for (int i = 0; i < 4; i++) {
                float mn = (i < 2) ? mnA : mnB;
                float cn = fsig_fast(gv[1][i])*c_reg[i]
                         + fsig_fast(gv[0][i])*ftanh_fast(gv[2][i]);
                float hn = fsig_fast(gv[3][i])*ftanh_fast(cn);
                c_reg[i] = cn * mn;
                zr[i] = tf32f(hn);
                hr[i] = zr[i] * mn;
                hl[i] = hn;
            }
            float* hn_ = hsh + ((t+1)&1) * 1088;
            *(float2*)&hn_[rA*68 + u] = make_float2(hr[0], hr[1]);
            *(float2*)&hn_[rB*68 + u] = make_float2(hr[2], hr[3]);
            float* zw = zs + (t&1) * 1088;
            *(float2*)&zw[rA*68 + u] = make_float2(zr[0], zr[1]);
            *(float2*)&zw[rB*68 + u] = make_float2(zr[2], zr[3]);
        } else {
            // ---- group B: prefetch x(t+3) ----
            bool issued = false;
            if (t + 3 < T_) {
                float* dst = xs + ((t+3)&1) * 2112;
                const float* src = x + (size_t)((t+3)*B_ + b0) * F_;
                #pragma unroll
                for (int j = 0; j < 4; j++) {
                    int q = tidB + j*128;
                    int r = q >> 5, c4 = (q & 31) * 4;
                    cp16(dst + r*132 + c4, src + r*F_ + c4);
                }
                asm volatile("cp.async.commit_group;");
                issued = true;
            }

            // ---- reduce(t-2): 2 outputs per B thread ----
            if (t >= 2) {
                const float* pb = pbuf + ((t-2)&1) * 1152;
                #pragma unroll
                for (int r2 = 0; r2 < 2; r2++) {
                    int rr = rrowB + r2*8;
                    float s = pb[0*288 + rr*18 + rcolB] + pb[1*288 + rr*18 + rcolB]
                            + pb[2*288 + rr*18 + rcolB] + pb[3*288 + rr*18 + rcolB]
                            + rbB;
                    size_t r = (size_t)(t-2)*B_ + b0 + rr;
                    if (rcolB < 15) out[r*A_ + rcolB] = s;
                    else            out[(size_t)TB_*A_ + r] = s;
                }
            }

            // ---- S1(t+2): K split in two halves (4 chains) ----
            if (t + 2 < T_) {
                const float* xb = xs + ((t+2)&1) * 2112;
                float a1[2][4], a1x[2][4];
                #pragma unroll
                for (int si = 0; si < 2; si++)
                    #pragma unroll
                    for (int j = 0; j < 4; j++) { a1[si][j] = 0.f; a1x[si][j] = 0.f; }
                #pragma unroll 4
                for (int kt = 0; kt < 8; kt++) {
                    int k0 = kt*8, k1 = (kt+8)*8;
                    unsigned a[4], axx[4];
                    a[0] = tf32_rna(xb[rA*132 + k0 + qc]);
                    a[1] = tf32_rna(xb[rB*132 + k0 + qc]);
                    a[2] = tf32_rna(xb[rA*132 + k0 + qc + 4]);
                    a[3] = tf32_rna(xb[rB*132 + k0 + qc + 4]);
                    axx[0] = tf32_rna(xb[rA*132 + k1 + qc]);
                    axx[1] = tf32_rna(xb[rB*132 + k1 + qc]);
                    axx[2] = tf32_rna(xb[rA*132 + k1 + qc + 4]);
                    axx[3] = tf32_rna(xb[rB*132 + k1 + qc + 4]);
                    #pragma unroll
                    for (int si = 0; si < 2; si++) {
                        int bn = wb*16 + si*8 + qr;
                        mma8(a1[si], a,
                             __float_as_uint(W1s[(k0+qc)*72 + bn]),
                             __float_as_uint(W1s[(k0+qc+4)*72 + bn]));
                        mma8(a1x[si], axx,
                             __float_as_uint(W1s[(k1+qc)*72 + bn]),
                             __float_as_uint(W1s[(k1+qc+4)*72 + bn]));
                    }
                }
                float* hd = h1b + ((t+2)&1) * 1088;
                #pragma unroll
                for (int si = 0; si < 2; si++) {
                    int c = wb*16 + si*8 + 2*qc;
                    float bb0 = bsm[c], bb1 = bsm[c+1];
                    *(float2*)&hd[rA*68 + c] = make_float2(
                        tf32f(ftanh_fast(a1[si][0]+a1x[si][0]+bb0)),
                        tf32f(ftanh_fast(a1[si][1]+a1x[si][1]+bb1)));
                    *(float2*)&hd[rB*68 + c] = make_float2(
                        tf32f(ftanh_fast(a1[si][2]+a1x[si][2]+bb0)),
                        tf32f(ftanh_fast(a1[si][3]+a1x[si][3]+bb1)));
                }
            }

            // ---- S2(t+1) ----
            if (t + 1 < T_) {
                const float* hs = h1b + ((t+1)&1) * 1088;
                float a2r[2][4];
                #pragma unroll
                for (int si = 0; si < 2; si++)
                    #pragma unroll
                    for (int j = 0; j < 4; j++) a2r[si][j] = 0.f;
                #pragma unroll
                for (int kt = 0; kt < 8; kt++) {
                    int k0 = kt*8;
                    unsigned a[4];
                    a[0] = __float_as_uint(hs[rA*68 + k0 + qc]);
                    a[1] = __float_as_uint(hs[rB*68 + k0 + qc]);
                    a[2] = __float_as_uint(hs[rA*68 + k0 + qc + 4]);
                    a[3] = __float_as_uint(hs[rB*68 + k0 + qc + 4]);
                    #pragma unroll
                    for (int si = 0; si < 2; si++) {
                        int bn = wb*16 + si*8 + qr;
                        mma8(a2r[si], a,
                             __float_as_uint(W2s[(k0+qc)*72 + bn]),
                             __float_as_uint(W2s[(k0+qc+4)*72 + bn]));
                    }
                }
                float* yd = ysb + ((t+1)&1) * 1088;
                #pragma unroll
                for (int si = 0; si < 2; si++) {
                    int c = wb*16 + si*8 + 2*qc;
                    float bb0 = bsm[64+c], bb1 = bsm[64+c+1];
                    *(float2*)&yd[rA*68 + c] =
                        make_float2(tf32f(ftanh_fast(a2r[si][0]+bb0)), tf32f(ftanh_fast(a2r[si][1]+bb1)));
                    *(float2*)&yd[rB*68 + c] =
                        make_float2(tf32f(ftanh_fast(a2r[si][2]+bb0)), tf32f(ftanh_fast(a2r[si][3]+bb1)));
                }
            }
            if (issued) asm volatile("cp.async.wait_group 0;");
        }
        __syncthreads();                   // publish all buffers
    }

    // ---- tail: reduce(T-2); partial(T-1); reduce(T-1); epilogue ----
    if (gA) {
        const float* pb = pbuf + ((T_-2)&1) * 1152;
        float s = pb[0*288 + rrow*18 + rcol] + pb[1*288 + rrow*18 + rcol]
                + pb[2*288 + rrow*18 + rcol] + pb[3*288 + rrow*18 + rcol]
                + rbias;
        size_t r = (size_t)(T_-2)*B_ + b0 + rrow;
        if (rcol < 15) out[r*A_ + rcol] = s;
        else           out[(size_t)TB_*A_ + r] = s;

        const float* zb = zs + ((T_-1)&1) * 1088;
        float* pw = pbuf + ((T_-1)&1) * 1152;
        float pacc[4] = {0.f, 0.f, 0.f, 0.f};
        #pragma unroll
        for (int i = 0; i < 2; i++) {
            int k0 = (ks*2 + i)*8;
            unsigned a[4];
            a[0] = __float_as_uint(zb[qr*68 + k0 + qc]);
            a[1] = __float_as_uint(zb[(qr+8)*68 + k0 + qc]);
            a[2] = __float_as_uint(zb[qr*68 + k0 + qc + 4]);
            a[3] = __float_as_uint(zb[(qr+8)*68 + k0 + qc + 4]);
            mma8(pacc, a, hb0[i], hb1[i]);
        }
        *(float2*)&pw[ks*288 + qr*18 + n0 + 2*qc]     = make_float2(pacc[0], pacc[1]);
        *(float2*)&pw[ks*288 + (qr+8)*18 + n0 + 2*qc] = make_float2(pacc[2], pacc[3]);
    }
    __syncthreads();
    if (gA) {
        const float* pw = pbuf + ((T_-1)&1) * 1152;
        float s = pw[0*288 + rrow*18 + rcol] + pw[1*288 + rrow*18 + rcol]
                + pw[2*288 + rrow*18 + rcol] + pw[3*288 + rrow*18 + rcol]
                + rbias;
        size_t r = (size_t)(T_-1)*B_ + b0 + rrow;
        if (rcol < 15) out[r*A_ + rcol] = s;
        else           out[(size_t)TB_*A_ + r] = s;

        const size_t OH = (size_t)TB_ * 16;
        *(float2*)&out[OH + (size_t)(b0+rA)*H_ + u]                 = make_float2(hl[0], hl[1]);
        *(float2*)&out[OH + (size_t)(b0+rB)*H_ + u]                 = make_float2(hl[2], hl[3]);
        *(float2*)&out[OH + (size_t)B_*H_ + (size_t)(b0+rA)*H_ + u] = make_float2(c_reg[0], c_reg[1]);
        *(float2*)&out[OH + (size_t)B_*H_ + (size_t)(b0+rB)*H_ + u] = make_float2(c_reg[2], c_reg[3]);
    }
}

// ---------------------------------------------------------------------------
extern "C" void kernel_launch(void* const* d_in, const int* in_sizes, int n_in,
                              void* d_out, int out_size) {
    const float* x    = (const float*)d_in[0];
    const float* done = (const float*)d_in[1];
    const float* h0   = (const float*)d_in[2];
    const float* c0   = (const float*)d_in[3];
    const float* W1   = (const float*)d_in[4];
    const float* b1   = (const float*)d_in[5];
    const float* W2   = (const float*)d_in[6];
    const float* b2   = (const float*)d_in[7];
    const float* Wih  = (const float*)d_in[8];
    const float* bih  = (const float*)d_in[9];
    const float* Whh  = (const float*)d_in[10];
    const float* bhh  = (const float*)d_in[11];
    const float* Wa   = (const float*)d_in[12];
    const float* ba   = (const float*)d_in[13];
    const float* Wc   = (const float*)d_in[14];
    const float* bc   = (const float*)d_in[15];
    float* out = (float*)d_out;

    cudaFuncSetAttribute(k_fused, cudaFuncAttributeMaxDynamicSharedMemorySize, LSF_SMEM*4);

    k_fused<<<B_/16, 384, LSF_SMEM*4>>>(x, done, h0, c0, W1, b1, W2, b2,
                                        Wih, bih, Whh, bhh, Wa, ba, Wc, bc, out);
}